// round 6
// baseline (speedup 1.0000x reference)
#include <cuda_runtime.h>
#include <math.h>

#define Nn  50000
#define Ee  300000
#define NCc 12500
#define ECc 75000

#define OFF_EC 1600000
#define OFF_V  11200000
#define OFF_E  17600000

typedef unsigned long long ull;

// smem layout (floats):
//   As[2 * 64*20]  = 2560   (layer-0 streamed A tiles, double buffered)
//   Bs[2 * 16*192] = 6144   (weight tiles, group-stride-12 swizzle, double buffered)
//   Hs[64 * 132]   = 8448   (activations)
//   idx            = 160
#define AS_OFF 0
#define AS_BUF 1280
#define BS_OFF 2560
#define BS_BUF 3072
#define HS_OFF 8704
#define IX_OFF 17152
#define SMEM_BYTES ((17152 + 160) * 4)

// ---------------- device scratch ----------------
__device__ float g_agg[Nn * 128];
__device__ float g_deg[Nn];
__device__ float g_cposs[NCc * 2];
__device__ float g_ccnt[NCc];
__device__ float g_cpos[NCc * 2];
__device__ float g_cinv[NCc];

__device__ __forceinline__ float selu_f(float x) {
    return x > 0.f ? 1.0507009873554805f * x : 1.7580993408473766f * expm1f(x);
}
__device__ __forceinline__ void ffma2(ull& d, ull a, ull b) {
    asm("fma.rn.f32x2 %0, %1, %2, %0;" : "+l"(d) : "l"(a), "l"(b));
}
__device__ __forceinline__ float2 unpk(ull p) {
    float2 f;
    asm("mov.b64 {%0, %1}, %2;" : "=f"(f.x), "=f"(f.y) : "l"(p));
    return f;
}
__device__ __forceinline__ ull dupf(float x) {
    ull r;
    asm("mov.b64 %0, {%1, %1};" : "=l"(r) : "f"(x));
    return r;
}

__device__ __forceinline__ void acc_init(ull (&acc)[8][4], const float* __restrict__ b, int c0) {
    ull bb[4];
#pragma unroll
    for (int j = 0; j < 4; j++) bb[j] = *(const ull*)&b[c0 + 2 * j];
#pragma unroll
    for (int i = 0; i < 8; i++)
#pragma unroll
        for (int j = 0; j < 4; j++) acc[i][j] = bb[j];
}

// Bs layout: Bs[k*192 + g*12 + (c%8)], g = c/8.  g*12 mod 32 covers all banks
// disjointly per quarter-warp for both LDS.128 offsets (+0 and +4).
__device__ __forceinline__ void fill_Bs(float* Bs, const float* __restrict__ W, int kt, int t) {
    const float4* wsrc = (const float4*)(W + (size_t)kt * 128);
#pragma unroll
    for (int i = 0; i < 4; i++) {
        int fi = i * 128 + t;      // float4 index within 16x128 tile
        float4 w = wsrc[fi];
        int k = fi >> 5;
        int q = fi & 31;
        *(float4*)&Bs[k * 192 + (q >> 1) * 12 + (q & 1) * 4] = w;
    }
}

// acc[8 rows][4 col-pairs] += A(64 x STRIDE)[:, koff:koff+16] @ Bs-tile
template <int STRIDE>
__device__ __forceinline__ void mma16(const float* A, int koff, const float* Bs,
                                      int r0, int gb, ull (&acc)[8][4]) {
#pragma unroll
    for (int k4 = 0; k4 < 4; k4++) {
        float4 a4[8];
#pragma unroll
        for (int i = 0; i < 8; i++)
            a4[i] = *(const float4*)&A[(r0 + i) * STRIDE + koff + 4 * k4];
#pragma unroll
        for (int kk = 0; kk < 4; kk++) {
            const float* bp = &Bs[(4 * k4 + kk) * 192 + gb];
            ulonglong2 bA = *(const ulonglong2*)bp;
            ulonglong2 bB = *(const ulonglong2*)(bp + 4);
#pragma unroll
            for (int i = 0; i < 8; i++) {
                float av = (kk == 0) ? a4[i].x : (kk == 1) ? a4[i].y
                         : (kk == 2) ? a4[i].z : a4[i].w;
                ull ad = dupf(av);
                ffma2(acc[i][0], ad, bA.x);
                ffma2(acc[i][1], ad, bA.y);
                ffma2(acc[i][2], ad, bB.x);
                ffma2(acc[i][3], ad, bB.y);
            }
        }
    }
}

__device__ __forceinline__ void selu_store(float* Hs, ull (&acc)[8][4], int r0, int c0) {
#pragma unroll
    for (int i = 0; i < 8; i++) {
        float2 p0 = unpk(acc[i][0]), p1 = unpk(acc[i][1]);
        float2 p2 = unpk(acc[i][2]), p3 = unpk(acc[i][3]);
        *(float4*)&Hs[(r0 + i) * 132 + c0] =
            make_float4(selu_f(p0.x), selu_f(p0.y), selu_f(p1.x), selu_f(p1.y));
        *(float4*)&Hs[(r0 + i) * 132 + c0 + 4] =
            make_float4(selu_f(p2.x), selu_f(p2.y), selu_f(p3.x), selu_f(p3.y));
    }
}

// hidden 128->128 layer, Bs double buffered, ONE sync per K-tile
__device__ __forceinline__ void hidden_layer(const float* __restrict__ W,
                                             const float* Hs, float* BsBase,
                                             int t, int r0, int gb, ull (&acc)[8][4]) {
    fill_Bs(BsBase, W, 0, t);
    __syncthreads();
#pragma unroll 1
    for (int kt = 0; kt < 8; kt++) {
        if (kt < 7) fill_Bs(BsBase + ((kt + 1) & 1) * BS_BUF, W, (kt + 1) * 16, t);
        mma16<132>(Hs, kt * 16, BsBase + (kt & 1) * BS_BUF, r0, gb, acc);
        __syncthreads();
    }
}

// ---------------- edge: e += MLP([e, v[src], v[dst]]); agg[dst] += e ----------------
__global__ void __launch_bounds__(128) edge_kernel(
    float* __restrict__ e, const float* __restrict__ v,
    const int* __restrict__ src, const int* __restrict__ dst,
    const float* __restrict__ w0, const float* __restrict__ b0,
    const float* __restrict__ w1, const float* __restrict__ b1,
    const float* __restrict__ w2, const float* __restrict__ b2,
    float* __restrict__ agg) {
    extern __shared__ float sm[];
    float* As = sm + AS_OFF;
    float* Bs = sm + BS_OFF;
    float* Hs = sm + HS_OFF;
    int* s_src = (int*)(sm + IX_OFF);
    int* s_dst = s_src + 64;

    const int t = threadIdx.x;
    const int row0 = blockIdx.x * 64;
    if (t < 64) {
        int r = row0 + t;
        if (r >= Ee) r = Ee - 1;
        s_src[t] = src[r];
        s_dst[t] = dst[r];
    }
    const int c0 = (t & 15) * 8;
    const int gb = (t & 15) * 12;
    const int r0 = (t >> 4) * 8;
    __syncthreads();

    ull acc[8][4];
    acc_init(acc, b0, c0);

    // layer 0: K = 384 streamed (gathered A + W tiles, double buffered)
    auto fill_As = [&](float* dstA, int kt) {
#pragma unroll
        for (int i = 0; i < 2; i++) {
            int f = t * 2 + i;
            int ar = f >> 2;
            int kl = (f & 3) << 2;
            int k = kt + kl;
            int grow = row0 + ar;
            if (grow >= Ee) grow = Ee - 1;
            float4 val;
            if (k < 128)      val = *(const float4*)(e + (size_t)grow * 128 + k);
            else if (k < 256) val = *(const float4*)(v + (size_t)s_src[ar] * 128 + (k - 128));
            else              val = *(const float4*)(v + (size_t)s_dst[ar] * 128 + (k - 256));
            *(float4*)&dstA[ar * 20 + kl] = val;
        }
    };
    fill_As(As, 0);
    fill_Bs(Bs, w0, 0, t);
    __syncthreads();
#pragma unroll 1
    for (int kt = 0; kt < 24; kt++) {
        if (kt < 23) {
            int nb = (kt + 1) & 1;
            fill_As(As + nb * AS_BUF, (kt + 1) * 16);
            fill_Bs(Bs + nb * BS_BUF, w0, (kt + 1) * 16, t);
        }
        mma16<20>(As + (kt & 1) * AS_BUF, 0, Bs + (kt & 1) * BS_BUF, r0, gb, acc);
        __syncthreads();
    }
    selu_store(Hs, acc, r0, c0);
    acc_init(acc, b1, c0);
    hidden_layer(w1, Hs, Bs, t, r0, gb, acc);
    selu_store(Hs, acc, r0, c0);
    acc_init(acc, b2, c0);
    hidden_layer(w2, Hs, Bs, t, r0, gb, acc);

#pragma unroll
    for (int i = 0; i < 8; i++) {
        int row = row0 + r0 + i;
        if (row < Ee) {
            int dn = s_dst[r0 + i];
            float* erow = e + (size_t)row * 128 + c0;
            float* arow = agg + (size_t)dn * 128 + c0;
            float2 p0 = unpk(acc[i][0]), p1 = unpk(acc[i][1]);
            float2 p2 = unpk(acc[i][2]), p3 = unpk(acc[i][3]);
            float4 e0 = *(float4*)erow;
            float4 e1 = *(float4*)(erow + 4);
            float rr[8] = {e0.x + p0.x, e0.y + p0.y, e0.z + p1.x, e0.w + p1.y,
                           e1.x + p2.x, e1.y + p2.y, e1.z + p3.x, e1.w + p3.y};
            *(float4*)erow       = make_float4(rr[0], rr[1], rr[2], rr[3]);
            *(float4*)(erow + 4) = make_float4(rr[4], rr[5], rr[6], rr[7]);
#pragma unroll
            for (int j = 0; j < 8; j++) atomicAdd(&arow[j], rr[j]);
        }
    }
}

// ---------------- node: v += MLP([v, agg/deg]) ----------------
__global__ void __launch_bounds__(128) node_kernel(
    float* __restrict__ v, const float* __restrict__ agg, const float* __restrict__ deg,
    const float* __restrict__ w0, const float* __restrict__ b0,
    const float* __restrict__ w1, const float* __restrict__ b1,
    const float* __restrict__ w2, const float* __restrict__ b2) {
    extern __shared__ float sm[];
    float* As = sm + AS_OFF;
    float* Bs = sm + BS_OFF;
    float* Hs = sm + HS_OFF;
    float* s_inv = sm + IX_OFF;

    const int t = threadIdx.x;
    const int row0 = blockIdx.x * 64;
    if (t < 64) {
        int r = row0 + t;
        if (r >= Nn) r = Nn - 1;
        s_inv[t] = 1.f / fmaxf(deg[r], 1.f);
    }
    const int c0 = (t & 15) * 8;
    const int gb = (t & 15) * 12;
    const int r0 = (t >> 4) * 8;
    __syncthreads();

    ull acc[8][4];
    acc_init(acc, b0, c0);

    auto fill_As = [&](float* dstA, int kt) {
#pragma unroll
        for (int i = 0; i < 2; i++) {
            int f = t * 2 + i;
            int ar = f >> 2;
            int kl = (f & 3) << 2;
            int k = kt + kl;
            int grow = row0 + ar;
            if (grow >= Nn) grow = Nn - 1;
            float4 val;
            if (k < 128) {
                val = *(const float4*)(v + (size_t)grow * 128 + k);
            } else {
                val = *(const float4*)(agg + (size_t)grow * 128 + (k - 128));
                float sc = s_inv[ar];
                val.x *= sc; val.y *= sc; val.z *= sc; val.w *= sc;
            }
            *(float4*)&dstA[ar * 20 + kl] = val;
        }
    };
    fill_As(As, 0);
    fill_Bs(Bs, w0, 0, t);
    __syncthreads();
#pragma unroll 1
    for (int kt = 0; kt < 16; kt++) {
        if (kt < 15) {
            int nb = (kt + 1) & 1;
            fill_As(As + nb * AS_BUF, (kt + 1) * 16);
            fill_Bs(Bs + nb * BS_BUF, w0, (kt + 1) * 16, t);
        }
        mma16<20>(As + (kt & 1) * AS_BUF, 0, Bs + (kt & 1) * BS_BUF, r0, gb, acc);
        __syncthreads();
    }
    selu_store(Hs, acc, r0, c0);
    acc_init(acc, b1, c0);
    hidden_layer(w1, Hs, Bs, t, r0, gb, acc);
    selu_store(Hs, acc, r0, c0);
    acc_init(acc, b2, c0);
    hidden_layer(w2, Hs, Bs, t, r0, gb, acc);

#pragma unroll
    for (int i = 0; i < 8; i++) {
        int row = row0 + r0 + i;
        if (row < Nn) {
            float* vrow = v + (size_t)row * 128 + c0;
            float2 p0 = unpk(acc[i][0]), p1 = unpk(acc[i][1]);
            float2 p2 = unpk(acc[i][2]), p3 = unpk(acc[i][3]);
            float4 v0 = *(float4*)vrow;
            float4 v1 = *(float4*)(vrow + 4);
            *(float4*)vrow       = make_float4(v0.x + p0.x, v0.y + p0.y, v0.z + p1.x, v0.w + p1.y);
            *(float4*)(vrow + 4) = make_float4(v1.x + p2.x, v1.y + p2.y, v1.z + p3.x, v1.w + p3.y);
        }
    }
}

// ---------------- pool: atomic-add MLP([v, rel]) into vc sums ----------------
__global__ void __launch_bounds__(128) pool_kernel(
    const float* __restrict__ v, const float* __restrict__ pos,
    const int* __restrict__ cluster, const float* __restrict__ cpos,
    const float* __restrict__ w0, const float* __restrict__ b0,
    const float* __restrict__ w1, const float* __restrict__ b1,
    const float* __restrict__ w2, const float* __restrict__ b2,
    float* __restrict__ vc) {
    extern __shared__ float sm[];
    float* As = sm + AS_OFF;
    float* Bs = sm + BS_OFF;
    float* Hs = sm + HS_OFF;
    float* s_rel = sm + IX_OFF;
    int* s_cl = (int*)(sm + IX_OFF + 64);

    const int t = threadIdx.x;
    const int row0 = blockIdx.x * 64;
    if (t < 64) {
        int r = row0 + t;
        if (r >= Nn) r = Nn - 1;
        int cl = cluster[r];
        float dx = pos[2 * r] - cpos[2 * cl];
        float dy = pos[2 * r + 1] - cpos[2 * cl + 1];
        s_rel[t] = sqrtf(dx * dx + dy * dy + 1e-12f);
        s_cl[t] = cl;
    }
    const int c0 = (t & 15) * 8;
    const int gb = (t & 15) * 12;
    const int r0 = (t >> 4) * 8;
    __syncthreads();

    ull acc[8][4];
    acc_init(acc, b0, c0);

    auto fill_As = [&](float* dstA, int kt) {
#pragma unroll
        for (int i = 0; i < 2; i++) {
            int f = t * 2 + i;
            int ar = f >> 2;
            int kl = (f & 3) << 2;
            int grow = row0 + ar;
            if (grow >= Nn) grow = Nn - 1;
            float4 val = *(const float4*)(v + (size_t)grow * 128 + kt + kl);
            *(float4*)&dstA[ar * 20 + kl] = val;
        }
    };
    fill_As(As, 0);
    fill_Bs(Bs, w0, 0, t);
    __syncthreads();
#pragma unroll 1
    for (int kt = 0; kt < 8; kt++) {
        if (kt < 7) {
            int nb = (kt + 1) & 1;
            fill_As(As + nb * AS_BUF, (kt + 1) * 16);
            fill_Bs(Bs + nb * BS_BUF, w0, (kt + 1) * 16, t);
        }
        mma16<20>(As + (kt & 1) * AS_BUF, 0, Bs + (kt & 1) * BS_BUF, r0, gb, acc);
        __syncthreads();
    }
    // extra K dim 128: rel_feat scalar
    {
        ull wx[4];
#pragma unroll
        for (int j = 0; j < 4; j++) wx[j] = *(const ull*)&w0[128 * 128 + c0 + 2 * j];
#pragma unroll
        for (int i = 0; i < 8; i++) {
            ull rl2 = dupf(s_rel[r0 + i]);
#pragma unroll
            for (int j = 0; j < 4; j++) ffma2(acc[i][j], rl2, wx[j]);
        }
    }
    selu_store(Hs, acc, r0, c0);
    acc_init(acc, b1, c0);
    hidden_layer(w1, Hs, Bs, t, r0, gb, acc);
    selu_store(Hs, acc, r0, c0);
    acc_init(acc, b2, c0);
    hidden_layer(w2, Hs, Bs, t, r0, gb, acc);

#pragma unroll
    for (int i = 0; i < 8; i++) {
        int row = row0 + r0 + i;
        if (row < Nn) {
            int cl = s_cl[r0 + i];
            float* crow = vc + (size_t)cl * 128 + c0;
            float2 p0 = unpk(acc[i][0]), p1 = unpk(acc[i][1]);
            float2 p2 = unpk(acc[i][2]), p3 = unpk(acc[i][3]);
            float rr[8] = {p0.x, p0.y, p1.x, p1.y, p2.x, p2.y, p3.x, p3.y};
#pragma unroll
            for (int j = 0; j < 8; j++) atomicAdd(&crow[j], rr[j]);
        }
    }
}

// ---------------- coarse edge encoder ----------------
__global__ void __launch_bounds__(128) eenc_kernel(
    const int* __restrict__ cei, const float* __restrict__ cpos,
    const float* __restrict__ w0, const float* __restrict__ b0,
    const float* __restrict__ w1, const float* __restrict__ b1,
    const float* __restrict__ w2, const float* __restrict__ b2,
    float* __restrict__ ec) {
    extern __shared__ float sm[];
    float* Bs = sm + BS_OFF;
    float* Hs = sm + HS_OFF;
    float* s_crel = sm + IX_OFF;

    const int t = threadIdx.x;
    const int row0 = blockIdx.x * 64;
    if (t < 64) {
        int r = row0 + t;
        if (r >= ECc) r = ECc - 1;
        int a = cei[r];
        int b = cei[ECc + r];
        float dx = cpos[2 * a] - cpos[2 * b];
        float dy = cpos[2 * a + 1] - cpos[2 * b + 1];
        s_crel[t] = sqrtf(dx * dx + dy * dy + 1e-12f);
    }
    const int c0 = (t & 15) * 8;
    const int gb = (t & 15) * 12;
    const int r0 = (t >> 4) * 8;
    __syncthreads();

    // layer 0 (K = 1)
#pragma unroll
    for (int i = 0; i < 8; i++) {
        float cr = s_crel[r0 + i];
#pragma unroll
        for (int j = 0; j < 8; j++)
            Hs[(r0 + i) * 132 + c0 + j] =
                selu_f(fmaf(cr, __ldg(&w0[c0 + j]), __ldg(&b0[c0 + j])));
    }

    ull acc[8][4];
    acc_init(acc, b1, c0);
    hidden_layer(w1, Hs, Bs, t, r0, gb, acc);
    selu_store(Hs, acc, r0, c0);
    acc_init(acc, b2, c0);
    hidden_layer(w2, Hs, Bs, t, r0, gb, acc);

#pragma unroll
    for (int i = 0; i < 8; i++) {
        int row = row0 + r0 + i;
        if (row < ECc) {
            float* erow = ec + (size_t)row * 128 + c0;
            float2 p0 = unpk(acc[i][0]), p1 = unpk(acc[i][1]);
            float2 p2 = unpk(acc[i][2]), p3 = unpk(acc[i][3]);
            *(float4*)erow       = make_float4(p0.x, p0.y, p1.x, p1.y);
            *(float4*)(erow + 4) = make_float4(p2.x, p2.y, p3.x, p3.y);
        }
    }
}

// ---------------- small helpers ----------------
__global__ void deg_scatter(const int* __restrict__ dst, float* __restrict__ deg) {
    int i = blockIdx.x * blockDim.x + threadIdx.x;
    if (i < Ee) atomicAdd(&deg[dst[i]], 1.f);
}
__global__ void cpos_scatter(const float* __restrict__ pos, const int* __restrict__ cluster,
                             float* __restrict__ cposs, float* __restrict__ ccnt) {
    int i = blockIdx.x * blockDim.x + threadIdx.x;
    if (i < Nn) {
        int c = cluster[i];
        atomicAdd(&cposs[2 * c], pos[2 * i]);
        atomicAdd(&cposs[2 * c + 1], pos[2 * i + 1]);
        atomicAdd(&ccnt[c], 1.f);
    }
}
__global__ void cpos_fin(const float* __restrict__ cposs, const float* __restrict__ ccnt,
                         float* __restrict__ cpos, float* __restrict__ cinv) {
    int c = blockIdx.x * blockDim.x + threadIdx.x;
    if (c < NCc) {
        float inv = 1.f / fmaxf(ccnt[c], 1.f);
        cpos[2 * c] = cposs[2 * c] * inv;
        cpos[2 * c + 1] = cposs[2 * c + 1] * inv;
        cinv[c] = inv;
    }
}
__global__ void vc_scale(float* __restrict__ vc, const float* __restrict__ cinv) {
    int i = blockIdx.x * blockDim.x + threadIdx.x;
    if (i < NCc * 128) vc[i] *= cinv[i >> 7];
}

// ---------------- launch ----------------
extern "C" void kernel_launch(void* const* d_in, const int* in_sizes, int n_in,
                              void* d_out, int out_size) {
    const float* v0      = (const float*)d_in[0];
    const float* e0      = (const float*)d_in[1];
    const float* pos     = (const float*)d_in[2];
    const int*   ei      = (const int*)d_in[3];
    const int*   cluster = (const int*)d_in[4];
    const int*   cei     = (const int*)d_in[5];
    const float* ew0 = (const float*)d_in[6],  *eb0 = (const float*)d_in[7];
    const float* ew1 = (const float*)d_in[8],  *eb1 = (const float*)d_in[9];
    const float* ew2 = (const float*)d_in[10], *eb2 = (const float*)d_in[11];
    const float* nw0 = (const float*)d_in[12], *nb0 = (const float*)d_in[13];
    const float* nw1 = (const float*)d_in[14], *nb1 = (const float*)d_in[15];
    const float* nw2 = (const float*)d_in[16], *nb2 = (const float*)d_in[17];
    const float* pw0 = (const float*)d_in[18], *pb0 = (const float*)d_in[19];
    const float* pw1 = (const float*)d_in[20], *pb1 = (const float*)d_in[21];
    const float* pw2 = (const float*)d_in[22], *pb2 = (const float*)d_in[23];
    const float* qw0 = (const float*)d_in[24], *qb0 = (const float*)d_in[25];
    const float* qw1 = (const float*)d_in[26], *qb1 = (const float*)d_in[27];
    const float* qw2 = (const float*)d_in[28], *qb2 = (const float*)d_in[29];

    float* out    = (float*)d_out;
    float* out_vc = out;
    float* out_ec = out + OFF_EC;
    float* vbuf   = out + OFF_V;
    float* ebuf   = out + OFF_E;

    float *agg, *deg, *cposs, *ccnt, *cpos, *cinv;
    cudaGetSymbolAddress((void**)&agg,   g_agg);
    cudaGetSymbolAddress((void**)&deg,   g_deg);
    cudaGetSymbolAddress((void**)&cposs, g_cposs);
    cudaGetSymbolAddress((void**)&ccnt,  g_ccnt);
    cudaGetSymbolAddress((void**)&cpos,  g_cpos);
    cudaGetSymbolAddress((void**)&cinv,  g_cinv);

    cudaFuncSetAttribute(edge_kernel, cudaFuncAttributeMaxDynamicSharedMemorySize, SMEM_BYTES);
    cudaFuncSetAttribute(node_kernel, cudaFuncAttributeMaxDynamicSharedMemorySize, SMEM_BYTES);
    cudaFuncSetAttribute(pool_kernel, cudaFuncAttributeMaxDynamicSharedMemorySize, SMEM_BYTES);
    cudaFuncSetAttribute(eenc_kernel, cudaFuncAttributeMaxDynamicSharedMemorySize, SMEM_BYTES);

    cudaMemcpyAsync(vbuf, v0, sizeof(float) * (size_t)Nn * 128, cudaMemcpyDeviceToDevice, 0);
    cudaMemcpyAsync(ebuf, e0, sizeof(float) * (size_t)Ee * 128, cudaMemcpyDeviceToDevice, 0);

    const int* src  = ei;
    const int* dstp = ei + Ee;

    cudaMemsetAsync(deg, 0, sizeof(float) * Nn, 0);
    deg_scatter<<<(Ee + 255) / 256, 256>>>(dstp, deg);

    for (int d = 0; d < 4; d++) {
        cudaMemsetAsync(agg, 0, sizeof(float) * (size_t)Nn * 128, 0);
        edge_kernel<<<(Ee + 63) / 64, 128, SMEM_BYTES>>>(
            ebuf, vbuf, src, dstp,
            ew0 + (size_t)d * 384 * 128, eb0 + d * 128,
            ew1 + (size_t)d * 128 * 128, eb1 + d * 128,
            ew2 + (size_t)d * 128 * 128, eb2 + d * 128, agg);
        node_kernel<<<(Nn + 63) / 64, 128, SMEM_BYTES>>>(
            vbuf, agg, deg,
            nw0 + (size_t)d * 256 * 128, nb0 + d * 128,
            nw1 + (size_t)d * 128 * 128, nb1 + d * 128,
            nw2 + (size_t)d * 128 * 128, nb2 + d * 128);
    }

    cudaMemsetAsync(cposs, 0, sizeof(float) * NCc * 2, 0);
    cudaMemsetAsync(ccnt, 0, sizeof(float) * NCc, 0);
    cpos_scatter<<<(Nn + 255) / 256, 256>>>(pos, cluster, cposs, ccnt);
    cpos_fin<<<(NCc + 255) / 256, 256>>>(cposs, ccnt, cpos, cinv);

    cudaMemsetAsync(out_vc, 0, sizeof(float) * NCc * 128, 0);
    pool_kernel<<<(Nn + 63) / 64, 128, SMEM_BYTES>>>(vbuf, pos, cluster, cpos,
                                                     pw0, pb0, pw1, pb1, pw2, pb2, out_vc);
    vc_scale<<<(NCc * 128 + 255) / 256, 256>>>(out_vc, cinv);

    eenc_kernel<<<(ECc + 63) / 64, 128, SMEM_BYTES>>>(cei, cpos, qw0, qb0, qw1, qb1, qw2, qb2, out_ec);
}

// round 9
// speedup vs baseline: 1.4145x; 1.4145x over previous
#include <cuda_runtime.h>
#include <cuda_bf16.h>
#include <math.h>

#define Nn  50000
#define Ee  300000
#define NCc 12500
#define ECc 75000

#define OFF_EC 1600000
#define OFF_V  11200000
#define OFF_E  17600000

typedef unsigned long long ull;
typedef unsigned int uint32;

// tcgen05 only exists on the 'a' target
#if defined(__CUDA_ARCH__) && defined(__CUDA_ARCH_FEAT_SM103_ALL)
#define TC_PATH 1
#else
#define TC_PATH 0
#endif

// ================= device scratch =================
__device__ float g_agg[Nn * 128];
__device__ float g_deg[Nn];
__device__ float g_cposs[NCc * 2];
__device__ float g_ccnt[NCc];
__device__ float g_cpos[NCc * 2];
__device__ float g_cinv[NCc];
// prepped edge weights: 4 blocks x 10 chunks x (hi 8192 + lo 8192) bf16
__device__ unsigned short g_wt[4 * 10 * 16384];

__device__ __forceinline__ float selu_f(float x) {
    return x > 0.f ? 1.0507009873554805f * x : 1.7580993408473766f * expm1f(x);
}

// ================= SIMT FFMA2 machinery =================
#define AS_OFF 0
#define AS_BUF 1280
#define BS_OFF 2560
#define BS_BUF 3072
#define HS_OFF 8704
#define IX_OFF 17152
#define SIMT_SMEM ((17152 + 160) * 4)

__device__ __forceinline__ void ffma2(ull& d, ull a, ull b) {
    asm("fma.rn.f32x2 %0, %1, %2, %0;" : "+l"(d) : "l"(a), "l"(b));
}
__device__ __forceinline__ float2 unpk(ull p) {
    float2 f;
    asm("mov.b64 {%0, %1}, %2;" : "=f"(f.x), "=f"(f.y) : "l"(p));
    return f;
}
__device__ __forceinline__ ull dupf(float x) {
    ull r;
    asm("mov.b64 %0, {%1, %1};" : "=l"(r) : "f"(x));
    return r;
}
__device__ __forceinline__ void acc_init(ull (&acc)[8][4], const float* __restrict__ b, int c0) {
    ull bb[4];
#pragma unroll
    for (int j = 0; j < 4; j++) bb[j] = *(const ull*)&b[c0 + 2 * j];
#pragma unroll
    for (int i = 0; i < 8; i++)
#pragma unroll
        for (int j = 0; j < 4; j++) acc[i][j] = bb[j];
}
__device__ __forceinline__ void fill_Bs(float* Bs, const float* __restrict__ W, int kt, int t) {
    const float4* wsrc = (const float4*)(W + (size_t)kt * 128);
#pragma unroll
    for (int i = 0; i < 4; i++) {
        int fi = i * 128 + t;
        float4 w = wsrc[fi];
        int k = fi >> 5;
        int q = fi & 31;
        *(float4*)&Bs[k * 192 + (q >> 1) * 12 + (q & 1) * 4] = w;
    }
}
template <int STRIDE>
__device__ __forceinline__ void mma16(const float* A, int koff, const float* Bs,
                                      int r0, int gb, ull (&acc)[8][4]) {
#pragma unroll
    for (int k4 = 0; k4 < 4; k4++) {
        float4 a4[8];
#pragma unroll
        for (int i = 0; i < 8; i++)
            a4[i] = *(const float4*)&A[(r0 + i) * STRIDE + koff + 4 * k4];
#pragma unroll
        for (int kk = 0; kk < 4; kk++) {
            const float* bp = &Bs[(4 * k4 + kk) * 192 + gb];
            ulonglong2 bA = *(const ulonglong2*)bp;
            ulonglong2 bB = *(const ulonglong2*)(bp + 4);
#pragma unroll
            for (int i = 0; i < 8; i++) {
                float av = (kk == 0) ? a4[i].x : (kk == 1) ? a4[i].y
                         : (kk == 2) ? a4[i].z : a4[i].w;
                ull ad = dupf(av);
                ffma2(acc[i][0], ad, bA.x);
                ffma2(acc[i][1], ad, bA.y);
                ffma2(acc[i][2], ad, bB.x);
                ffma2(acc[i][3], ad, bB.y);
            }
        }
    }
}
__device__ __forceinline__ void selu_store(float* Hs, ull (&acc)[8][4], int r0, int c0) {
#pragma unroll
    for (int i = 0; i < 8; i++) {
        float2 p0 = unpk(acc[i][0]), p1 = unpk(acc[i][1]);
        float2 p2 = unpk(acc[i][2]), p3 = unpk(acc[i][3]);
        *(float4*)&Hs[(r0 + i) * 132 + c0] =
            make_float4(selu_f(p0.x), selu_f(p0.y), selu_f(p1.x), selu_f(p1.y));
        *(float4*)&Hs[(r0 + i) * 132 + c0 + 4] =
            make_float4(selu_f(p2.x), selu_f(p2.y), selu_f(p3.x), selu_f(p3.y));
    }
}
__device__ __forceinline__ void hidden_layer(const float* __restrict__ W,
                                             const float* Hs, float* BsBase,
                                             int t, int r0, int gb, ull (&acc)[8][4]) {
    fill_Bs(BsBase, W, 0, t);
    __syncthreads();
#pragma unroll 1
    for (int kt = 0; kt < 8; kt++) {
        if (kt < 7) fill_Bs(BsBase + ((kt + 1) & 1) * BS_BUF, W, (kt + 1) * 16, t);
        mma16<132>(Hs, kt * 16, BsBase + (kt & 1) * BS_BUF, r0, gb, acc);
        __syncthreads();
    }
}

// FFMA2 edge tile (64 rows) — fallback body for non-'a' compilation
__device__ void edge_simt_tile(
    float* sm, float* __restrict__ e, const float* __restrict__ v,
    const int* __restrict__ src, const int* __restrict__ dst,
    const float* __restrict__ w0, const float* __restrict__ b0,
    const float* __restrict__ w1, const float* __restrict__ b1,
    const float* __restrict__ w2, const float* __restrict__ b2,
    float* __restrict__ agg, int row0, int t) {
    float* As = sm + AS_OFF;
    float* Bs = sm + BS_OFF;
    float* Hs = sm + HS_OFF;
    int* s_src = (int*)(sm + IX_OFF);
    int* s_dst = s_src + 64;

    __syncthreads();
    if (t < 64) {
        int r = row0 + t;
        if (r >= Ee) r = Ee - 1;
        s_src[t] = src[r];
        s_dst[t] = dst[r];
    }
    const int c0 = (t & 15) * 8;
    const int gb = (t & 15) * 12;
    const int r0 = (t >> 4) * 8;
    __syncthreads();

    ull acc[8][4];
    acc_init(acc, b0, c0);

    auto fill_As = [&](float* dstA, int kt) {
#pragma unroll
        for (int i = 0; i < 2; i++) {
            int f = t * 2 + i;
            int ar = f >> 2;
            int kl = (f & 3) << 2;
            int k = kt + kl;
            int grow = row0 + ar;
            if (grow >= Ee) grow = Ee - 1;
            float4 val;
            if (k < 128)      val = *(const float4*)(e + (size_t)grow * 128 + k);
            else if (k < 256) val = *(const float4*)(v + (size_t)s_src[ar] * 128 + (k - 128));
            else              val = *(const float4*)(v + (size_t)s_dst[ar] * 128 + (k - 256));
            *(float4*)&dstA[ar * 20 + kl] = val;
        }
    };
    fill_As(As, 0);
    fill_Bs(Bs, w0, 0, t);
    __syncthreads();
#pragma unroll 1
    for (int kt = 0; kt < 24; kt++) {
        if (kt < 23) {
            int nb = (kt + 1) & 1;
            fill_As(As + nb * AS_BUF, (kt + 1) * 16);
            fill_Bs(Bs + nb * BS_BUF, w0, (kt + 1) * 16, t);
        }
        mma16<20>(As + (kt & 1) * AS_BUF, 0, Bs + (kt & 1) * BS_BUF, r0, gb, acc);
        __syncthreads();
    }
    selu_store(Hs, acc, r0, c0);
    acc_init(acc, b1, c0);
    hidden_layer(w1, Hs, Bs, t, r0, gb, acc);
    selu_store(Hs, acc, r0, c0);
    acc_init(acc, b2, c0);
    hidden_layer(w2, Hs, Bs, t, r0, gb, acc);

#pragma unroll
    for (int i = 0; i < 8; i++) {
        int row = row0 + r0 + i;
        if (row < Ee) {
            int dn = s_dst[r0 + i];
            float* erow = e + (size_t)row * 128 + c0;
            float* arow = agg + (size_t)dn * 128 + c0;
            float2 p0 = unpk(acc[i][0]), p1 = unpk(acc[i][1]);
            float2 p2 = unpk(acc[i][2]), p3 = unpk(acc[i][3]);
            float4 e0 = *(float4*)erow;
            float4 e1 = *(float4*)(erow + 4);
            float rr[8] = {e0.x + p0.x, e0.y + p0.y, e0.z + p1.x, e0.w + p1.y,
                           e1.x + p2.x, e1.y + p2.y, e1.z + p3.x, e1.w + p3.y};
            *(float4*)erow       = make_float4(rr[0], rr[1], rr[2], rr[3]);
            *(float4*)(erow + 4) = make_float4(rr[4], rr[5], rr[6], rr[7]);
#pragma unroll
            for (int j = 0; j < 8; j++) atomicAdd(&arow[j], rr[j]);
        }
    }
}

// ================= tcgen05 helpers (sm_103a only) =================
#if TC_PATH
__device__ __forceinline__ uint32 elect_one_pred() {
    uint32 pred;
    asm volatile("{\n\t.reg .pred p;\n\telect.sync _|p, 0xFFFFFFFF;\n\tselp.b32 %0, 1, 0, p;\n\t}" : "=r"(pred));
    return pred;
}
__device__ __forceinline__ uint32 smem_u32(const void* p) {
    uint32 a;
    asm("{ .reg .u64 tmp; cvta.to.shared.u64 tmp, %1; cvt.u32.u64 %0, tmp; }" : "=r"(a) : "l"(p));
    return a;
}
#define MBARRIER_INIT(addr, cnt) \
    asm volatile("mbarrier.init.shared.b64 [%0], %1;" :: "r"((uint32)(addr)), "r"((uint32)(cnt)) : "memory")
#define MBARRIER_WAIT_PARITY(addr, par) do {                                            \
    uint32 _m = (uint32)(addr); uint32 _p = (uint32)(par); uint32 _d;                   \
    asm volatile("{\n\t.reg .pred p;\n\t"                                               \
        "mbarrier.try_wait.parity.acquire.cta.shared::cta.b64 p, [%1], %2;\n\t"         \
        "selp.b32 %0, 1, 0, p;\n\t}" : "=r"(_d) : "r"(_m), "r"(_p) : "memory");         \
    if (!_d) {                                                                          \
        asm volatile("{\n\t.reg .pred P1;\n\t"                                          \
            "WL_%=:\n\t"                                                                \
            "mbarrier.try_wait.parity.acquire.cta.shared::cta.b64 P1, [%0], %1, 0x989680;\n\t" \
            "@P1 bra.uni WD_%=;\n\tbra.uni WL_%=;\n\tWD_%=:\n\t}"                        \
            :: "r"(_m), "r"(_p) : "memory");                                            \
    } } while (0)
#define TCGEN05_ALLOC(slot, n) \
    asm volatile("tcgen05.alloc.cta_group::1.sync.aligned.shared::cta.b32 [%0], %1;" :: "r"((uint32)(slot)), "r"((uint32)(n)) : "memory")
#define TCGEN05_DEALLOC(tm, n) \
    asm volatile("tcgen05.dealloc.cta_group::1.sync.aligned.b32 %0, %1;" :: "r"(tm), "r"((uint32)(n)))
#define TCGEN05_RELINQ() \
    asm volatile("tcgen05.relinquish_alloc_permit.cta_group::1.sync.aligned;")
#define TCGEN05_COMMIT(mb) \
    asm volatile("tcgen05.commit.cta_group::1.mbarrier::arrive::one.shared::cluster.b64 [%0];" :: "r"((uint32)(mb)) : "memory")
#define TCGEN05_WAIT_LD() asm volatile("tcgen05.wait::ld.sync.aligned;" ::: "memory")
#define TCGEN05_FENCE_BEFORE() asm volatile("tcgen05.fence::before_thread_sync;" ::: "memory")
#define TCGEN05_FENCE_AFTER()  asm volatile("tcgen05.fence::after_thread_sync;" ::: "memory")
#define FENCE_PROXY_ASYNC() asm volatile("fence.proxy.async.shared::cta;" ::: "memory")
#define TCGEN05_LD_X32(r, tm) \
    asm volatile("tcgen05.ld.sync.aligned.32x32b.x32.b32 " \
        "{%0, %1, %2, %3, %4, %5, %6, %7, %8, %9, %10, %11, %12, %13, %14, %15, " \
        " %16, %17, %18, %19, %20, %21, %22, %23, %24, %25, %26, %27, %28, %29, %30, %31}, [%32];" \
        : "=r"((r)[0]),  "=r"((r)[1]),  "=r"((r)[2]),  "=r"((r)[3]),  "=r"((r)[4]),  "=r"((r)[5]),  "=r"((r)[6]),  "=r"((r)[7]), \
          "=r"((r)[8]),  "=r"((r)[9]),  "=r"((r)[10]), "=r"((r)[11]), "=r"((r)[12]), "=r"((r)[13]), "=r"((r)[14]), "=r"((r)[15]), \
          "=r"((r)[16]), "=r"((r)[17]), "=r"((r)[18]), "=r"((r)[19]), "=r"((r)[20]), "=r"((r)[21]), "=r"((r)[22]), "=r"((r)[23]), \
          "=r"((r)[24]), "=r"((r)[25]), "=r"((r)[26]), "=r"((r)[27]), "=r"((r)[28]), "=r"((r)[29]), "=r"((r)[30]), "=r"((r)[31]) \
        : "r"(tm))

static constexpr unsigned long long SMEM_DESC_BASE_SW128 =
    (2ull << 61) | (1ull << 46) | (64ull << 32) | (1ull << 16);
#define MAKE_SMEM_DESC(addr) (SMEM_DESC_BASE_SW128 | (((unsigned long long)((addr) >> 4)) & 0x3FFF))

// idesc: F32 acc, BF16 x BF16, M=128, N=128, K-major both
#define IDESC_BF 0x8200490u

__device__ __forceinline__ void mma_ss_bf16(uint32 d, unsigned long long a, unsigned long long b, uint32 en) {
    asm volatile(
        "{\n\t.reg .pred p;\n\tsetp.ne.u32 p, %4, 0;\n\t"
        "tcgen05.mma.cta_group::1.kind::f16 [%0], %1, %2, %3, {%5, %5, %5, %5}, p;\n\t}"
        :: "r"(d), "l"(a), "l"(b), "r"(IDESC_BF), "r"(en), "r"(0u) : "memory");
}
#endif  // TC_PATH

__device__ __forceinline__ void split2(float a, float b, unsigned& h, unsigned& l) {
    __nv_bfloat16 ha = __float2bfloat16(a), hb = __float2bfloat16(b);
    __nv_bfloat16 la = __float2bfloat16(a - __bfloat162float(ha));
    __nv_bfloat16 lb = __float2bfloat16(b - __bfloat162float(hb));
    h = (unsigned)__bfloat16_as_ushort(ha) | ((unsigned)__bfloat16_as_ushort(hb) << 16);
    l = (unsigned)__bfloat16_as_ushort(la) | ((unsigned)__bfloat16_as_ushort(lb) << 16);
}

// ===== weight prep: transpose + bf16 split + SW128 swizzle, per 64-K chunk =====
__global__ void prep_w_kernel(const float* __restrict__ w, int Kdim, unsigned short* __restrict__ outp) {
    int idx = blockIdx.x * blockDim.x + threadIdx.x;
    if (idx >= Kdim * 128) return;
    int k = idx >> 7, n = idx & 127;
    float x = w[(size_t)k * 128 + n];
    __nv_bfloat16 h = __float2bfloat16(x);
    __nv_bfloat16 l = __float2bfloat16(x - __bfloat162float(h));
    int c = k >> 6, kl = k & 63;
    int byte = n * 128 + kl * 2;
    int sw = byte ^ ((byte >> 3) & 0x70);
    char* base = (char*)(outp + (size_t)c * 16384);
    *(unsigned short*)(base + sw) = __bfloat16_as_ushort(h);
    *(unsigned short*)(base + 16384 + sw) = __bfloat16_as_ushort(l);
}

// ================= edge kernel: tcgen05 on sm_103a, FFMA2 fallback elsewhere =================
#define EDGE_SMEM (1024 + 131072 + 2080)

__global__ void __launch_bounds__(128) edge_tc_kernel(
    float* __restrict__ e, const float* __restrict__ v,
    const int* __restrict__ src, const int* __restrict__ dst,
    const unsigned short* __restrict__ wt,
    const float* __restrict__ w0f, const float* __restrict__ w1f, const float* __restrict__ w2f,
    const float* __restrict__ b0, const float* __restrict__ b1, const float* __restrict__ b2,
    float* __restrict__ agg) {
    extern __shared__ float smraw[];
#if TC_PATH
    uint32 raw = smem_u32(smraw);
    uint32 sb = (raw + 1023) & ~1023u;
    char* gb = (char*)smraw + (sb - raw);

    const uint32 A_B = sb;
    const uint32 W_B = sb + 65536;
    const uint32 MISC = sb + 131072;
    char* A_g = gb;
    char* W_g = gb + 65536;
    uint32 slot = MISC;
    uint32 mb0 = MISC + 8, mb1 = MISC + 16;
    int* s_src = (int*)(gb + 131072 + 32);
    int* s_dst = s_src + 128;

    const int t = threadIdx.x;
    const int wid = t >> 5, lid = t & 31;
    const int row0 = blockIdx.x * 128;

    {
        int r = row0 + t;
        if (r >= Ee) r = Ee - 1;
        s_src[t] = src[r];
        s_dst[t] = dst[r];
    }
    if (t == 0) { MBARRIER_INIT(mb0, 1); MBARRIER_INIT(mb1, 1); }
    if (wid == 0) { TCGEN05_ALLOC(slot, 128); TCGEN05_RELINQ(); }
    __syncthreads();
    uint32 tmb;
    asm volatile("ld.shared.b32 %0, [%1];" : "=r"(tmb) : "r"(slot));

    // A tile fill: 128 rows x 64 bf16 (hi) + 64 bf16 (lo), SW128 swizzled.
    // 2048 8-byte segments: row = fi>>4 (0..127), q = fi&15 (0..15).
    auto fill_A = [&](int kc) {
        char* hi = A_g + (kc & 1) * 32768;
        char* lo = hi + 16384;
#pragma unroll
        for (int i = 0; i < 16; i++) {
            int fi = i * 128 + t;
            int row = fi >> 4, q = fi & 15;
            int grow = row0 + row; if (grow >= Ee) grow = Ee - 1;
            const float* rp;
            if (kc < 2)      rp = e + (size_t)grow * 128;
            else if (kc < 4) rp = v + (size_t)s_src[row] * 128;
            else             rp = v + (size_t)s_dst[row] * 128;
            float4 x = *(const float4*)(rp + (kc & 1) * 64 + q * 4);
            uint2 hb, lb;
            split2(x.x, x.y, hb.x, lb.x);
            split2(x.z, x.w, hb.y, lb.y);
            int byte = row * 128 + q * 8;
            int sw = byte ^ ((byte >> 3) & 0x70);
            *(uint2*)(hi + sw) = hb;
            *(uint2*)(lo + sw) = lb;
        }
    };
    auto fill_W = [&](const unsigned short* chunk, int b) {
        const uint4* s = (const uint4*)chunk;
        uint4* d = (uint4*)(W_g + b * 32768);
#pragma unroll
        for (int i = 0; i < 16; i++) d[i * 128 + t] = s[i * 128 + t];
    };
    auto mma_chunk = [&](uint32 aoff, int b, bool first) {
        if (wid == 0 && elect_one_pred()) {
            FENCE_PROXY_ASYNC();
            unsigned long long ah = MAKE_SMEM_DESC(aoff);
            unsigned long long al = MAKE_SMEM_DESC(aoff + 16384);
            unsigned long long wh = MAKE_SMEM_DESC(W_B + b * 32768);
            unsigned long long wl = MAKE_SMEM_DESC(W_B + b * 32768 + 16384);
            uint32 en = first ? 0u : 1u;
#pragma unroll
            for (int s = 0; s < 4; s++) {
                mma_ss_bf16(tmb, ah + s * 2, wh + s * 2, en); en = 1u;
                mma_ss_bf16(tmb, ah + s * 2, wl + s * 2, 1u);
                mma_ss_bf16(tmb, al + s * 2, wh + s * 2, 1u);
            }
            TCGEN05_COMMIT(b ? mb1 : mb0);
        }
    };
    auto epi_hidden = [&](const float* __restrict__ bias) {
        TCGEN05_FENCE_AFTER();
        int r = wid * 32 + lid;
#pragma unroll 1
        for (int cb = 0; cb < 4; cb++) {
            uint32 d[32];
            TCGEN05_LD_X32(d, tmb + cb * 32);
            TCGEN05_WAIT_LD();
            char* hi = A_g + (cb >> 1) * 32768;
            char* lo = hi + 16384;
#pragma unroll
            for (int j = 0; j < 32; j += 2) {
                float x0 = selu_f(__uint_as_float(d[j])     + __ldg(&bias[cb * 32 + j]));
                float x1 = selu_f(__uint_as_float(d[j + 1]) + __ldg(&bias[cb * 32 + j + 1]));
                unsigned hb, lb;
                split2(x0, x1, hb, lb);
                int c = (cb & 1) * 32 + j;
                int byte = r * 128 + c * 2;
                int sw = byte ^ ((byte >> 3) & 0x70);
                *(unsigned*)(hi + sw) = hb;
                *(unsigned*)(lo + sw) = lb;
            }
        }
        TCGEN05_FENCE_BEFORE();
        __syncthreads();
    };

    // layer 0: K = 384, 6 chunks
    fill_A(0); fill_W(wt + 0 * 16384, 0); __syncthreads(); mma_chunk(A_B, 0, true);
    fill_A(1); fill_W(wt + 1 * 16384, 1); __syncthreads(); mma_chunk(A_B + 32768, 1, false);
    MBARRIER_WAIT_PARITY(mb0, 0);
    fill_A(2); fill_W(wt + 2 * 16384, 0); __syncthreads(); mma_chunk(A_B, 0, false);
    MBARRIER_WAIT_PARITY(mb1, 0);
    fill_A(3); fill_W(wt + 3 * 16384, 1); __syncthreads(); mma_chunk(A_B + 32768, 1, false);
    MBARRIER_WAIT_PARITY(mb0, 1);
    fill_A(4); fill_W(wt + 4 * 16384, 0); __syncthreads(); mma_chunk(A_B, 0, false);
    MBARRIER_WAIT_PARITY(mb1, 1);
    fill_A(5); fill_W(wt + 5 * 16384, 1); __syncthreads(); mma_chunk(A_B + 32768, 1, false);
    MBARRIER_WAIT_PARITY(mb0, 0); MBARRIER_WAIT_PARITY(mb1, 0);
    epi_hidden(b0);

    // layer 1: K = 128, A resident in A region
    fill_W(wt + 6 * 16384, 0); __syncthreads(); mma_chunk(A_B, 0, true);
    fill_W(wt + 7 * 16384, 1); __syncthreads(); mma_chunk(A_B + 32768, 1, false);
    MBARRIER_WAIT_PARITY(mb0, 1); MBARRIER_WAIT_PARITY(mb1, 1);
    epi_hidden(b1);

    // layer 2
    fill_W(wt + 8 * 16384, 0); __syncthreads(); mma_chunk(A_B, 0, true);
    fill_W(wt + 9 * 16384, 1); __syncthreads(); mma_chunk(A_B + 32768, 1, false);
    MBARRIER_WAIT_PARITY(mb0, 0); MBARRIER_WAIT_PARITY(mb1, 0);

    // final epilogue: residual + store e + atomic agg
    TCGEN05_FENCE_AFTER();
    {
        int r = wid * 32 + lid;
        int grow = row0 + r;
        bool valid = grow < Ee;
        int dn = valid ? s_dst[r] : 0;
#pragma unroll 1
        for (int cb = 0; cb < 4; cb++) {
            uint32 d[32];
            TCGEN05_LD_X32(d, tmb + cb * 32);
            TCGEN05_WAIT_LD();
            if (valid) {
                float* erow = e + (size_t)grow * 128 + cb * 32;
                float* arow = agg + (size_t)dn * 128 + cb * 32;
#pragma unroll
                for (int q = 0; q < 8; q++) {
                    float4 ev = *(float4*)(erow + q * 4);
                    float4 rr;
                    rr.x = ev.x + __uint_as_float(d[q * 4 + 0]) + __ldg(&b2[cb * 32 + q * 4 + 0]);
                    rr.y = ev.y + __uint_as_float(d[q * 4 + 1]) + __ldg(&b2[cb * 32 + q * 4 + 1]);
                    rr.z = ev.z + __uint_as_float(d[q * 4 + 2]) + __ldg(&b2[cb * 32 + q * 4 + 2]);
                    rr.w = ev.w + __uint_as_float(d[q * 4 + 3]) + __ldg(&b2[cb * 32 + q * 4 + 3]);
                    *(float4*)(erow + q * 4) = rr;
                    atomicAdd(arow + q * 4 + 0, rr.x);
                    atomicAdd(arow + q * 4 + 1, rr.y);
                    atomicAdd(arow + q * 4 + 2, rr.z);
                    atomicAdd(arow + q * 4 + 3, rr.w);
                }
            }
        }
    }
    TCGEN05_FENCE_BEFORE();
    __syncthreads();
    if (wid == 0) TCGEN05_DEALLOC(tmb, 128);
#else
    // fallback: two 64-row FFMA2 passes (non-'a' target)
    const int t = threadIdx.x;
    const int row0 = blockIdx.x * 128;
    edge_simt_tile(smraw, e, v, src, dst, w0f, b0, w1f, b1, w2f, b2, agg, row0, t);
    edge_simt_tile(smraw, e, v, src, dst, w0f, b0, w1f, b1, w2f, b2, agg, row0 + 64, t);
#endif
}

// ---------------- node: v += MLP([v, agg/deg]) ----------------
__global__ void __launch_bounds__(128) node_kernel(
    float* __restrict__ v, const float* __restrict__ agg, const float* __restrict__ deg,
    const float* __restrict__ w0, const float* __restrict__ b0,
    const float* __restrict__ w1, const float* __restrict__ b1,
    const float* __restrict__ w2, const float* __restrict__ b2) {
    extern __shared__ float sm[];
    float* As = sm + AS_OFF;
    float* Bs = sm + BS_OFF;
    float* Hs = sm + HS_OFF;
    float* s_inv = sm + IX_OFF;

    const int t = threadIdx.x;
    const int row0 = blockIdx.x * 64;
    if (t < 64) {
        int r = row0 + t;
        if (r >= Nn) r = Nn - 1;
        s_inv[t] = 1.f / fmaxf(deg[r], 1.f);
    }
    const int c0 = (t & 15) * 8;
    const int gb = (t & 15) * 12;
    const int r0 = (t >> 4) * 8;
    __syncthreads();

    ull acc[8][4];
    acc_init(acc, b0, c0);

    auto fill_As = [&](float* dstA, int kt) {
#pragma unroll
        for (int i = 0; i < 2; i++) {
            int f = t * 2 + i;
            int ar = f >> 2;
            int kl = (f & 3) << 2;
            int k = kt + kl;
            int grow = row0 + ar;
            if (grow >= Nn) grow = Nn - 1;
            float4 val;
            if (k < 128) {
                val = *(const float4*)(v + (size_t)grow * 128 + k);
            } else {
                val = *(const float4*)(agg + (size_t)grow * 128 + (k - 128));
                float sc = s_inv[ar];
                val.x *= sc; val.y *= sc; val.z *= sc; val.w *= sc;
            }
            *(float4*)&dstA[ar * 20 + kl] = val;
        }
    };
    fill_As(As, 0);
    fill_Bs(Bs, w0, 0, t);
    __syncthreads();
#pragma unroll 1
    for (int kt = 0; kt < 16; kt++) {
        if (kt < 15) {
            int nb = (kt + 1) & 1;
            fill_As(As + nb * AS_BUF, (kt + 1) * 16);
            fill_Bs(Bs + nb * BS_BUF, w0, (kt + 1) * 16, t);
        }
        mma16<20>(As + (kt & 1) * AS_BUF, 0, Bs + (kt & 1) * BS_BUF, r0, gb, acc);
        __syncthreads();
    }
    selu_store(Hs, acc, r0, c0);
    acc_init(acc, b1, c0);
    hidden_layer(w1, Hs, Bs, t, r0, gb, acc);
    selu_store(Hs, acc, r0, c0);
    acc_init(acc, b2, c0);
    hidden_layer(w2, Hs, Bs, t, r0, gb, acc);

#pragma unroll
    for (int i = 0; i < 8; i++) {
        int row = row0 + r0 + i;
        if (row < Nn) {
            float* vrow = v + (size_t)row * 128 + c0;
            float2 p0 = unpk(acc[i][0]), p1 = unpk(acc[i][1]);
            float2 p2 = unpk(acc[i][2]), p3 = unpk(acc[i][3]);
            float4 v0 = *(float4*)vrow;
            float4 v1 = *(float4*)(vrow + 4);
            *(float4*)vrow       = make_float4(v0.x + p0.x, v0.y + p0.y, v0.z + p1.x, v0.w + p1.y);
            *(float4*)(vrow + 4) = make_float4(v1.x + p2.x, v1.y + p2.y, v1.z + p3.x, v1.w + p3.y);
        }
    }
}

// ---------------- pool: atomic-add MLP([v, rel]) into vc sums ----------------
__global__ void __launch_bounds__(128) pool_kernel(
    const float* __restrict__ v, const float* __restrict__ pos,
    const int* __restrict__ cluster, const float* __restrict__ cpos,
    const float* __restrict__ w0, const float* __restrict__ b0,
    const float* __restrict__ w1, const float* __restrict__ b1,
    const float* __restrict__ w2, const float* __restrict__ b2,
    float* __restrict__ vc) {
    extern __shared__ float sm[];
    float* As = sm + AS_OFF;
    float* Bs = sm + BS_OFF;
    float* Hs = sm + HS_OFF;
    float* s_rel = sm + IX_OFF;
    int* s_cl = (int*)(sm + IX_OFF + 64);

    const int t = threadIdx.x;
    const int row0 = blockIdx.x * 64;
    if (t < 64) {
        int r = row0 + t;
        if (r >= Nn) r = Nn - 1;
        int cl = cluster[r];
        float dx = pos[2 * r] - cpos[2 * cl];
        float dy = pos[2 * r + 1] - cpos[2 * cl + 1];
        s_rel[t] = sqrtf(dx * dx + dy * dy + 1e-12f);
        s_cl[t] = cl;
    }
    const int c0 = (t & 15) * 8;
    const int gb = (t & 15) * 12;
    const int r0 = (t >> 4) * 8;
    __syncthreads();

    ull acc[8][4];
    acc_init(acc, b0, c0);

    auto fill_As = [&](float* dstA, int kt) {
#pragma unroll
        for (int i = 0; i < 2; i++) {
            int f = t * 2 + i;
            int ar = f >> 2;
            int kl = (f & 3) << 2;
            int grow = row0 + ar;
            if (grow >= Nn) grow = Nn - 1;
            float4 val = *(const float4*)(v + (size_t)grow * 128 + kt + kl);
            *(float4*)&dstA[ar * 20 + kl] = val;
        }
    };
    fill_As(As, 0);
    fill_Bs(Bs, w0, 0, t);
    __syncthreads();
#pragma unroll 1
    for (int kt = 0; kt < 8; kt++) {
        if (kt < 7) {
            int nb = (kt + 1) & 1;
            fill_As(As + nb * AS_BUF, (kt + 1) * 16);
            fill_Bs(Bs + nb * BS_BUF, w0, (kt + 1) * 16, t);
        }
        mma16<20>(As + (kt & 1) * AS_BUF, 0, Bs + (kt & 1) * BS_BUF, r0, gb, acc);
        __syncthreads();
    }
    {
        ull wx[4];
#pragma unroll
        for (int j = 0; j < 4; j++) wx[j] = *(const ull*)&w0[128 * 128 + c0 + 2 * j];
#pragma unroll
        for (int i = 0; i < 8; i++) {
            ull rl2 = dupf(s_rel[r0 + i]);
#pragma unroll
            for (int j = 0; j < 4; j++) ffma2(acc[i][j], rl2, wx[j]);
        }
    }
    selu_store(Hs, acc, r0, c0);
    acc_init(acc, b1, c0);
    hidden_layer(w1, Hs, Bs, t, r0, gb, acc);
    selu_store(Hs, acc, r0, c0);
    acc_init(acc, b2, c0);
    hidden_layer(w2, Hs, Bs, t, r0, gb, acc);

#pragma unroll
    for (int i = 0; i < 8; i++) {
        int row = row0 + r0 + i;
        if (row < Nn) {
            int cl = s_cl[r0 + i];
            float* crow = vc + (size_t)cl * 128 + c0;
            float2 p0 = unpk(acc[i][0]), p1 = unpk(acc[i][1]);
            float2 p2 = unpk(acc[i][2]), p3 = unpk(acc[i][3]);
            float rr[8] = {p0.x, p0.y, p1.x, p1.y, p2.x, p2.y, p3.x, p3.y};
#pragma unroll
            for (int j = 0; j < 8; j++) atomicAdd(&crow[j], rr[j]);
        }
    }
}

// ---------------- coarse edge encoder ----------------
__global__ void __launch_bounds__(128) eenc_kernel(
    const int* __restrict__ cei, const float* __restrict__ cpos,
    const float* __restrict__ w0, const float* __restrict__ b0,
    const float* __restrict__ w1, const float* __restrict__ b1,
    const float* __restrict__ w2, const float* __restrict__ b2,
    float* __restrict__ ec) {
    extern __shared__ float sm[];
    float* Bs = sm + BS_OFF;
    float* Hs = sm + HS_OFF;
    float* s_crel = sm + IX_OFF;

    const int t = threadIdx.x;
    const int row0 = blockIdx.x * 64;
    if (t < 64) {
        int r = row0 + t;
        if (r >= ECc) r = ECc - 1;
        int a = cei[r];
        int b = cei[ECc + r];
        float dx = cpos[2 * a] - cpos[2 * b];
        float dy = cpos[2 * a + 1] - cpos[2 * b + 1];
        s_crel[t] = sqrtf(dx * dx + dy * dy + 1e-12f);
    }
    const int c0 = (t & 15) * 8;
    const int gb = (t & 15) * 12;
    const int r0 = (t >> 4) * 8;
    __syncthreads();

#pragma unroll
    for (int i = 0; i < 8; i++) {
        float cr = s_crel[r0 + i];
#pragma unroll
        for (int j = 0; j < 8; j++)
            Hs[(r0 + i) * 132 + c0 + j] =
                selu_f(fmaf(cr, __ldg(&w0[c0 + j]), __ldg(&b0[c0 + j])));
    }

    ull acc[8][4];
    acc_init(acc, b1, c0);
    hidden_layer(w1, Hs, Bs, t, r0, gb, acc);
    selu_store(Hs, acc, r0, c0);
    acc_init(acc, b2, c0);
    hidden_layer(w2, Hs, Bs, t, r0, gb, acc);

#pragma unroll
    for (int i = 0; i < 8; i++) {
        int row = row0 + r0 + i;
        if (row < ECc) {
            float* erow = ec + (size_t)row * 128 + c0;
            float2 p0 = unpk(acc[i][0]), p1 = unpk(acc[i][1]);
            float2 p2 = unpk(acc[i][2]), p3 = unpk(acc[i][3]);
            *(float4*)erow       = make_float4(p0.x, p0.y, p1.x, p1.y);
            *(float4*)(erow + 4) = make_float4(p2.x, p2.y, p3.x, p3.y);
        }
    }
}

// ---------------- small helpers ----------------
__global__ void deg_scatter(const int* __restrict__ dst, float* __restrict__ deg) {
    int i = blockIdx.x * blockDim.x + threadIdx.x;
    if (i < Ee) atomicAdd(&deg[dst[i]], 1.f);
}
__global__ void cpos_scatter(const float* __restrict__ pos, const int* __restrict__ cluster,
                             float* __restrict__ cposs, float* __restrict__ ccnt) {
    int i = blockIdx.x * blockDim.x + threadIdx.x;
    if (i < Nn) {
        int c = cluster[i];
        atomicAdd(&cposs[2 * c], pos[2 * i]);
        atomicAdd(&cposs[2 * c + 1], pos[2 * i + 1]);
        atomicAdd(&ccnt[c], 1.f);
    }
}
__global__ void cpos_fin(const float* __restrict__ cposs, const float* __restrict__ ccnt,
                         float* __restrict__ cpos, float* __restrict__ cinv) {
    int c = blockIdx.x * blockDim.x + threadIdx.x;
    if (c < NCc) {
        float inv = 1.f / fmaxf(ccnt[c], 1.f);
        cpos[2 * c] = cposs[2 * c] * inv;
        cpos[2 * c + 1] = cposs[2 * c + 1] * inv;
        cinv[c] = inv;
    }
}
__global__ void vc_scale(float* __restrict__ vc, const float* __restrict__ cinv) {
    int i = blockIdx.x * blockDim.x + threadIdx.x;
    if (i < NCc * 128) vc[i] *= cinv[i >> 7];
}

// ---------------- launch ----------------
extern "C" void kernel_launch(void* const* d_in, const int* in_sizes, int n_in,
                              void* d_out, int out_size) {
    const float* v0      = (const float*)d_in[0];
    const float* e0      = (const float*)d_in[1];
    const float* pos     = (const float*)d_in[2];
    const int*   ei      = (const int*)d_in[3];
    const int*   cluster = (const int*)d_in[4];
    const int*   cei     = (const int*)d_in[5];
    const float* ew0 = (const float*)d_in[6],  *eb0 = (const float*)d_in[7];
    const float* ew1 = (const float*)d_in[8],  *eb1 = (const float*)d_in[9];
    const float* ew2 = (const float*)d_in[10], *eb2 = (const float*)d_in[11];
    const float* nw0 = (const float*)d_in[12], *nb0 = (const float*)d_in[13];
    const float* nw1 = (const float*)d_in[14], *nb1 = (const float*)d_in[15];
    const float* nw2 = (const float*)d_in[16], *nb2 = (const float*)d_in[17];
    const float* pw0 = (const float*)d_in[18], *pb0 = (const float*)d_in[19];
    const float* pw1 = (const float*)d_in[20], *pb1 = (const float*)d_in[21];
    const float* pw2 = (const float*)d_in[22], *pb2 = (const float*)d_in[23];
    const float* qw0 = (const float*)d_in[24], *qb0 = (const float*)d_in[25];
    const float* qw1 = (const float*)d_in[26], *qb1 = (const float*)d_in[27];
    const float* qw2 = (const float*)d_in[28], *qb2 = (const float*)d_in[29];

    float* out    = (float*)d_out;
    float* out_vc = out;
    float* out_ec = out + OFF_EC;
    float* vbuf   = out + OFF_V;
    float* ebuf   = out + OFF_E;

    float *agg, *deg, *cposs, *ccnt, *cpos, *cinv;
    unsigned short* wt;
    cudaGetSymbolAddress((void**)&agg,   g_agg);
    cudaGetSymbolAddress((void**)&deg,   g_deg);
    cudaGetSymbolAddress((void**)&cposs, g_cposs);
    cudaGetSymbolAddress((void**)&ccnt,  g_ccnt);
    cudaGetSymbolAddress((void**)&cpos,  g_cpos);
    cudaGetSymbolAddress((void**)&cinv,  g_cinv);
    cudaGetSymbolAddress((void**)&wt,    g_wt);

    cudaFuncSetAttribute(edge_tc_kernel, cudaFuncAttributeMaxDynamicSharedMemorySize, EDGE_SMEM);
    cudaFuncSetAttribute(node_kernel, cudaFuncAttributeMaxDynamicSharedMemorySize, SIMT_SMEM);
    cudaFuncSetAttribute(pool_kernel, cudaFuncAttributeMaxDynamicSharedMemorySize, SIMT_SMEM);
    cudaFuncSetAttribute(eenc_kernel, cudaFuncAttributeMaxDynamicSharedMemorySize, SIMT_SMEM);

    cudaMemcpyAsync(vbuf, v0, sizeof(float) * (size_t)Nn * 128, cudaMemcpyDeviceToDevice, 0);
    cudaMemcpyAsync(ebuf, e0, sizeof(float) * (size_t)Ee * 128, cudaMemcpyDeviceToDevice, 0);

    const int* src  = ei;
    const int* dstp = ei + Ee;

    cudaMemsetAsync(deg, 0, sizeof(float) * Nn, 0);
    deg_scatter<<<(Ee + 255) / 256, 256>>>(dstp, deg);

    // prep all edge-block weights (transpose + bf16 split + swizzle)
    for (int d = 0; d < 4; d++) {
        unsigned short* wtb = wt + (size_t)d * 163840;
        prep_w_kernel<<<(384 * 128 + 255) / 256, 256>>>(ew0 + (size_t)d * 384 * 128, 384, wtb);
        prep_w_kernel<<<(128 * 128 + 255) / 256, 256>>>(ew1 + (size_t)d * 128 * 128, 128, wtb + 6 * 16384);
        prep_w_kernel<<<(128 * 128 + 255) / 256, 256>>>(ew2 + (size_t)d * 128 * 128, 128, wtb + 8 * 16384);
    }

    for (int d = 0; d < 4; d++) {
        cudaMemsetAsync(agg, 0, sizeof(float) * (size_t)Nn * 128, 0);
        edge_tc_kernel<<<(Ee + 127) / 128, 128, EDGE_SMEM>>>(
            ebuf, vbuf, src, dstp, wt + (size_t)d * 163840,
            ew0 + (size_t)d * 384 * 128, ew1 + (size_t)d * 128 * 128, ew2 + (size_t)d * 128 * 128,
            eb0 + d * 128, eb1 + d * 128, eb2 + d * 128, agg);
        node_kernel<<<(Nn + 63) / 64, 128, SIMT_SMEM>>>(
            vbuf, agg, deg,
            nw0 + (size_t)d * 256 * 128, nb0 + d * 128,
            nw1 + (size_t)d * 128 * 128, nb1 + d * 128,
            nw2 + (size_t)d * 128 * 128, nb2 + d * 128);
    }

    cudaMemsetAsync(cposs, 0, sizeof(float) * NCc * 2, 0);
    cudaMemsetAsync(ccnt, 0, sizeof(float) * NCc, 0);
    cpos_scatter<<<(Nn + 255) / 256, 256>>>(pos, cluster, cposs, ccnt);
    cpos_fin<<<(NCc + 255) / 256, 256>>>(cposs, ccnt, cpos, cinv);

    cudaMemsetAsync(out_vc, 0, sizeof(float) * NCc * 128, 0);
    pool_kernel<<<(Nn + 63) / 64, 128, SIMT_SMEM>>>(vbuf, pos, cluster, cpos,
                                                    pw0, pb0, pw1, pb1, pw2, pb2, out_vc);
    vc_scale<<<(NCc * 128 + 255) / 256, 256>>>(out_vc, cinv);

    eenc_kernel<<<(ECc + 63) / 64, 128, SIMT_SMEM>>>(cei, cpos, qw0, qb0, qw1, qb1, qw2, qb2, out_ec);
}

// round 10
// speedup vs baseline: 2.0923x; 1.4792x over previous
#include <cuda_runtime.h>
#include <cuda_bf16.h>
#include <math.h>

#define Nn  50000
#define Ee  300000
#define NCc 12500
#define ECc 75000

#define OFF_EC 1600000
#define OFF_V  11200000
#define OFF_E  17600000

typedef unsigned long long ull;
typedef unsigned int uint32;

// tcgen05 only exists on the 'a' target
#if defined(__CUDA_ARCH__) && defined(__CUDA_ARCH_FEAT_SM103_ALL)
#define TC_PATH 1
#else
#define TC_PATH 0
#endif

// ================= device scratch =================
__device__ float g_agg[Nn * 128];
__device__ float g_deg[Nn];
__device__ float g_cposs[NCc * 2];
__device__ float g_ccnt[NCc];
__device__ float g_cpos[NCc * 2];
__device__ float g_cinv[NCc];
// prepped edge weights: 4 blocks x 10 chunks x (hi 8192 + lo 8192) bf16
__device__ unsigned short g_wt[4 * 10 * 16384];

__device__ __forceinline__ float selu_f(float x) {
    return x > 0.f ? 1.0507009873554805f * x : 1.7580993408473766f * expm1f(x);
}

// ================= SIMT FFMA2 machinery =================
#define AS_OFF 0
#define AS_BUF 1280
#define BS_OFF 2560
#define BS_BUF 3072
#define HS_OFF 8704
#define IX_OFF 17152
#define SIMT_FLOATS 17312
#define SIMT_SMEM (SIMT_FLOATS * 4)

__device__ __forceinline__ void ffma2(ull& d, ull a, ull b) {
    asm("fma.rn.f32x2 %0, %1, %2, %0;" : "+l"(d) : "l"(a), "l"(b));
}
__device__ __forceinline__ float2 unpk(ull p) {
    float2 f;
    asm("mov.b64 {%0, %1}, %2;" : "=f"(f.x), "=f"(f.y) : "l"(p));
    return f;
}
__device__ __forceinline__ ull dupf(float x) {
    ull r;
    asm("mov.b64 %0, {%1, %1};" : "=l"(r) : "f"(x));
    return r;
}
__device__ __forceinline__ void acc_init(ull (&acc)[8][4], const float* __restrict__ b, int c0) {
    ull bb[4];
#pragma unroll
    for (int j = 0; j < 4; j++) bb[j] = *(const ull*)&b[c0 + 2 * j];
#pragma unroll
    for (int i = 0; i < 8; i++)
#pragma unroll
        for (int j = 0; j < 4; j++) acc[i][j] = bb[j];
}
__device__ __forceinline__ void fill_Bs(float* Bs, const float* __restrict__ W, int kt, int t) {
    const float4* wsrc = (const float4*)(W + (size_t)kt * 128);
#pragma unroll
    for (int i = 0; i < 4; i++) {
        int fi = i * 128 + t;
        float4 w = wsrc[fi];
        int k = fi >> 5;
        int q = fi & 31;
        *(float4*)&Bs[k * 192 + (q >> 1) * 12 + (q & 1) * 4] = w;
    }
}
template <int STRIDE>
__device__ __forceinline__ void mma16(const float* A, int koff, const float* Bs,
                                      int r0, int gb, ull (&acc)[8][4]) {
#pragma unroll
    for (int k4 = 0; k4 < 4; k4++) {
        float4 a4[8];
#pragma unroll
        for (int i = 0; i < 8; i++)
            a4[i] = *(const float4*)&A[(r0 + i) * STRIDE + koff + 4 * k4];
#pragma unroll
        for (int kk = 0; kk < 4; kk++) {
            const float* bp = &Bs[(4 * k4 + kk) * 192 + gb];
            ulonglong2 bA = *(const ulonglong2*)bp;
            ulonglong2 bB = *(const ulonglong2*)(bp + 4);
#pragma unroll
            for (int i = 0; i < 8; i++) {
                float av = (kk == 0) ? a4[i].x : (kk == 1) ? a4[i].y
                         : (kk == 2) ? a4[i].z : a4[i].w;
                ull ad = dupf(av);
                ffma2(acc[i][0], ad, bA.x);
                ffma2(acc[i][1], ad, bA.y);
                ffma2(acc[i][2], ad, bB.x);
                ffma2(acc[i][3], ad, bB.y);
            }
        }
    }
}
__device__ __forceinline__ void selu_store(float* Hs, ull (&acc)[8][4], int r0, int c0) {
#pragma unroll
    for (int i = 0; i < 8; i++) {
        float2 p0 = unpk(acc[i][0]), p1 = unpk(acc[i][1]);
        float2 p2 = unpk(acc[i][2]), p3 = unpk(acc[i][3]);
        *(float4*)&Hs[(r0 + i) * 132 + c0] =
            make_float4(selu_f(p0.x), selu_f(p0.y), selu_f(p1.x), selu_f(p1.y));
        *(float4*)&Hs[(r0 + i) * 132 + c0 + 4] =
            make_float4(selu_f(p2.x), selu_f(p2.y), selu_f(p3.x), selu_f(p3.y));
    }
}
__device__ __forceinline__ void hidden_layer(const float* __restrict__ W,
                                             const float* Hs, float* BsBase,
                                             int t, int r0, int gb, ull (&acc)[8][4]) {
    fill_Bs(BsBase, W, 0, t);
    __syncthreads();
#pragma unroll 1
    for (int kt = 0; kt < 8; kt++) {
        if (kt < 7) fill_Bs(BsBase + ((kt + 1) & 1) * BS_BUF, W, (kt + 1) * 16, t);
        mma16<132>(Hs, kt * 16, BsBase + (kt & 1) * BS_BUF, r0, gb, acc);
        __syncthreads();
    }
}

// FFMA2 edge tile (64 rows) — fallback body for non-'a' compilation.
// NOTE: uniform loop/barrier structure — safe to call from two half-blocks.
__device__ void edge_simt_tile(
    float* sm, float* __restrict__ e, const float* __restrict__ v,
    const int* __restrict__ src, const int* __restrict__ dst,
    const float* __restrict__ w0, const float* __restrict__ b0,
    const float* __restrict__ w1, const float* __restrict__ b1,
    const float* __restrict__ w2, const float* __restrict__ b2,
    float* __restrict__ agg, int row0, int t) {
    float* As = sm + AS_OFF;
    float* Bs = sm + BS_OFF;
    float* Hs = sm + HS_OFF;
    int* s_src = (int*)(sm + IX_OFF);
    int* s_dst = s_src + 64;

    __syncthreads();
    if (t < 64) {
        int r = row0 + t;
        if (r >= Ee) r = Ee - 1;
        s_src[t] = src[r];
        s_dst[t] = dst[r];
    }
    const int c0 = (t & 15) * 8;
    const int gb = (t & 15) * 12;
    const int r0 = (t >> 4) * 8;
    __syncthreads();

    ull acc[8][4];
    acc_init(acc, b0, c0);

    auto fill_As = [&](float* dstA, int kt) {
#pragma unroll
        for (int i = 0; i < 2; i++) {
            int f = t * 2 + i;
            int ar = f >> 2;
            int kl = (f & 3) << 2;
            int k = kt + kl;
            int grow = row0 + ar;
            if (grow >= Ee) grow = Ee - 1;
            float4 val;
            if (k < 128)      val = *(const float4*)(e + (size_t)grow * 128 + k);
            else if (k < 256) val = *(const float4*)(v + (size_t)s_src[ar] * 128 + (k - 128));
            else              val = *(const float4*)(v + (size_t)s_dst[ar] * 128 + (k - 256));
            *(float4*)&dstA[ar * 20 + kl] = val;
        }
    };
    fill_As(As, 0);
    fill_Bs(Bs, w0, 0, t);
    __syncthreads();
#pragma unroll 1
    for (int kt = 0; kt < 24; kt++) {
        if (kt < 23) {
            int nb = (kt + 1) & 1;
            fill_As(As + nb * AS_BUF, (kt + 1) * 16);
            fill_Bs(Bs + nb * BS_BUF, w0, (kt + 1) * 16, t);
        }
        mma16<20>(As + (kt & 1) * AS_BUF, 0, Bs + (kt & 1) * BS_BUF, r0, gb, acc);
        __syncthreads();
    }
    selu_store(Hs, acc, r0, c0);
    acc_init(acc, b1, c0);
    hidden_layer(w1, Hs, Bs, t, r0, gb, acc);
    selu_store(Hs, acc, r0, c0);
    acc_init(acc, b2, c0);
    hidden_layer(w2, Hs, Bs, t, r0, gb, acc);

#pragma unroll
    for (int i = 0; i < 8; i++) {
        int row = row0 + r0 + i;
        if (row < Ee) {
            int dn = s_dst[r0 + i];
            float* erow = e + (size_t)row * 128 + c0;
            float* arow = agg + (size_t)dn * 128 + c0;
            float2 p0 = unpk(acc[i][0]), p1 = unpk(acc[i][1]);
            float2 p2 = unpk(acc[i][2]), p3 = unpk(acc[i][3]);
            float4 e0 = *(float4*)erow;
            float4 e1 = *(float4*)(erow + 4);
            float rr[8] = {e0.x + p0.x, e0.y + p0.y, e0.z + p1.x, e0.w + p1.y,
                           e1.x + p2.x, e1.y + p2.y, e1.z + p3.x, e1.w + p3.y};
            *(float4*)erow       = make_float4(rr[0], rr[1], rr[2], rr[3]);
            *(float4*)(erow + 4) = make_float4(rr[4], rr[5], rr[6], rr[7]);
#pragma unroll
            for (int j = 0; j < 8; j++) atomicAdd(&arow[j], rr[j]);
        }
    }
}

// ================= tcgen05 helpers (sm_103a only) =================
#if TC_PATH
__device__ __forceinline__ uint32 elect_one_pred() {
    uint32 pred;
    asm volatile("{\n\t.reg .pred p;\n\telect.sync _|p, 0xFFFFFFFF;\n\tselp.b32 %0, 1, 0, p;\n\t}" : "=r"(pred));
    return pred;
}
__device__ __forceinline__ uint32 smem_u32(const void* p) {
    uint32 a;
    asm("{ .reg .u64 tmp; cvta.to.shared.u64 tmp, %1; cvt.u32.u64 %0, tmp; }" : "=r"(a) : "l"(p));
    return a;
}
#define MBARRIER_INIT(addr, cnt) \
    asm volatile("mbarrier.init.shared.b64 [%0], %1;" :: "r"((uint32)(addr)), "r"((uint32)(cnt)) : "memory")
#define MBARRIER_WAIT_PARITY(addr, par) do {                                            \
    uint32 _m = (uint32)(addr); uint32 _p = (uint32)(par); uint32 _d;                   \
    asm volatile("{\n\t.reg .pred p;\n\t"                                               \
        "mbarrier.try_wait.parity.acquire.cta.shared::cta.b64 p, [%1], %2;\n\t"         \
        "selp.b32 %0, 1, 0, p;\n\t}" : "=r"(_d) : "r"(_m), "r"(_p) : "memory");         \
    if (!_d) {                                                                          \
        asm volatile("{\n\t.reg .pred P1;\n\t"                                          \
            "WL_%=:\n\t"                                                                \
            "mbarrier.try_wait.parity.acquire.cta.shared::cta.b64 P1, [%0], %1, 0x989680;\n\t" \
            "@P1 bra.uni WD_%=;\n\tbra.uni WL_%=;\n\tWD_%=:\n\t}"                        \
            :: "r"(_m), "r"(_p) : "memory");                                            \
    } } while (0)
#define TCGEN05_ALLOC(slot, n) \
    asm volatile("tcgen05.alloc.cta_group::1.sync.aligned.shared::cta.b32 [%0], %1;" :: "r"((uint32)(slot)), "r"((uint32)(n)) : "memory")
#define TCGEN05_DEALLOC(tm, n) \
    asm volatile("tcgen05.dealloc.cta_group::1.sync.aligned.b32 %0, %1;" :: "r"(tm), "r"((uint32)(n)))
#define TCGEN05_RELINQ() \
    asm volatile("tcgen05.relinquish_alloc_permit.cta_group::1.sync.aligned;")
#define TCGEN05_COMMIT(mb) \
    asm volatile("tcgen05.commit.cta_group::1.mbarrier::arrive::one.shared::cluster.b64 [%0];" :: "r"((uint32)(mb)) : "memory")
#define TCGEN05_WAIT_LD() asm volatile("tcgen05.wait::ld.sync.aligned;" ::: "memory")
#define TCGEN05_FENCE_BEFORE() asm volatile("tcgen05.fence::before_thread_sync;" ::: "memory")
#define TCGEN05_FENCE_AFTER()  asm volatile("tcgen05.fence::after_thread_sync;" ::: "memory")
#define FENCE_PROXY_ASYNC() asm volatile("fence.proxy.async.shared::cta;" ::: "memory")
#define TCGEN05_LD_X32(r, tm) \
    asm volatile("tcgen05.ld.sync.aligned.32x32b.x32.b32 " \
        "{%0, %1, %2, %3, %4, %5, %6, %7, %8, %9, %10, %11, %12, %13, %14, %15, " \
        " %16, %17, %18, %19, %20, %21, %22, %23, %24, %25, %26, %27, %28, %29, %30, %31}, [%32];" \
        : "=r"((r)[0]),  "=r"((r)[1]),  "=r"((r)[2]),  "=r"((r)[3]),  "=r"((r)[4]),  "=r"((r)[5]),  "=r"((r)[6]),  "=r"((r)[7]), \
          "=r"((r)[8]),  "=r"((r)[9]),  "=r"((r)[10]), "=r"((r)[11]), "=r"((r)[12]), "=r"((r)[13]), "=r"((r)[14]), "=r"((r)[15]), \
          "=r"((r)[16]), "=r"((r)[17]), "=r"((r)[18]), "=r"((r)[19]), "=r"((r)[20]), "=r"((r)[21]), "=r"((r)[22]), "=r"((r)[23]), \
          "=r"((r)[24]), "=r"((r)[25]), "=r"((r)[26]), "=r"((r)[27]), "=r"((r)[28]), "=r"((r)[29]), "=r"((r)[30]), "=r"((r)[31]) \
        : "r"(tm))

static constexpr unsigned long long SMEM_DESC_BASE_SW128 =
    (2ull << 61) | (1ull << 46) | (64ull << 32) | (1ull << 16);
#define MAKE_SMEM_DESC(addr) (SMEM_DESC_BASE_SW128 | (((unsigned long long)((addr) >> 4)) & 0x3FFF))

// idesc: F32 acc, BF16 x BF16, M=128, N=128, K-major both
#define IDESC_BF 0x8200490u

__device__ __forceinline__ void mma_ss_bf16(uint32 d, unsigned long long a, unsigned long long b, uint32 en) {
    asm volatile(
        "{\n\t.reg .pred p;\n\tsetp.ne.u32 p, %4, 0;\n\t"
        "tcgen05.mma.cta_group::1.kind::f16 [%0], %1, %2, %3, {%5, %5, %5, %5}, p;\n\t}"
        :: "r"(d), "l"(a), "l"(b), "r"(IDESC_BF), "r"(en), "r"(0u) : "memory");
}
#endif  // TC_PATH

// split pair of fp32 into packed bf16 hi + packed bf16 residual (2 cvt total)
__device__ __forceinline__ void split2(float a, float b, unsigned& h, unsigned& l) {
    asm("cvt.rn.bf16x2.f32 %0, %1, %2;" : "=r"(h) : "f"(b), "f"(a));
    float ha = __uint_as_float(h << 16);
    float hb = __uint_as_float(h & 0xffff0000u);
    asm("cvt.rn.bf16x2.f32 %0, %1, %2;" : "=r"(l) : "f"(b - hb), "f"(a - ha));
}

// ===== weight prep: transpose + bf16 split + SW128 swizzle, per 64-K chunk =====
__global__ void prep_w_kernel(const float* __restrict__ w, int Kdim, unsigned short* __restrict__ outp) {
    int idx = blockIdx.x * blockDim.x + threadIdx.x;
    if (idx >= Kdim * 128) return;
    int k = idx >> 7, n = idx & 127;
    float x = w[(size_t)k * 128 + n];
    __nv_bfloat16 h = __float2bfloat16(x);
    __nv_bfloat16 l = __float2bfloat16(x - __bfloat162float(h));
    int c = k >> 6, kl = k & 63;
    int byte = n * 128 + kl * 2;
    int sw = byte ^ ((byte >> 3) & 0x70);
    char* base = (char*)(outp + (size_t)c * 16384);
    *(unsigned short*)(base + sw) = __bfloat16_as_ushort(h);
    *(unsigned short*)(base + 16384 + sw) = __bfloat16_as_ushort(l);
}

// ================= edge kernel: tcgen05 on sm_103a, FFMA2 fallback elsewhere =================
// 256 threads. TC smem: A 64KB | W 64KB | misc. Fallback: 2 x SIMT tile regions.
#define EDGE_SMEM 138496

__global__ void __launch_bounds__(256) edge_tc_kernel(
    float* __restrict__ e, const float* __restrict__ v,
    const int* __restrict__ src, const int* __restrict__ dst,
    const unsigned short* __restrict__ wt,
    const float* __restrict__ w0f, const float* __restrict__ w1f, const float* __restrict__ w2f,
    const float* __restrict__ b0, const float* __restrict__ b1, const float* __restrict__ b2,
    float* __restrict__ agg) {
    extern __shared__ float smraw[];
#if TC_PATH
    uint32 raw = smem_u32(smraw);
    uint32 sb = (raw + 1023) & ~1023u;
    char* gb = (char*)smraw + (sb - raw);

    const uint32 A_B = sb;
    const uint32 W_B = sb + 65536;
    const uint32 MISC = sb + 131072;
    char* A_g = gb;
    char* W_g = gb + 65536;
    uint32 slot = MISC;
    uint32 mb0 = MISC + 8, mb1 = MISC + 16;
    int* s_src = (int*)(gb + 131072 + 32);
    int* s_dst = s_src + 128;

    const int t = threadIdx.x;
    const int wid = t >> 5, lid = t & 31;
    const int row0 = blockIdx.x * 128;

    if (t < 128) {
        int r = row0 + t;
        if (r >= Ee) r = Ee - 1;
        s_src[t] = src[r];
        s_dst[t] = dst[r];
    }
    if (t == 0) { MBARRIER_INIT(mb0, 1); MBARRIER_INIT(mb1, 1); }
    if (wid == 0) { TCGEN05_ALLOC(slot, 128); TCGEN05_RELINQ(); }
    __syncthreads();
    uint32 tmb;
    asm volatile("ld.shared.b32 %0, [%1];" : "=r"(tmb) : "r"(slot));

    // A tile fill: 128 rows x 64 bf16 (hi) + 64 bf16 (lo), SW128 swizzled.
    // 2048 8-byte segments over 256 threads: 8 iterations.
    auto fill_A = [&](int kc) {
        char* hi = A_g + (kc & 1) * 32768;
        char* lo = hi + 16384;
#pragma unroll
        for (int i = 0; i < 8; i++) {
            int fi = i * 256 + t;
            int row = fi >> 4, q = fi & 15;
            int grow = row0 + row; if (grow >= Ee) grow = Ee - 1;
            const float* rp;
            if (kc < 2)      rp = e + (size_t)grow * 128;
            else if (kc < 4) rp = v + (size_t)s_src[row] * 128;
            else             rp = v + (size_t)s_dst[row] * 128;
            float4 x = *(const float4*)(rp + (kc & 1) * 64 + q * 4);
            uint2 hb, lb;
            split2(x.x, x.y, hb.x, lb.x);
            split2(x.z, x.w, hb.y, lb.y);
            int byte = row * 128 + q * 8;
            int sw = byte ^ ((byte >> 3) & 0x70);
            *(uint2*)(hi + sw) = hb;
            *(uint2*)(lo + sw) = lb;
        }
    };
    auto fill_W = [&](const unsigned short* chunk, int b) {
        const uint4* s = (const uint4*)chunk;
        uint4* d = (uint4*)(W_g + b * 32768);
#pragma unroll
        for (int i = 0; i < 8; i++) d[i * 256 + t] = s[i * 256 + t];
    };
    auto mma_chunk = [&](uint32 aoff, int b, bool first) {
        if (wid == 0 && elect_one_pred()) {
            FENCE_PROXY_ASYNC();
            unsigned long long ah = MAKE_SMEM_DESC(aoff);
            unsigned long long al = MAKE_SMEM_DESC(aoff + 16384);
            unsigned long long wh = MAKE_SMEM_DESC(W_B + b * 32768);
            unsigned long long wl = MAKE_SMEM_DESC(W_B + b * 32768 + 16384);
            uint32 en = first ? 0u : 1u;
#pragma unroll
            for (int s = 0; s < 4; s++) {
                mma_ss_bf16(tmb, ah + s * 2, wh + s * 2, en); en = 1u;
                mma_ss_bf16(tmb, ah + s * 2, wl + s * 2, 1u);
                mma_ss_bf16(tmb, al + s * 2, wh + s * 2, 1u);
            }
            TCGEN05_COMMIT(b ? mb1 : mb0);
        }
    };
    // 8-warp epilogue: warp w reads rows (w&3)*32 (its SMSP subpartition),
    // column blocks (w>>2)*2 + {0,1}. Covers full 128x128 D.
    auto epi_hidden = [&](const float* __restrict__ bias) {
        TCGEN05_FENCE_AFTER();
        int r = (wid & 3) * 32 + lid;
        int cb0 = (wid >> 2) * 2;
#pragma unroll 1
        for (int k = 0; k < 2; k++) {
            int cb = cb0 + k;
            uint32 d[32];
            TCGEN05_LD_X32(d, tmb + cb * 32);
            TCGEN05_WAIT_LD();
            char* hi = A_g + (cb >> 1) * 32768;
            char* lo = hi + 16384;
#pragma unroll
            for (int j = 0; j < 32; j += 2) {
                float x0 = selu_f(__uint_as_float(d[j])     + __ldg(&bias[cb * 32 + j]));
                float x1 = selu_f(__uint_as_float(d[j + 1]) + __ldg(&bias[cb * 32 + j + 1]));
                unsigned hb, lb;
                split2(x0, x1, hb, lb);
                int c = (cb & 1) * 32 + j;
                int byte = r * 128 + c * 2;
                int sw = byte ^ ((byte >> 3) & 0x70);
                *(unsigned*)(hi + sw) = hb;
                *(unsigned*)(lo + sw) = lb;
            }
        }
        TCGEN05_FENCE_BEFORE();
        __syncthreads();
    };

    // layer 0: K = 384, 6 chunks
    fill_A(0); fill_W(wt + 0 * 16384, 0); __syncthreads(); mma_chunk(A_B, 0, true);
    fill_A(1); fill_W(wt + 1 * 16384, 1); __syncthreads(); mma_chunk(A_B + 32768, 1, false);
    MBARRIER_WAIT_PARITY(mb0, 0);
    fill_A(2); fill_W(wt + 2 * 16384, 0); __syncthreads(); mma_chunk(A_B, 0, false);
    MBARRIER_WAIT_PARITY(mb1, 0);
    fill_A(3); fill_W(wt + 3 * 16384, 1); __syncthreads(); mma_chunk(A_B + 32768, 1, false);
    MBARRIER_WAIT_PARITY(mb0, 1);
    fill_A(4); fill_W(wt + 4 * 16384, 0); __syncthreads(); mma_chunk(A_B, 0, false);
    MBARRIER_WAIT_PARITY(mb1, 1);
    fill_A(5); fill_W(wt + 5 * 16384, 1); __syncthreads(); mma_chunk(A_B + 32768, 1, false);
    MBARRIER_WAIT_PARITY(mb0, 0); MBARRIER_WAIT_PARITY(mb1, 0);
    epi_hidden(b0);

    // layer 1: K = 128, A resident in A region
    fill_W(wt + 6 * 16384, 0); __syncthreads(); mma_chunk(A_B, 0, true);
    fill_W(wt + 7 * 16384, 1); __syncthreads(); mma_chunk(A_B + 32768, 1, false);
    MBARRIER_WAIT_PARITY(mb0, 1); MBARRIER_WAIT_PARITY(mb1, 1);
    epi_hidden(b1);

    // layer 2
    fill_W(wt + 8 * 16384, 0); __syncthreads(); mma_chunk(A_B, 0, true);
    fill_W(wt + 9 * 16384, 1); __syncthreads(); mma_chunk(A_B + 32768, 1, false);
    MBARRIER_WAIT_PARITY(mb0, 0); MBARRIER_WAIT_PARITY(mb1, 0);

    // final epilogue: residual + store e + atomic agg (8-warp column split)
    TCGEN05_FENCE_AFTER();
    {
        int r = (wid & 3) * 32 + lid;
        int cb0 = (wid >> 2) * 2;
        int grow = row0 + r;
        bool valid = grow < Ee;
        int dn = valid ? s_dst[r] : 0;
#pragma unroll 1
        for (int k = 0; k < 2; k++) {
            int cb = cb0 + k;
            uint32 d[32];
            TCGEN05_LD_X32(d, tmb + cb * 32);
            TCGEN05_WAIT_LD();
            if (valid) {
                float* erow = e + (size_t)grow * 128 + cb * 32;
                float* arow = agg + (size_t)dn * 128 + cb * 32;
#pragma unroll
                for (int q = 0; q < 8; q++) {
                    float4 ev = *(float4*)(erow + q * 4);
                    float4 rr;
                    rr.x = ev.x + __uint_as_float(d[q * 4 + 0]) + __ldg(&b2[cb * 32 + q * 4 + 0]);
                    rr.y = ev.y + __uint_as_float(d[q * 4 + 1]) + __ldg(&b2[cb * 32 + q * 4 + 1]);
                    rr.z = ev.z + __uint_as_float(d[q * 4 + 2]) + __ldg(&b2[cb * 32 + q * 4 + 2]);
                    rr.w = ev.w + __uint_as_float(d[q * 4 + 3]) + __ldg(&b2[cb * 32 + q * 4 + 3]);
                    *(float4*)(erow + q * 4) = rr;
                    atomicAdd(arow + q * 4 + 0, rr.x);
                    atomicAdd(arow + q * 4 + 1, rr.y);
                    atomicAdd(arow + q * 4 + 2, rr.z);
                    atomicAdd(arow + q * 4 + 3, rr.w);
                }
            }
        }
    }
    TCGEN05_FENCE_BEFORE();
    __syncthreads();
    if (wid == 0) TCGEN05_DEALLOC(tmb, 128);
#else
    // fallback: two parallel 64-row FFMA2 half-blocks (uniform barrier structure)
    const int t = threadIdx.x;
    const int half = t >> 7;
    const int tl = t & 127;
    const int row0 = blockIdx.x * 128 + half * 64;
    edge_simt_tile(smraw + half * SIMT_FLOATS, e, v, src, dst,
                   w0f, b0, w1f, b1, w2f, b2, agg, row0, tl);
#endif
}

// ---------------- node: v += MLP([v, agg/deg]) ----------------
__global__ void __launch_bounds__(128) node_kernel(
    float* __restrict__ v, const float* __restrict__ agg, const float* __restrict__ deg,
    const float* __restrict__ w0, const float* __restrict__ b0,
    const float* __restrict__ w1, const float* __restrict__ b1,
    const float* __restrict__ w2, const float* __restrict__ b2) {
    extern __shared__ float sm[];
    float* As = sm + AS_OFF;
    float* Bs = sm + BS_OFF;
    float* Hs = sm + HS_OFF;
    float* s_inv = sm + IX_OFF;

    const int t = threadIdx.x;
    const int row0 = blockIdx.x * 64;
    if (t < 64) {
        int r = row0 + t;
        if (r >= Nn) r = Nn - 1;
        s_inv[t] = 1.f / fmaxf(deg[r], 1.f);
    }
    const int c0 = (t & 15) * 8;
    const int gb = (t & 15) * 12;
    const int r0 = (t >> 4) * 8;
    __syncthreads();

    ull acc[8][4];
    acc_init(acc, b0, c0);

    auto fill_As = [&](float* dstA, int kt) {
#pragma unroll
        for (int i = 0; i < 2; i++) {
            int f = t * 2 + i;
            int ar = f >> 2;
            int kl = (f & 3) << 2;
            int k = kt + kl;
            int grow = row0 + ar;
            if (grow >= Nn) grow = Nn - 1;
            float4 val;
            if (k < 128) {
                val = *(const float4*)(v + (size_t)grow * 128 + k);
            } else {
                val = *(const float4*)(agg + (size_t)grow * 128 + (k - 128));
                float sc = s_inv[ar];
                val.x *= sc; val.y *= sc; val.z *= sc; val.w *= sc;
            }
            *(float4*)&dstA[ar * 20 + kl] = val;
        }
    };
    fill_As(As, 0);
    fill_Bs(Bs, w0, 0, t);
    __syncthreads();
#pragma unroll 1
    for (int kt = 0; kt < 16; kt++) {
        if (kt < 15) {
            int nb = (kt + 1) & 1;
            fill_As(As + nb * AS_BUF, (kt + 1) * 16);
            fill_Bs(Bs + nb * BS_BUF, w0, (kt + 1) * 16, t);
        }
        mma16<20>(As + (kt & 1) * AS_BUF, 0, Bs + (kt & 1) * BS_BUF, r0, gb, acc);
        __syncthreads();
    }
    selu_store(Hs, acc, r0, c0);
    acc_init(acc, b1, c0);
    hidden_layer(w1, Hs, Bs, t, r0, gb, acc);
    selu_store(Hs, acc, r0, c0);
    acc_init(acc, b2, c0);
    hidden_layer(w2, Hs, Bs, t, r0, gb, acc);

#pragma unroll
    for (int i = 0; i < 8; i++) {
        int row = row0 + r0 + i;
        if (row < Nn) {
            float* vrow = v + (size_t)row * 128 + c0;
            float2 p0 = unpk(acc[i][0]), p1 = unpk(acc[i][1]);
            float2 p2 = unpk(acc[i][2]), p3 = unpk(acc[i][3]);
            float4 v0 = *(float4*)vrow;
            float4 v1 = *(float4*)(vrow + 4);
            *(float4*)vrow       = make_float4(v0.x + p0.x, v0.y + p0.y, v0.z + p1.x, v0.w + p1.y);
            *(float4*)(vrow + 4) = make_float4(v1.x + p2.x, v1.y + p2.y, v1.z + p3.x, v1.w + p3.y);
        }
    }
}

// ---------------- pool: atomic-add MLP([v, rel]) into vc sums ----------------
__global__ void __launch_bounds__(128) pool_kernel(
    const float* __restrict__ v, const float* __restrict__ pos,
    const int* __restrict__ cluster, const float* __restrict__ cpos,
    const float* __restrict__ w0, const float* __restrict__ b0,
    const float* __restrict__ w1, const float* __restrict__ b1,
    const float* __restrict__ w2, const float* __restrict__ b2,
    float* __restrict__ vc) {
    extern __shared__ float sm[];
    float* As = sm + AS_OFF;
    float* Bs = sm + BS_OFF;
    float* Hs = sm + HS_OFF;
    float* s_rel = sm + IX_OFF;
    int* s_cl = (int*)(sm + IX_OFF + 64);

    const int t = threadIdx.x;
    const int row0 = blockIdx.x * 64;
    if (t < 64) {
        int r = row0 + t;
        if (r >= Nn) r = Nn - 1;
        int cl = cluster[r];
        float dx = pos[2 * r] - cpos[2 * cl];
        float dy = pos[2 * r + 1] - cpos[2 * cl + 1];
        s_rel[t] = sqrtf(dx * dx + dy * dy + 1e-12f);
        s_cl[t] = cl;
    }
    const int c0 = (t & 15) * 8;
    const int gb = (t & 15) * 12;
    const int r0 = (t >> 4) * 8;
    __syncthreads();

    ull acc[8][4];
    acc_init(acc, b0, c0);

    auto fill_As = [&](float* dstA, int kt) {
#pragma unroll
        for (int i = 0; i < 2; i++) {
            int f = t * 2 + i;
            int ar = f >> 2;
            int kl = (f & 3) << 2;
            int grow = row0 + ar;
            if (grow >= Nn) grow = Nn - 1;
            float4 val = *(const float4*)(v + (size_t)grow * 128 + kt + kl);
            *(float4*)&dstA[ar * 20 + kl] = val;
        }
    };
    fill_As(As, 0);
    fill_Bs(Bs, w0, 0, t);
    __syncthreads();
#pragma unroll 1
    for (int kt = 0; kt < 8; kt++) {
        if (kt < 7) {
            int nb = (kt + 1) & 1;
            fill_As(As + nb * AS_BUF, (kt + 1) * 16);
            fill_Bs(Bs + nb * BS_BUF, w0, (kt + 1) * 16, t);
        }
        mma16<20>(As + (kt & 1) * AS_BUF, 0, Bs + (kt & 1) * BS_BUF, r0, gb, acc);
        __syncthreads();
    }
    {
        ull wx[4];
#pragma unroll
        for (int j = 0; j < 4; j++) wx[j] = *(const ull*)&w0[128 * 128 + c0 + 2 * j];
#pragma unroll
        for (int i = 0; i < 8; i++) {
            ull rl2 = dupf(s_rel[r0 + i]);
#pragma unroll
            for (int j = 0; j < 4; j++) ffma2(acc[i][j], rl2, wx[j]);
        }
    }
    selu_store(Hs, acc, r0, c0);
    acc_init(acc, b1, c0);
    hidden_layer(w1, Hs, Bs, t, r0, gb, acc);
    selu_store(Hs, acc, r0, c0);
    acc_init(acc, b2, c0);
    hidden_layer(w2, Hs, Bs, t, r0, gb, acc);

#pragma unroll
    for (int i = 0; i < 8; i++) {
        int row = row0 + r0 + i;
        if (row < Nn) {
            int cl = s_cl[r0 + i];
            float* crow = vc + (size_t)cl * 128 + c0;
            float2 p0 = unpk(acc[i][0]), p1 = unpk(acc[i][1]);
            float2 p2 = unpk(acc[i][2]), p3 = unpk(acc[i][3]);
            float rr[8] = {p0.x, p0.y, p1.x, p1.y, p2.x, p2.y, p3.x, p3.y};
#pragma unroll
            for (int j = 0; j < 8; j++) atomicAdd(&crow[j], rr[j]);
        }
    }
}

// ---------------- coarse edge encoder ----------------
__global__ void __launch_bounds__(128) eenc_kernel(
    const int* __restrict__ cei, const float* __restrict__ cpos,
    const float* __restrict__ w0, const float* __restrict__ b0,
    const float* __restrict__ w1, const float* __restrict__ b1,
    const float* __restrict__ w2, const float* __restrict__ b2,
    float* __restrict__ ec) {
    extern __shared__ float sm[];
    float* Bs = sm + BS_OFF;
    float* Hs = sm + HS_OFF;
    float* s_crel = sm + IX_OFF;

    const int t = threadIdx.x;
    const int row0 = blockIdx.x * 64;
    if (t < 64) {
        int r = row0 + t;
        if (r >= ECc) r = ECc - 1;
        int a = cei[r];
        int b = cei[ECc + r];
        float dx = cpos[2 * a] - cpos[2 * b];
        float dy = cpos[2 * a + 1] - cpos[2 * b + 1];
        s_crel[t] = sqrtf(dx * dx + dy * dy + 1e-12f);
    }
    const int c0 = (t & 15) * 8;
    const int gb = (t & 15) * 12;
    const int r0 = (t >> 4) * 8;
    __syncthreads();

#pragma unroll
    for (int i = 0; i < 8; i++) {
        float cr = s_crel[r0 + i];
#pragma unroll
        for (int j = 0; j < 8; j++)
            Hs[(r0 + i) * 132 + c0 + j] =
                selu_f(fmaf(cr, __ldg(&w0[c0 + j]), __ldg(&b0[c0 + j])));
    }

    ull acc[8][4];
    acc_init(acc, b1, c0);
    hidden_layer(w1, Hs, Bs, t, r0, gb, acc);
    selu_store(Hs, acc, r0, c0);
    acc_init(acc, b2, c0);
    hidden_layer(w2, Hs, Bs, t, r0, gb, acc);

#pragma unroll
    for (int i = 0; i < 8; i++) {
        int row = row0 + r0 + i;
        if (row < ECc) {
            float* erow = ec + (size_t)row * 128 + c0;
            float2 p0 = unpk(acc[i][0]), p1 = unpk(acc[i][1]);
            float2 p2 = unpk(acc[i][2]), p3 = unpk(acc[i][3]);
            *(float4*)erow       = make_float4(p0.x, p0.y, p1.x, p1.y);
            *(float4*)(erow + 4) = make_float4(p2.x, p2.y, p3.x, p3.y);
        }
    }
}

// ---------------- small helpers ----------------
__global__ void deg_scatter(const int* __restrict__ dst, float* __restrict__ deg) {
    int i = blockIdx.x * blockDim.x + threadIdx.x;
    if (i < Ee) atomicAdd(&deg[dst[i]], 1.f);
}
__global__ void cpos_scatter(const float* __restrict__ pos, const int* __restrict__ cluster,
                             float* __restrict__ cposs, float* __restrict__ ccnt) {
    int i = blockIdx.x * blockDim.x + threadIdx.x;
    if (i < Nn) {
        int c = cluster[i];
        atomicAdd(&cposs[2 * c], pos[2 * i]);
        atomicAdd(&cposs[2 * c + 1], pos[2 * i + 1]);
        atomicAdd(&ccnt[c], 1.f);
    }
}
__global__ void cpos_fin(const float* __restrict__ cposs, const float* __restrict__ ccnt,
                         float* __restrict__ cpos, float* __restrict__ cinv) {
    int c = blockIdx.x * blockDim.x + threadIdx.x;
    if (c < NCc) {
        float inv = 1.f / fmaxf(ccnt[c], 1.f);
        cpos[2 * c] = cposs[2 * c] * inv;
        cpos[2 * c + 1] = cposs[2 * c + 1] * inv;
        cinv[c] = inv;
    }
}
__global__ void vc_scale(float* __restrict__ vc, const float* __restrict__ cinv) {
    int i = blockIdx.x * blockDim.x + threadIdx.x;
    if (i < NCc * 128) vc[i] *= cinv[i >> 7];
}

// ---------------- launch ----------------
extern "C" void kernel_launch(void* const* d_in, const int* in_sizes, int n_in,
                              void* d_out, int out_size) {
    const float* v0      = (const float*)d_in[0];
    const float* e0      = (const float*)d_in[1];
    const float* pos     = (const float*)d_in[2];
    const int*   ei      = (const int*)d_in[3];
    const int*   cluster = (const int*)d_in[4];
    const int*   cei     = (const int*)d_in[5];
    const float* ew0 = (const float*)d_in[6],  *eb0 = (const float*)d_in[7];
    const float* ew1 = (const float*)d_in[8],  *eb1 = (const float*)d_in[9];
    const float* ew2 = (const float*)d_in[10], *eb2 = (const float*)d_in[11];
    const float* nw0 = (const float*)d_in[12], *nb0 = (const float*)d_in[13];
    const float* nw1 = (const float*)d_in[14], *nb1 = (const float*)d_in[15];
    const float* nw2 = (const float*)d_in[16], *nb2 = (const float*)d_in[17];
    const float* pw0 = (const float*)d_in[18], *pb0 = (const float*)d_in[19];
    const float* pw1 = (const float*)d_in[20], *pb1 = (const float*)d_in[21];
    const float* pw2 = (const float*)d_in[22], *pb2 = (const float*)d_in[23];
    const float* qw0 = (const float*)d_in[24], *qb0 = (const float*)d_in[25];
    const float* qw1 = (const float*)d_in[26], *qb1 = (const float*)d_in[27];
    const float* qw2 = (const float*)d_in[28], *qb2 = (const float*)d_in[29];

    float* out    = (float*)d_out;
    float* out_vc = out;
    float* out_ec = out + OFF_EC;
    float* vbuf   = out + OFF_V;
    float* ebuf   = out + OFF_E;

    float *agg, *deg, *cposs, *ccnt, *cpos, *cinv;
    unsigned short* wt;
    cudaGetSymbolAddress((void**)&agg,   g_agg);
    cudaGetSymbolAddress((void**)&deg,   g_deg);
    cudaGetSymbolAddress((void**)&cposs, g_cposs);
    cudaGetSymbolAddress((void**)&ccnt,  g_ccnt);
    cudaGetSymbolAddress((void**)&cpos,  g_cpos);
    cudaGetSymbolAddress((void**)&cinv,  g_cinv);
    cudaGetSymbolAddress((void**)&wt,    g_wt);

    cudaFuncSetAttribute(edge_tc_kernel, cudaFuncAttributeMaxDynamicSharedMemorySize, EDGE_SMEM);
    cudaFuncSetAttribute(node_kernel, cudaFuncAttributeMaxDynamicSharedMemorySize, SIMT_SMEM);
    cudaFuncSetAttribute(pool_kernel, cudaFuncAttributeMaxDynamicSharedMemorySize, SIMT_SMEM);
    cudaFuncSetAttribute(eenc_kernel, cudaFuncAttributeMaxDynamicSharedMemorySize, SIMT_SMEM);

    cudaMemcpyAsync(vbuf, v0, sizeof(float) * (size_t)Nn * 128, cudaMemcpyDeviceToDevice, 0);
    cudaMemcpyAsync(ebuf, e0, sizeof(float) * (size_t)Ee * 128, cudaMemcpyDeviceToDevice, 0);

    const int* src  = ei;
    const int* dstp = ei + Ee;

    cudaMemsetAsync(deg, 0, sizeof(float) * Nn, 0);
    deg_scatter<<<(Ee + 255) / 256, 256>>>(dstp, deg);

    // prep all edge-block weights (transpose + bf16 split + swizzle)
    for (int d = 0; d < 4; d++) {
        unsigned short* wtb = wt + (size_t)d * 163840;
        prep_w_kernel<<<(384 * 128 + 255) / 256, 256>>>(ew0 + (size_t)d * 384 * 128, 384, wtb);
        prep_w_kernel<<<(128 * 128 + 255) / 256, 256>>>(ew1 + (size_t)d * 128 * 128, 128, wtb + 6 * 16384);
        prep_w_kernel<<<(128 * 128 + 255) / 256, 256>>>(ew2 + (size_t)d * 128 * 128, 128, wtb + 8 * 16384);
    }

    for (int d = 0; d < 4; d++) {
        cudaMemsetAsync(agg, 0, sizeof(float) * (size_t)Nn * 128, 0);
        edge_tc_kernel<<<(Ee + 127) / 128, 256, EDGE_SMEM>>>(
            ebuf, vbuf, src, dstp, wt + (size_t)d * 163840,
            ew0 + (size_t)d * 384 * 128, ew1 + (size_t)d * 128 * 128, ew2 + (size_t)d * 128 * 128,
            eb0 + d * 128, eb1 + d * 128, eb2 + d * 128, agg);
        node_kernel<<<(Nn + 63) / 64, 128, SIMT_SMEM>>>(
            vbuf, agg, deg,
            nw0 + (size_t)d * 256 * 128, nb0 + d * 128,
            nw1 + (size_t)d * 128 * 128, nb1 + d * 128,
            nw2 + (size_t)d * 128 * 128, nb2 + d * 128);
    }

    cudaMemsetAsync(cposs, 0, sizeof(float) * NCc * 2, 0);
    cudaMemsetAsync(ccnt, 0, sizeof(float) * NCc, 0);
    cpos_scatter<<<(Nn + 255) / 256, 256>>>(pos, cluster, cposs, ccnt);
    cpos_fin<<<(NCc + 255) / 256, 256>>>(cposs, ccnt, cpos, cinv);

    cudaMemsetAsync(out_vc, 0, sizeof(float) * NCc * 128, 0);
    pool_kernel<<<(Nn + 63) / 64, 128, SIMT_SMEM>>>(vbuf, pos, cluster, cpos,
                                                    pw0, pb0, pw1, pb1, pw2, pb2, out_vc);
    vc_scale<<<(NCc * 128 + 255) / 256, 256>>>(out_vc, cinv);

    eenc_kernel<<<(ECc + 63) / 64, 128, SIMT_SMEM>>>(cei, cpos, qw0, qb0, qw1, qb1, qw2, qb2, out_ec);
}

// round 11
// speedup vs baseline: 2.7420x; 1.3105x over previous
#include <cuda_runtime.h>
#include <cuda_bf16.h>
#include <math.h>

#define Nn  50000
#define Ee  300000
#define NCc 12500
#define ECc 75000

#define OFF_EC 1600000
#define OFF_V  11200000
#define OFF_E  17600000

typedef unsigned long long ull;
typedef unsigned int uint32;

#if defined(__CUDA_ARCH__) && defined(__CUDA_ARCH_FEAT_SM103_ALL)
#define TC_PATH 1
#else
#define TC_PATH 0
#endif

// ================= device scratch =================
__device__ float g_agg[Nn * 128];
__device__ float g_deg[Nn];
__device__ float g_cposs[NCc * 2];
__device__ float g_ccnt[NCc];
__device__ float g_cpos[NCc * 2];
__device__ float g_cinv[NCc];
// prepped edge weights: 4 blocks x 10 chunks x (hi 8192 + lo 8192) bf16
__device__ unsigned short g_wt[4 * 10 * 16384];
// prepped node weights: 4 blocks x 8 chunks
__device__ unsigned short g_wtn[4 * 8 * 16384];

__device__ __forceinline__ float selu_f(float x) {
    return x > 0.f ? 1.0507009873554805f * x : 1.7580993408473766f * expm1f(x);
}

// ================= SIMT FFMA2 machinery =================
#define AS_OFF 0
#define AS_BUF 1280
#define BS_OFF 2560
#define BS_BUF 3072
#define HS_OFF 8704
#define IX_OFF 17152
#define SIMT_FLOATS 17312
#define SIMT_SMEM (SIMT_FLOATS * 4)

__device__ __forceinline__ void ffma2(ull& d, ull a, ull b) {
    asm("fma.rn.f32x2 %0, %1, %2, %0;" : "+l"(d) : "l"(a), "l"(b));
}
__device__ __forceinline__ float2 unpk(ull p) {
    float2 f;
    asm("mov.b64 {%0, %1}, %2;" : "=f"(f.x), "=f"(f.y) : "l"(p));
    return f;
}
__device__ __forceinline__ ull dupf(float x) {
    ull r;
    asm("mov.b64 %0, {%1, %1};" : "=l"(r) : "f"(x));
    return r;
}
__device__ __forceinline__ void acc_init(ull (&acc)[8][4], const float* __restrict__ b, int c0) {
    ull bb[4];
#pragma unroll
    for (int j = 0; j < 4; j++) bb[j] = *(const ull*)&b[c0 + 2 * j];
#pragma unroll
    for (int i = 0; i < 8; i++)
#pragma unroll
        for (int j = 0; j < 4; j++) acc[i][j] = bb[j];
}
__device__ __forceinline__ void fill_Bs(float* Bs, const float* __restrict__ W, int kt, int t) {
    const float4* wsrc = (const float4*)(W + (size_t)kt * 128);
#pragma unroll
    for (int i = 0; i < 4; i++) {
        int fi = i * 128 + t;
        float4 w = wsrc[fi];
        int k = fi >> 5;
        int q = fi & 31;
        *(float4*)&Bs[k * 192 + (q >> 1) * 12 + (q & 1) * 4] = w;
    }
}
template <int STRIDE>
__device__ __forceinline__ void mma16(const float* A, int koff, const float* Bs,
                                      int r0, int gb, ull (&acc)[8][4]) {
#pragma unroll
    for (int k4 = 0; k4 < 4; k4++) {
        float4 a4[8];
#pragma unroll
        for (int i = 0; i < 8; i++)
            a4[i] = *(const float4*)&A[(r0 + i) * STRIDE + koff + 4 * k4];
#pragma unroll
        for (int kk = 0; kk < 4; kk++) {
            const float* bp = &Bs[(4 * k4 + kk) * 192 + gb];
            ulonglong2 bA = *(const ulonglong2*)bp;
            ulonglong2 bB = *(const ulonglong2*)(bp + 4);
#pragma unroll
            for (int i = 0; i < 8; i++) {
                float av = (kk == 0) ? a4[i].x : (kk == 1) ? a4[i].y
                         : (kk == 2) ? a4[i].z : a4[i].w;
                ull ad = dupf(av);
                ffma2(acc[i][0], ad, bA.x);
                ffma2(acc[i][1], ad, bA.y);
                ffma2(acc[i][2], ad, bB.x);
                ffma2(acc[i][3], ad, bB.y);
            }
        }
    }
}
__device__ __forceinline__ void selu_store(float* Hs, ull (&acc)[8][4], int r0, int c0) {
#pragma unroll
    for (int i = 0; i < 8; i++) {
        float2 p0 = unpk(acc[i][0]), p1 = unpk(acc[i][1]);
        float2 p2 = unpk(acc[i][2]), p3 = unpk(acc[i][3]);
        *(float4*)&Hs[(r0 + i) * 132 + c0] =
            make_float4(selu_f(p0.x), selu_f(p0.y), selu_f(p1.x), selu_f(p1.y));
        *(float4*)&Hs[(r0 + i) * 132 + c0 + 4] =
            make_float4(selu_f(p2.x), selu_f(p2.y), selu_f(p3.x), selu_f(p3.y));
    }
}
// act=false threads participate in barriers only (reads are in-range via tl indices)
__device__ __forceinline__ void hidden_layer(const float* __restrict__ W,
                                             const float* Hs, float* BsBase,
                                             int t, int r0, int gb, ull (&acc)[8][4],
                                             bool act) {
    if (act) fill_Bs(BsBase, W, 0, t);
    __syncthreads();
#pragma unroll 1
    for (int kt = 0; kt < 8; kt++) {
        if (kt < 7 && act) fill_Bs(BsBase + ((kt + 1) & 1) * BS_BUF, W, (kt + 1) * 16, t);
        mma16<132>(Hs, kt * 16, BsBase + (kt & 1) * BS_BUF, r0, gb, acc);
        __syncthreads();
    }
}

// FFMA2 edge tile (64 rows) — fallback body. tfull may be 0..255; only tfull<128 writes.
__device__ void edge_simt_tile(
    float* sm, float* __restrict__ e, const float* __restrict__ v,
    const int* __restrict__ src, const int* __restrict__ dst,
    const float* __restrict__ w0, const float* __restrict__ b0,
    const float* __restrict__ w1, const float* __restrict__ b1,
    const float* __restrict__ w2, const float* __restrict__ b2,
    float* __restrict__ agg, int row0, int tfull) {
    float* As = sm + AS_OFF;
    float* Bs = sm + BS_OFF;
    float* Hs = sm + HS_OFF;
    int* s_src = (int*)(sm + IX_OFF);
    int* s_dst = s_src + 64;
    const bool act = tfull < 128;
    const int t = tfull & 127;

    __syncthreads();
    if (act && t < 64) {
        int r = row0 + t;
        if (r >= Ee) r = Ee - 1;
        s_src[t] = src[r];
        s_dst[t] = dst[r];
    }
    const int c0 = (t & 15) * 8;
    const int gb = (t & 15) * 12;
    const int r0 = (t >> 4) * 8;
    __syncthreads();

    ull acc[8][4];
    acc_init(acc, b0, c0);

    auto fill_As = [&](float* dstA, int kt) {
#pragma unroll
        for (int i = 0; i < 2; i++) {
            int f = t * 2 + i;
            int ar = f >> 2;
            int kl = (f & 3) << 2;
            int k = kt + kl;
            int grow = row0 + ar;
            if (grow >= Ee) grow = Ee - 1;
            float4 val;
            if (k < 128)      val = *(const float4*)(e + (size_t)grow * 128 + k);
            else if (k < 256) val = *(const float4*)(v + (size_t)s_src[ar] * 128 + (k - 128));
            else              val = *(const float4*)(v + (size_t)s_dst[ar] * 128 + (k - 256));
            *(float4*)&dstA[ar * 20 + kl] = val;
        }
    };
    if (act) { fill_As(As, 0); fill_Bs(Bs, w0, 0, t); }
    __syncthreads();
#pragma unroll 1
    for (int kt = 0; kt < 24; kt++) {
        if (kt < 23 && act) {
            int nb = (kt + 1) & 1;
            fill_As(As + nb * AS_BUF, (kt + 1) * 16);
            fill_Bs(Bs + nb * BS_BUF, w0, (kt + 1) * 16, t);
        }
        mma16<20>(As + (kt & 1) * AS_BUF, 0, Bs + (kt & 1) * BS_BUF, r0, gb, acc);
        __syncthreads();
    }
    if (act) selu_store(Hs, acc, r0, c0);
    acc_init(acc, b1, c0);
    hidden_layer(w1, Hs, Bs, t, r0, gb, acc, act);
    if (act) selu_store(Hs, acc, r0, c0);
    acc_init(acc, b2, c0);
    hidden_layer(w2, Hs, Bs, t, r0, gb, acc, act);

    if (act) {
#pragma unroll
        for (int i = 0; i < 8; i++) {
            int row = row0 + r0 + i;
            if (row < Ee) {
                int dn = s_dst[r0 + i];
                float* erow = e + (size_t)row * 128 + c0;
                float* arow = agg + (size_t)dn * 128 + c0;
                float2 p0 = unpk(acc[i][0]), p1 = unpk(acc[i][1]);
                float2 p2 = unpk(acc[i][2]), p3 = unpk(acc[i][3]);
                float4 e0 = *(float4*)erow;
                float4 e1 = *(float4*)(erow + 4);
                float rr[8] = {e0.x + p0.x, e0.y + p0.y, e0.z + p1.x, e0.w + p1.y,
                               e1.x + p2.x, e1.y + p2.y, e1.z + p3.x, e1.w + p3.y};
                *(float4*)erow       = make_float4(rr[0], rr[1], rr[2], rr[3]);
                *(float4*)(erow + 4) = make_float4(rr[4], rr[5], rr[6], rr[7]);
#pragma unroll
                for (int j = 0; j < 8; j++) atomicAdd(&arow[j], rr[j]);
            }
        }
    }
}

// FFMA2 node tile (64 rows) — fallback body
__device__ void node_simt_tile(
    float* sm, float* __restrict__ v, const float* __restrict__ agg,
    const float* __restrict__ deg,
    const float* __restrict__ w0, const float* __restrict__ b0,
    const float* __restrict__ w1, const float* __restrict__ b1,
    const float* __restrict__ w2, const float* __restrict__ b2,
    int row0, int tfull) {
    float* As = sm + AS_OFF;
    float* Bs = sm + BS_OFF;
    float* Hs = sm + HS_OFF;
    float* s_inv = sm + IX_OFF;
    const bool act = tfull < 128;
    const int t = tfull & 127;

    __syncthreads();
    if (act && t < 64) {
        int r = row0 + t;
        if (r >= Nn) r = Nn - 1;
        s_inv[t] = 1.f / fmaxf(deg[r], 1.f);
    }
    const int c0 = (t & 15) * 8;
    const int gb = (t & 15) * 12;
    const int r0 = (t >> 4) * 8;
    __syncthreads();

    ull acc[8][4];
    acc_init(acc, b0, c0);

    auto fill_As = [&](float* dstA, int kt) {
#pragma unroll
        for (int i = 0; i < 2; i++) {
            int f = t * 2 + i;
            int ar = f >> 2;
            int kl = (f & 3) << 2;
            int k = kt + kl;
            int grow = row0 + ar;
            if (grow >= Nn) grow = Nn - 1;
            float4 val;
            if (k < 128) {
                val = *(const float4*)(v + (size_t)grow * 128 + k);
            } else {
                val = *(const float4*)(agg + (size_t)grow * 128 + (k - 128));
                float sc = s_inv[ar];
                val.x *= sc; val.y *= sc; val.z *= sc; val.w *= sc;
            }
            *(float4*)&dstA[ar * 20 + kl] = val;
        }
    };
    if (act) { fill_As(As, 0); fill_Bs(Bs, w0, 0, t); }
    __syncthreads();
#pragma unroll 1
    for (int kt = 0; kt < 16; kt++) {
        if (kt < 15 && act) {
            int nb = (kt + 1) & 1;
            fill_As(As + nb * AS_BUF, (kt + 1) * 16);
            fill_Bs(Bs + nb * BS_BUF, w0, (kt + 1) * 16, t);
        }
        mma16<20>(As + (kt & 1) * AS_BUF, 0, Bs + (kt & 1) * BS_BUF, r0, gb, acc);
        __syncthreads();
    }
    if (act) selu_store(Hs, acc, r0, c0);
    acc_init(acc, b1, c0);
    hidden_layer(w1, Hs, Bs, t, r0, gb, acc, act);
    if (act) selu_store(Hs, acc, r0, c0);
    acc_init(acc, b2, c0);
    hidden_layer(w2, Hs, Bs, t, r0, gb, acc, act);

    if (act) {
#pragma unroll
        for (int i = 0; i < 8; i++) {
            int row = row0 + r0 + i;
            if (row < Nn) {
                float* vrow = v + (size_t)row * 128 + c0;
                float2 p0 = unpk(acc[i][0]), p1 = unpk(acc[i][1]);
                float2 p2 = unpk(acc[i][2]), p3 = unpk(acc[i][3]);
                float4 v0 = *(float4*)vrow;
                float4 v1 = *(float4*)(vrow + 4);
                *(float4*)vrow       = make_float4(v0.x + p0.x, v0.y + p0.y, v0.z + p1.x, v0.w + p1.y);
                *(float4*)(vrow + 4) = make_float4(v1.x + p2.x, v1.y + p2.y, v1.z + p3.x, v1.w + p3.y);
            }
        }
    }
}

// ================= tcgen05 helpers (sm_103a only) =================
#if TC_PATH
__device__ __forceinline__ uint32 elect_one_pred() {
    uint32 pred;
    asm volatile("{\n\t.reg .pred p;\n\telect.sync _|p, 0xFFFFFFFF;\n\tselp.b32 %0, 1, 0, p;\n\t}" : "=r"(pred));
    return pred;
}
__device__ __forceinline__ uint32 smem_u32(const void* p) {
    uint32 a;
    asm("{ .reg .u64 tmp; cvta.to.shared.u64 tmp, %1; cvt.u32.u64 %0, tmp; }" : "=r"(a) : "l"(p));
    return a;
}
#define MBARRIER_INIT(addr, cnt) \
    asm volatile("mbarrier.init.shared.b64 [%0], %1;" :: "r"((uint32)(addr)), "r"((uint32)(cnt)) : "memory")
#define MBARRIER_WAIT_PARITY(addr, par) do {                                            \
    uint32 _m = (uint32)(addr); uint32 _p = (uint32)(par); uint32 _d;                   \
    asm volatile("{\n\t.reg .pred p;\n\t"                                               \
        "mbarrier.try_wait.parity.acquire.cta.shared::cta.b64 p, [%1], %2;\n\t"         \
        "selp.b32 %0, 1, 0, p;\n\t}" : "=r"(_d) : "r"(_m), "r"(_p) : "memory");         \
    if (!_d) {                                                                          \
        asm volatile("{\n\t.reg .pred P1;\n\t"                                          \
            "WL_%=:\n\t"                                                                \
            "mbarrier.try_wait.parity.acquire.cta.shared::cta.b64 P1, [%0], %1, 0x989680;\n\t" \
            "@P1 bra.uni WD_%=;\n\tbra.uni WL_%=;\n\tWD_%=:\n\t}"                        \
            :: "r"(_m), "r"(_p) : "memory");                                            \
    } } while (0)
#define TCGEN05_ALLOC(slot, n) \
    asm volatile("tcgen05.alloc.cta_group::1.sync.aligned.shared::cta.b32 [%0], %1;" :: "r"((uint32)(slot)), "r"((uint32)(n)) : "memory")
#define TCGEN05_DEALLOC(tm, n) \
    asm volatile("tcgen05.dealloc.cta_group::1.sync.aligned.b32 %0, %1;" :: "r"(tm), "r"((uint32)(n)))
#define TCGEN05_RELINQ() \
    asm volatile("tcgen05.relinquish_alloc_permit.cta_group::1.sync.aligned;")
#define TCGEN05_COMMIT(mb) \
    asm volatile("tcgen05.commit.cta_group::1.mbarrier::arrive::one.shared::cluster.b64 [%0];" :: "r"((uint32)(mb)) : "memory")
#define TCGEN05_WAIT_LD() asm volatile("tcgen05.wait::ld.sync.aligned;" ::: "memory")
#define TCGEN05_FENCE_BEFORE() asm volatile("tcgen05.fence::before_thread_sync;" ::: "memory")
#define TCGEN05_FENCE_AFTER()  asm volatile("tcgen05.fence::after_thread_sync;" ::: "memory")
#define FENCE_PROXY_ASYNC() asm volatile("fence.proxy.async.shared::cta;" ::: "memory")
#define TCGEN05_LD_X32(r, tm) \
    asm volatile("tcgen05.ld.sync.aligned.32x32b.x32.b32 " \
        "{%0, %1, %2, %3, %4, %5, %6, %7, %8, %9, %10, %11, %12, %13, %14, %15, " \
        " %16, %17, %18, %19, %20, %21, %22, %23, %24, %25, %26, %27, %28, %29, %30, %31}, [%32];" \
        : "=r"((r)[0]),  "=r"((r)[1]),  "=r"((r)[2]),  "=r"((r)[3]),  "=r"((r)[4]),  "=r"((r)[5]),  "=r"((r)[6]),  "=r"((r)[7]), \
          "=r"((r)[8]),  "=r"((r)[9]),  "=r"((r)[10]), "=r"((r)[11]), "=r"((r)[12]), "=r"((r)[13]), "=r"((r)[14]), "=r"((r)[15]), \
          "=r"((r)[16]), "=r"((r)[17]), "=r"((r)[18]), "=r"((r)[19]), "=r"((r)[20]), "=r"((r)[21]), "=r"((r)[22]), "=r"((r)[23]), \
          "=r"((r)[24]), "=r"((r)[25]), "=r"((r)[26]), "=r"((r)[27]), "=r"((r)[28]), "=r"((r)[29]), "=r"((r)[30]), "=r"((r)[31]) \
        : "r"(tm))

static constexpr unsigned long long SMEM_DESC_BASE_SW128 =
    (2ull << 61) | (1ull << 46) | (64ull << 32) | (1ull << 16);
#define MAKE_SMEM_DESC(addr) (SMEM_DESC_BASE_SW128 | (((unsigned long long)((addr) >> 4)) & 0x3FFF))

// idesc: F32 acc, BF16 x BF16, M=128, N=128, K-major both
#define IDESC_BF 0x8200490u

__device__ __forceinline__ void mma_ss_bf16(uint32 d, unsigned long long a, unsigned long long b, uint32 en) {
    asm volatile(
        "{\n\t.reg .pred p;\n\tsetp.ne.u32 p, %4, 0;\n\t"
        "tcgen05.mma.cta_group::1.kind::f16 [%0], %1, %2, %3, {%5, %5, %5, %5}, p;\n\t}"
        :: "r"(d), "l"(a), "l"(b), "r"(IDESC_BF), "r"(en), "r"(0u) : "memory");
}
#endif  // TC_PATH

// split pair of fp32 into packed bf16 hi + packed bf16 residual (2 cvt total)
__device__ __forceinline__ void split2(float a, float b, unsigned& h, unsigned& l) {
    asm("cvt.rn.bf16x2.f32 %0, %1, %2;" : "=r"(h) : "f"(b), "f"(a));
    float ha = __uint_as_float(h << 16);
    float hb = __uint_as_float(h & 0xffff0000u);
    asm("cvt.rn.bf16x2.f32 %0, %1, %2;" : "=r"(l) : "f"(b - hb), "f"(a - ha));
}

// ===== weight prep: transpose + bf16 split + SW128 swizzle, per 64-K chunk =====
__global__ void prep_w_kernel(const float* __restrict__ w, int Kdim, unsigned short* __restrict__ outp) {
    int idx = blockIdx.x * blockDim.x + threadIdx.x;
    if (idx >= Kdim * 128) return;
    int k = idx >> 7, n = idx & 127;
    float x = w[(size_t)k * 128 + n];
    __nv_bfloat16 h = __float2bfloat16(x);
    __nv_bfloat16 l = __float2bfloat16(x - __bfloat162float(h));
    int c = k >> 6, kl = k & 63;
    int byte = n * 128 + kl * 2;
    int sw = byte ^ ((byte >> 3) & 0x70);
    char* base = (char*)(outp + (size_t)c * 16384);
    *(unsigned short*)(base + sw) = __bfloat16_as_ushort(h);
    *(unsigned short*)(base + 16384 + sw) = __bfloat16_as_ushort(l);
}

// ================= tc kernels: A 64KB + W 32KB single buffer -> 2 CTAs/SM =================
#define TC_SMEM 101376

__global__ void __launch_bounds__(256) edge_tc_kernel(
    float* __restrict__ e, const float* __restrict__ v,
    const int* __restrict__ src, const int* __restrict__ dst,
    const unsigned short* __restrict__ wt,
    const float* __restrict__ w0f, const float* __restrict__ w1f, const float* __restrict__ w2f,
    const float* __restrict__ b0, const float* __restrict__ b1, const float* __restrict__ b2,
    float* __restrict__ agg) {
    extern __shared__ float smraw[];
#if TC_PATH
    uint32 raw = smem_u32(smraw);
    uint32 sb = (raw + 1023) & ~1023u;
    char* gb = (char*)smraw + (sb - raw);

    const uint32 A_B = sb;
    const uint32 W_B = sb + 65536;
    const uint32 MISC = sb + 98304;
    char* A_g = gb;
    char* W_g = gb + 65536;
    uint32 slot = MISC;
    uint32 mb0 = MISC + 8;
    int* s_src = (int*)(gb + 98304 + 16);
    int* s_dst = s_src + 128;

    const int t = threadIdx.x;
    const int wid = t >> 5, lid = t & 31;
    const int row0 = blockIdx.x * 128;

    if (t < 128) {
        int r = row0 + t;
        if (r >= Ee) r = Ee - 1;
        s_src[t] = src[r];
        s_dst[t] = dst[r];
    }
    if (t == 0) MBARRIER_INIT(mb0, 1);
    if (wid == 0) { TCGEN05_ALLOC(slot, 128); TCGEN05_RELINQ(); }
    __syncthreads();
    uint32 tmb;
    asm volatile("ld.shared.b32 %0, [%1];" : "=r"(tmb) : "r"(slot));
    int par = 0;

    auto fill_A = [&](int kc) {
        char* hi = A_g + (kc & 1) * 32768;
        char* lo = hi + 16384;
#pragma unroll
        for (int i = 0; i < 8; i++) {
            int fi = i * 256 + t;
            int row = fi >> 4, q = fi & 15;
            int grow = row0 + row; if (grow >= Ee) grow = Ee - 1;
            const float* rp;
            if (kc < 2)      rp = e + (size_t)grow * 128;
            else if (kc < 4) rp = v + (size_t)s_src[row] * 128;
            else             rp = v + (size_t)s_dst[row] * 128;
            float4 x = *(const float4*)(rp + (kc & 1) * 64 + q * 4);
            uint2 hb, lb;
            split2(x.x, x.y, hb.x, lb.x);
            split2(x.z, x.w, hb.y, lb.y);
            int byte = row * 128 + q * 8;
            int sw = byte ^ ((byte >> 3) & 0x70);
            *(uint2*)(hi + sw) = hb;
            *(uint2*)(lo + sw) = lb;
        }
    };
    auto fill_W = [&](const unsigned short* chunk) {
        const uint4* s = (const uint4*)chunk;
        uint4* d = (uint4*)W_g;
#pragma unroll
        for (int i = 0; i < 8; i++) d[i * 256 + t] = s[i * 256 + t];
    };
    auto mma_chunk = [&](uint32 aoff, bool first) {
        if (wid == 0 && elect_one_pred()) {
            FENCE_PROXY_ASYNC();
            unsigned long long ah = MAKE_SMEM_DESC(aoff);
            unsigned long long al = MAKE_SMEM_DESC(aoff + 16384);
            unsigned long long wh = MAKE_SMEM_DESC(W_B);
            unsigned long long wl = MAKE_SMEM_DESC(W_B + 16384);
            uint32 en = first ? 0u : 1u;
#pragma unroll
            for (int s = 0; s < 4; s++) {
                mma_ss_bf16(tmb, ah + s * 2, wh + s * 2, en); en = 1u;
                mma_ss_bf16(tmb, ah + s * 2, wl + s * 2, 1u);
                mma_ss_bf16(tmb, al + s * 2, wh + s * 2, 1u);
            }
            TCGEN05_COMMIT(mb0);
        }
    };
    auto wait1 = [&]() { MBARRIER_WAIT_PARITY(mb0, par); par ^= 1; };
    auto epi_hidden = [&](const float* __restrict__ bias) {
        TCGEN05_FENCE_AFTER();
        int r = (wid & 3) * 32 + lid;
        int cb0 = (wid >> 2) * 2;
#pragma unroll 1
        for (int k = 0; k < 2; k++) {
            int cb = cb0 + k;
            uint32 d[32];
            TCGEN05_LD_X32(d, tmb + cb * 32);
            TCGEN05_WAIT_LD();
            char* hi = A_g + (cb >> 1) * 32768;
            char* lo = hi + 16384;
#pragma unroll
            for (int j = 0; j < 32; j += 2) {
                float x0 = selu_f(__uint_as_float(d[j])     + __ldg(&bias[cb * 32 + j]));
                float x1 = selu_f(__uint_as_float(d[j + 1]) + __ldg(&bias[cb * 32 + j + 1]));
                unsigned hb, lb;
                split2(x0, x1, hb, lb);
                int c = (cb & 1) * 32 + j;
                int byte = r * 128 + c * 2;
                int sw = byte ^ ((byte >> 3) & 0x70);
                *(unsigned*)(hi + sw) = hb;
                *(unsigned*)(lo + sw) = lb;
            }
        }
        TCGEN05_FENCE_BEFORE();
        __syncthreads();
    };

    // layer 0: K = 384, 6 chunks (single W buffer; fill_A overlaps prior MMA)
    fill_A(0); fill_W(wt); __syncthreads(); mma_chunk(A_B, true);
#pragma unroll 1
    for (int i = 1; i < 6; i++) {
        fill_A(i);
        wait1();
        fill_W(wt + i * 16384); __syncthreads();
        mma_chunk(A_B + (i & 1) * 32768, false);
    }
    wait1();
    epi_hidden(b0);

    // layer 1: K = 128, A resident
    fill_W(wt + 6 * 16384); __syncthreads(); mma_chunk(A_B, true);
    wait1();
    fill_W(wt + 7 * 16384); __syncthreads(); mma_chunk(A_B + 32768, false);
    wait1();
    epi_hidden(b1);

    // layer 2
    fill_W(wt + 8 * 16384); __syncthreads(); mma_chunk(A_B, true);
    wait1();
    fill_W(wt + 9 * 16384); __syncthreads(); mma_chunk(A_B + 32768, false);
    wait1();

    // final epilogue: residual + store e + atomic agg
    TCGEN05_FENCE_AFTER();
    {
        int r = (wid & 3) * 32 + lid;
        int cb0 = (wid >> 2) * 2;
        int grow = row0 + r;
        bool valid = grow < Ee;
        int dn = valid ? s_dst[r] : 0;
#pragma unroll 1
        for (int k = 0; k < 2; k++) {
            int cb = cb0 + k;
            uint32 d[32];
            TCGEN05_LD_X32(d, tmb + cb * 32);
            TCGEN05_WAIT_LD();
            if (valid) {
                float* erow = e + (size_t)grow * 128 + cb * 32;
                float* arow = agg + (size_t)dn * 128 + cb * 32;
#pragma unroll
                for (int q = 0; q < 8; q++) {
                    float4 ev = *(float4*)(erow + q * 4);
                    float4 rr;
                    rr.x = ev.x + __uint_as_float(d[q * 4 + 0]) + __ldg(&b2[cb * 32 + q * 4 + 0]);
                    rr.y = ev.y + __uint_as_float(d[q * 4 + 1]) + __ldg(&b2[cb * 32 + q * 4 + 1]);
                    rr.z = ev.z + __uint_as_float(d[q * 4 + 2]) + __ldg(&b2[cb * 32 + q * 4 + 2]);
                    rr.w = ev.w + __uint_as_float(d[q * 4 + 3]) + __ldg(&b2[cb * 32 + q * 4 + 3]);
                    *(float4*)(erow + q * 4) = rr;
                    atomicAdd(arow + q * 4 + 0, rr.x);
                    atomicAdd(arow + q * 4 + 1, rr.y);
                    atomicAdd(arow + q * 4 + 2, rr.z);
                    atomicAdd(arow + q * 4 + 3, rr.w);
                }
            }
        }
    }
    TCGEN05_FENCE_BEFORE();
    __syncthreads();
    if (wid == 0) TCGEN05_DEALLOC(tmb, 128);
#else
    const int t = threadIdx.x;
    const int row0 = blockIdx.x * 128;
    edge_simt_tile(smraw, e, v, src, dst, w0f, b0, w1f, b1, w2f, b2, agg, row0, t);
    edge_simt_tile(smraw, e, v, src, dst, w0f, b0, w1f, b1, w2f, b2, agg, row0 + 64, t);
#endif
}

__global__ void __launch_bounds__(256) node_tc_kernel(
    float* __restrict__ v, const float* __restrict__ agg, const float* __restrict__ deg,
    const unsigned short* __restrict__ wt,
    const float* __restrict__ w0f, const float* __restrict__ w1f, const float* __restrict__ w2f,
    const float* __restrict__ b0, const float* __restrict__ b1, const float* __restrict__ b2) {
    extern __shared__ float smraw[];
#if TC_PATH
    uint32 raw = smem_u32(smraw);
    uint32 sb = (raw + 1023) & ~1023u;
    char* gb = (char*)smraw + (sb - raw);

    const uint32 A_B = sb;
    const uint32 W_B = sb + 65536;
    const uint32 MISC = sb + 98304;
    char* A_g = gb;
    char* W_g = gb + 65536;
    uint32 slot = MISC;
    uint32 mb0 = MISC + 8;
    float* s_inv = (float*)(gb + 98304 + 16);

    const int t = threadIdx.x;
    const int wid = t >> 5, lid = t & 31;
    const int row0 = blockIdx.x * 128;

    if (t < 128) {
        int r = row0 + t;
        if (r >= Nn) r = Nn - 1;
        s_inv[t] = 1.f / fmaxf(deg[r], 1.f);
    }
    if (t == 0) MBARRIER_INIT(mb0, 1);
    if (wid == 0) { TCGEN05_ALLOC(slot, 128); TCGEN05_RELINQ(); }
    __syncthreads();
    uint32 tmb;
    asm volatile("ld.shared.b32 %0, [%1];" : "=r"(tmb) : "r"(slot));
    int par = 0;

    auto fill_A = [&](int kc) {
        char* hi = A_g + (kc & 1) * 32768;
        char* lo = hi + 16384;
#pragma unroll
        for (int i = 0; i < 8; i++) {
            int fi = i * 256 + t;
            int row = fi >> 4, q = fi & 15;
            int grow = row0 + row; if (grow >= Nn) grow = Nn - 1;
            float4 x;
            if (kc < 2) {
                x = *(const float4*)(v + (size_t)grow * 128 + (kc & 1) * 64 + q * 4);
            } else {
                x = *(const float4*)(agg + (size_t)grow * 128 + (kc & 1) * 64 + q * 4);
                float sc = s_inv[row];
                x.x *= sc; x.y *= sc; x.z *= sc; x.w *= sc;
            }
            uint2 hb, lb;
            split2(x.x, x.y, hb.x, lb.x);
            split2(x.z, x.w, hb.y, lb.y);
            int byte = row * 128 + q * 8;
            int sw = byte ^ ((byte >> 3) & 0x70);
            *(uint2*)(hi + sw) = hb;
            *(uint2*)(lo + sw) = lb;
        }
    };
    auto fill_W = [&](const unsigned short* chunk) {
        const uint4* s = (const uint4*)chunk;
        uint4* d = (uint4*)W_g;
#pragma unroll
        for (int i = 0; i < 8; i++) d[i * 256 + t] = s[i * 256 + t];
    };
    auto mma_chunk = [&](uint32 aoff, bool first) {
        if (wid == 0 && elect_one_pred()) {
            FENCE_PROXY_ASYNC();
            unsigned long long ah = MAKE_SMEM_DESC(aoff);
            unsigned long long al = MAKE_SMEM_DESC(aoff + 16384);
            unsigned long long wh = MAKE_SMEM_DESC(W_B);
            unsigned long long wl = MAKE_SMEM_DESC(W_B + 16384);
            uint32 en = first ? 0u : 1u;
#pragma unroll
            for (int s = 0; s < 4; s++) {
                mma_ss_bf16(tmb, ah + s * 2, wh + s * 2, en); en = 1u;
                mma_ss_bf16(tmb, ah + s * 2, wl + s * 2, 1u);
                mma_ss_bf16(tmb, al + s * 2, wh + s * 2, 1u);
            }
            TCGEN05_COMMIT(mb0);
        }
    };
    auto wait1 = [&]() { MBARRIER_WAIT_PARITY(mb0, par); par ^= 1; };
    auto epi_hidden = [&](const float* __restrict__ bias) {
        TCGEN05_FENCE_AFTER();
        int r = (wid & 3) * 32 + lid;
        int cb0 = (wid >> 2) * 2;
#pragma unroll 1
        for (int k = 0; k < 2; k++) {
            int cb = cb0 + k;
            uint32 d[32];
            TCGEN05_LD_X32(d, tmb + cb * 32);
            TCGEN05_WAIT_LD();
            char* hi = A_g + (cb >> 1) * 32768;
            char* lo = hi + 16384;
#pragma unroll
            for (int j = 0; j < 32; j += 2) {
                float x0 = selu_f(__uint_as_float(d[j])     + __ldg(&bias[cb * 32 + j]));
                float x1 = selu_f(__uint_as_float(d[j + 1]) + __ldg(&bias[cb * 32 + j + 1]));
                unsigned hb, lb;
                split2(x0, x1, hb, lb);
                int c = (cb & 1) * 32 + j;
                int byte = r * 128 + c * 2;
                int sw = byte ^ ((byte >> 3) & 0x70);
                *(unsigned*)(hi + sw) = hb;
                *(unsigned*)(lo + sw) = lb;
            }
        }
        TCGEN05_FENCE_BEFORE();
        __syncthreads();
    };

    // layer 0: K = 256, 4 chunks
    fill_A(0); fill_W(wt); __syncthreads(); mma_chunk(A_B, true);
#pragma unroll 1
    for (int i = 1; i < 4; i++) {
        fill_A(i);
        wait1();
        fill_W(wt + i * 16384); __syncthreads();
        mma_chunk(A_B + (i & 1) * 32768, false);
    }
    wait1();
    epi_hidden(b0);

    // layer 1
    fill_W(wt + 4 * 16384); __syncthreads(); mma_chunk(A_B, true);
    wait1();
    fill_W(wt + 5 * 16384); __syncthreads(); mma_chunk(A_B + 32768, false);
    wait1();
    epi_hidden(b1);

    // layer 2
    fill_W(wt + 6 * 16384); __syncthreads(); mma_chunk(A_B, true);
    wait1();
    fill_W(wt + 7 * 16384); __syncthreads(); mma_chunk(A_B + 32768, false);
    wait1();

    // final epilogue: v += d + b2
    TCGEN05_FENCE_AFTER();
    {
        int r = (wid & 3) * 32 + lid;
        int cb0 = (wid >> 2) * 2;
        int grow = row0 + r;
        bool valid = grow < Nn;
#pragma unroll 1
        for (int k = 0; k < 2; k++) {
            int cb = cb0 + k;
            uint32 d[32];
            TCGEN05_LD_X32(d, tmb + cb * 32);
            TCGEN05_WAIT_LD();
            if (valid) {
                float* vrow = v + (size_t)grow * 128 + cb * 32;
#pragma unroll
                for (int q = 0; q < 8; q++) {
                    float4 vv = *(float4*)(vrow + q * 4);
                    vv.x += __uint_as_float(d[q * 4 + 0]) + __ldg(&b2[cb * 32 + q * 4 + 0]);
                    vv.y += __uint_as_float(d[q * 4 + 1]) + __ldg(&b2[cb * 32 + q * 4 + 1]);
                    vv.z += __uint_as_float(d[q * 4 + 2]) + __ldg(&b2[cb * 32 + q * 4 + 2]);
                    vv.w += __uint_as_float(d[q * 4 + 3]) + __ldg(&b2[cb * 32 + q * 4 + 3]);
                    *(float4*)(vrow + q * 4) = vv;
                }
            }
        }
    }
    TCGEN05_FENCE_BEFORE();
    __syncthreads();
    if (wid == 0) TCGEN05_DEALLOC(tmb, 128);
#else
    const int t = threadIdx.x;
    const int row0 = blockIdx.x * 128;
    node_simt_tile(smraw, v, agg, deg, w0f, b0, w1f, b1, w2f, b2, row0, t);
    node_simt_tile(smraw, v, agg, deg, w0f, b0, w1f, b1, w2f, b2, row0 + 64, t);
#endif
}

// ---------------- pool: atomic-add MLP([v, rel]) into vc sums ----------------
__global__ void __launch_bounds__(128) pool_kernel(
    const float* __restrict__ v, const float* __restrict__ pos,
    const int* __restrict__ cluster, const float* __restrict__ cpos,
    const float* __restrict__ w0, const float* __restrict__ b0,
    const float* __restrict__ w1, const float* __restrict__ b1,
    const float* __restrict__ w2, const float* __restrict__ b2,
    float* __restrict__ vc) {
    extern __shared__ float sm[];
    float* As = sm + AS_OFF;
    float* Bs = sm + BS_OFF;
    float* Hs = sm + HS_OFF;
    float* s_rel = sm + IX_OFF;
    int* s_cl = (int*)(sm + IX_OFF + 64);

    const int t = threadIdx.x;
    const int row0 = blockIdx.x * 64;
    if (t < 64) {
        int r = row0 + t;
        if (r >= Nn) r = Nn - 1;
        int cl = cluster[r];
        float dx = pos[2 * r] - cpos[2 * cl];
        float dy = pos[2 * r + 1] - cpos[2 * cl + 1];
        s_rel[t] = sqrtf(dx * dx + dy * dy + 1e-12f);
        s_cl[t] = cl;
    }
    const int c0 = (t & 15) * 8;
    const int gb = (t & 15) * 12;
    const int r0 = (t >> 4) * 8;
    __syncthreads();

    ull acc[8][4];
    acc_init(acc, b0, c0);

    auto fill_As = [&](float* dstA, int kt) {
#pragma unroll
        for (int i = 0; i < 2; i++) {
            int f = t * 2 + i;
            int ar = f >> 2;
            int kl = (f & 3) << 2;
            int grow = row0 + ar;
            if (grow >= Nn) grow = Nn - 1;
            float4 val = *(const float4*)(v + (size_t)grow * 128 + kt + kl);
            *(float4*)&dstA[ar * 20 + kl] = val;
        }
    };
    fill_As(As, 0);
    fill_Bs(Bs, w0, 0, t);
    __syncthreads();
#pragma unroll 1
    for (int kt = 0; kt < 8; kt++) {
        if (kt < 7) {
            int nb = (kt + 1) & 1;
            fill_As(As + nb * AS_BUF, (kt + 1) * 16);
            fill_Bs(Bs + nb * BS_BUF, w0, (kt + 1) * 16, t);
        }
        mma16<20>(As + (kt & 1) * AS_BUF, 0, Bs + (kt & 1) * BS_BUF, r0, gb, acc);
        __syncthreads();
    }
    {
        ull wx[4];
#pragma unroll
        for (int j = 0; j < 4; j++) wx[j] = *(const ull*)&w0[128 * 128 + c0 + 2 * j];
#pragma unroll
        for (int i = 0; i < 8; i++) {
            ull rl2 = dupf(s_rel[r0 + i]);
#pragma unroll
            for (int j = 0; j < 4; j++) ffma2(acc[i][j], rl2, wx[j]);
        }
    }
    selu_store(Hs, acc, r0, c0);
    acc_init(acc, b1, c0);
    hidden_layer(w1, Hs, Bs, t, r0, gb, acc, true);
    selu_store(Hs, acc, r0, c0);
    acc_init(acc, b2, c0);
    hidden_layer(w2, Hs, Bs, t, r0, gb, acc, true);

#pragma unroll
    for (int i = 0; i < 8; i++) {
        int row = row0 + r0 + i;
        if (row < Nn) {
            int cl = s_cl[r0 + i];
            float* crow = vc + (size_t)cl * 128 + c0;
            float2 p0 = unpk(acc[i][0]), p1 = unpk(acc[i][1]);
            float2 p2 = unpk(acc[i][2]), p3 = unpk(acc[i][3]);
            float rr[8] = {p0.x, p0.y, p1.x, p1.y, p2.x, p2.y, p3.x, p3.y};
#pragma unroll
            for (int j = 0; j < 8; j++) atomicAdd(&crow[j], rr[j]);
        }
    }
}

// ---------------- coarse edge encoder ----------------
__global__ void __launch_bounds__(128) eenc_kernel(
    const int* __restrict__ cei, const float* __restrict__ cpos,
    const float* __restrict__ w0, const float* __restrict__ b0,
    const float* __restrict__ w1, const float* __restrict__ b1,
    const float* __restrict__ w2, const float* __restrict__ b2,
    float* __restrict__ ec) {
    extern __shared__ float sm[];
    float* Bs = sm + BS_OFF;
    float* Hs = sm + HS_OFF;
    float* s_crel = sm + IX_OFF;

    const int t = threadIdx.x;
    const int row0 = blockIdx.x * 64;
    if (t < 64) {
        int r = row0 + t;
        if (r >= ECc) r = ECc - 1;
        int a = cei[r];
        int b = cei[ECc + r];
        float dx = cpos[2 * a] - cpos[2 * b];
        float dy = cpos[2 * a + 1] - cpos[2 * b + 1];
        s_crel[t] = sqrtf(dx * dx + dy * dy + 1e-12f);
    }
    const int c0 = (t & 15) * 8;
    const int gb = (t & 15) * 12;
    const int r0 = (t >> 4) * 8;
    __syncthreads();

#pragma unroll
    for (int i = 0; i < 8; i++) {
        float cr = s_crel[r0 + i];
#pragma unroll
        for (int j = 0; j < 8; j++)
            Hs[(r0 + i) * 132 + c0 + j] =
                selu_f(fmaf(cr, __ldg(&w0[c0 + j]), __ldg(&b0[c0 + j])));
    }

    ull acc[8][4];
    acc_init(acc, b1, c0);
    hidden_layer(w1, Hs, Bs, t, r0, gb, acc, true);
    selu_store(Hs, acc, r0, c0);
    acc_init(acc, b2, c0);
    hidden_layer(w2, Hs, Bs, t, r0, gb, acc, true);

#pragma unroll
    for (int i = 0; i < 8; i++) {
        int row = row0 + r0 + i;
        if (row < ECc) {
            float* erow = ec + (size_t)row * 128 + c0;
            float2 p0 = unpk(acc[i][0]), p1 = unpk(acc[i][1]);
            float2 p2 = unpk(acc[i][2]), p3 = unpk(acc[i][3]);
            *(float4*)erow       = make_float4(p0.x, p0.y, p1.x, p1.y);
            *(float4*)(erow + 4) = make_float4(p2.x, p2.y, p3.x, p3.y);
        }
    }
}

// ---------------- small helpers ----------------
__global__ void deg_scatter(const int* __restrict__ dst, float* __restrict__ deg) {
    int i = blockIdx.x * blockDim.x + threadIdx.x;
    if (i < Ee) atomicAdd(&deg[dst[i]], 1.f);
}
__global__ void cpos_scatter(const float* __restrict__ pos, const int* __restrict__ cluster,
                             float* __restrict__ cposs, float* __restrict__ ccnt) {
    int i = blockIdx.x * blockDim.x + threadIdx.x;
    if (i < Nn) {
        int c = cluster[i];
        atomicAdd(&cposs[2 * c], pos[2 * i]);
        atomicAdd(&cposs[2 * c + 1], pos[2 * i + 1]);
        atomicAdd(&ccnt[c], 1.f);
    }
}
__global__ void cpos_fin(const float* __restrict__ cposs, const float* __restrict__ ccnt,
                         float* __restrict__ cpos, float* __restrict__ cinv) {
    int c = blockIdx.x * blockDim.x + threadIdx.x;
    if (c < NCc) {
        float inv = 1.f / fmaxf(ccnt[c], 1.f);
        cpos[2 * c] = cposs[2 * c] * inv;
        cpos[2 * c + 1] = cposs[2 * c + 1] * inv;
        cinv[c] = inv;
    }
}
__global__ void vc_scale(float* __restrict__ vc, const float* __restrict__ cinv) {
    int i = blockIdx.x * blockDim.x + threadIdx.x;
    if (i < NCc * 128) vc[i] *= cinv[i >> 7];
}

// ---------------- launch ----------------
extern "C" void kernel_launch(void* const* d_in, const int* in_sizes, int n_in,
                              void* d_out, int out_size) {
    const float* v0      = (const float*)d_in[0];
    const float* e0      = (const float*)d_in[1];
    const float* pos     = (const float*)d_in[2];
    const int*   ei      = (const int*)d_in[3];
    const int*   cluster = (const int*)d_in[4];
    const int*   cei     = (const int*)d_in[5];
    const float* ew0 = (const float*)d_in[6],  *eb0 = (const float*)d_in[7];
    const float* ew1 = (const float*)d_in[8],  *eb1 = (const float*)d_in[9];
    const float* ew2 = (const float*)d_in[10], *eb2 = (const float*)d_in[11];
    const float* nw0 = (const float*)d_in[12], *nb0 = (const float*)d_in[13];
    const float* nw1 = (const float*)d_in[14], *nb1 = (const float*)d_in[15];
    const float* nw2 = (const float*)d_in[16], *nb2 = (const float*)d_in[17];
    const float* pw0 = (const float*)d_in[18], *pb0 = (const float*)d_in[19];
    const float* pw1 = (const float*)d_in[20], *pb1 = (const float*)d_in[21];
    const float* pw2 = (const float*)d_in[22], *pb2 = (const float*)d_in[23];
    const float* qw0 = (const float*)d_in[24], *qb0 = (const float*)d_in[25];
    const float* qw1 = (const float*)d_in[26], *qb1 = (const float*)d_in[27];
    const float* qw2 = (const float*)d_in[28], *qb2 = (const float*)d_in[29];

    float* out    = (float*)d_out;
    float* out_vc = out;
    float* out_ec = out + OFF_EC;
    float* vbuf   = out + OFF_V;
    float* ebuf   = out + OFF_E;

    float *agg, *deg, *cposs, *ccnt, *cpos, *cinv;
    unsigned short *wt, *wtn;
    cudaGetSymbolAddress((void**)&agg,   g_agg);
    cudaGetSymbolAddress((void**)&deg,   g_deg);
    cudaGetSymbolAddress((void**)&cposs, g_cposs);
    cudaGetSymbolAddress((void**)&ccnt,  g_ccnt);
    cudaGetSymbolAddress((void**)&cpos,  g_cpos);
    cudaGetSymbolAddress((void**)&cinv,  g_cinv);
    cudaGetSymbolAddress((void**)&wt,    g_wt);
    cudaGetSymbolAddress((void**)&wtn,   g_wtn);

    cudaFuncSetAttribute(edge_tc_kernel, cudaFuncAttributeMaxDynamicSharedMemorySize, TC_SMEM);
    cudaFuncSetAttribute(node_tc_kernel, cudaFuncAttributeMaxDynamicSharedMemorySize, TC_SMEM);
    cudaFuncSetAttribute(pool_kernel, cudaFuncAttributeMaxDynamicSharedMemorySize, SIMT_SMEM);
    cudaFuncSetAttribute(eenc_kernel, cudaFuncAttributeMaxDynamicSharedMemorySize, SIMT_SMEM);

    cudaMemcpyAsync(vbuf, v0, sizeof(float) * (size_t)Nn * 128, cudaMemcpyDeviceToDevice, 0);
    cudaMemcpyAsync(ebuf, e0, sizeof(float) * (size_t)Ee * 128, cudaMemcpyDeviceToDevice, 0);

    const int* src  = ei;
    const int* dstp = ei + Ee;

    cudaMemsetAsync(deg, 0, sizeof(float) * Nn, 0);
    deg_scatter<<<(Ee + 255) / 256, 256>>>(dstp, deg);

    // prep all weights (transpose + bf16 split + swizzle)
    for (int d = 0; d < 4; d++) {
        unsigned short* wtb = wt + (size_t)d * 163840;
        prep_w_kernel<<<(384 * 128 + 255) / 256, 256>>>(ew0 + (size_t)d * 384 * 128, 384, wtb);
        prep_w_kernel<<<(128 * 128 + 255) / 256, 256>>>(ew1 + (size_t)d * 128 * 128, 128, wtb + 6 * 16384);
        prep_w_kernel<<<(128 * 128 + 255) / 256, 256>>>(ew2 + (size_t)d * 128 * 128, 128, wtb + 8 * 16384);
        unsigned short* wnb = wtn + (size_t)d * 131072;
        prep_w_kernel<<<(256 * 128 + 255) / 256, 256>>>(nw0 + (size_t)d * 256 * 128, 256, wnb);
        prep_w_kernel<<<(128 * 128 + 255) / 256, 256>>>(nw1 + (size_t)d * 128 * 128, 128, wnb + 4 * 16384);
        prep_w_kernel<<<(128 * 128 + 255) / 256, 256>>>(nw2 + (size_t)d * 128 * 128, 128, wnb + 6 * 16384);
    }

    for (int d = 0; d < 4; d++) {
        cudaMemsetAsync(agg, 0, sizeof(float) * (size_t)Nn * 128, 0);
        edge_tc_kernel<<<(Ee + 127) / 128, 256, TC_SMEM>>>(
            ebuf, vbuf, src, dstp, wt + (size_t)d * 163840,
            ew0 + (size_t)d * 384 * 128, ew1 + (size_t)d * 128 * 128, ew2 + (size_t)d * 128 * 128,
            eb0 + d * 128, eb1 + d * 128, eb2 + d * 128, agg);
        node_tc_kernel<<<(Nn + 127) / 128, 256, TC_SMEM>>>(
            vbuf, agg, deg, wtn + (size_t)d * 131072,
            nw0 + (size_t)d * 256 * 128, nw1 + (size_t)d * 128 * 128, nw2 + (size_t)d * 128 * 128,
            nb0 + d * 128, nb1 + d * 128, nb2 + d * 128);
    }

    cudaMemsetAsync(cposs, 0, sizeof(float) * NCc * 2, 0);
    cudaMemsetAsync(ccnt, 0, sizeof(float) * NCc, 0);
    cpos_scatter<<<(Nn + 255) / 256, 256>>>(pos, cluster, cposs, ccnt);
    cpos_fin<<<(NCc + 255) / 256, 256>>>(cposs, ccnt, cpos, cinv);

    cudaMemsetAsync(out_vc, 0, sizeof(float) * NCc * 128, 0);
    pool_kernel<<<(Nn + 63) / 64, 128, SIMT_SMEM>>>(vbuf, pos, cluster, cpos,
                                                    pw0, pb0, pw1, pb1, pw2, pb2, out_vc);
    vc_scale<<<(NCc * 128 + 255) / 256, 256>>>(out_vc, cinv);

    eenc_kernel<<<(ECc + 63) / 64, 128, SIMT_SMEM>>>(cei, cpos, qw0, qb0, qw1, qb1, qw2, qb2, out_ec);
}

// round 13
// speedup vs baseline: 3.5223x; 1.2846x over previous
#include <cuda_runtime.h>
#include <cuda_bf16.h>
#include <math.h>

#define Nn  50000
#define Ee  300000
#define NCc 12500
#define ECc 75000

#define OFF_EC 1600000
#define OFF_V  11200000
#define OFF_E  17600000

typedef unsigned long long ull;
typedef unsigned int uint32;

#if defined(__CUDA_ARCH__) && defined(__CUDA_ARCH_FEAT_SM103_ALL)
#define TC_PATH 1
#else
#define TC_PATH 0
#endif

// ================= device scratch =================
__device__ float g_agg[Nn * 128];
__device__ float g_deg[Nn];
__device__ float g_cposs[NCc * 2];
__device__ float g_ccnt[NCc];
__device__ float g_cpos[NCc * 2];
__device__ float g_cinv[NCc];
__device__ unsigned short g_wt[4 * 10 * 16384];   // edge weights
__device__ unsigned short g_wtn[4 * 8 * 16384];   // node weights
__device__ unsigned short g_wtp[6 * 16384];       // pool weights
__device__ unsigned short g_wtq[4 * 16384];       // eenc weights

__device__ __forceinline__ float selu_f(float x) {
    return x > 0.f ? 1.0507009873554805f * x : 1.7580993408473766f * expm1f(x);
}
__device__ __forceinline__ void red_add_v4(float* addr, float4 v) {
    asm volatile("red.global.add.v4.f32 [%0], {%1, %2, %3, %4};"
                 :: "l"(addr), "f"(v.x), "f"(v.y), "f"(v.z), "f"(v.w) : "memory");
}

// ================= SIMT FFMA2 machinery (fallback only at runtime) =================
#define AS_OFF 0
#define AS_BUF 1280
#define BS_OFF 2560
#define BS_BUF 3072
#define HS_OFF 8704
#define IX_OFF 17152
#define SIMT_FLOATS 17312

__device__ __forceinline__ void ffma2(ull& d, ull a, ull b) {
    asm("fma.rn.f32x2 %0, %1, %2, %0;" : "+l"(d) : "l"(a), "l"(b));
}
__device__ __forceinline__ float2 unpk(ull p) {
    float2 f;
    asm("mov.b64 {%0, %1}, %2;" : "=f"(f.x), "=f"(f.y) : "l"(p));
    return f;
}
__device__ __forceinline__ ull dupf(float x) {
    ull r;
    asm("mov.b64 %0, {%1, %1};" : "=l"(r) : "f"(x));
    return r;
}
__device__ __forceinline__ void acc_init(ull (&acc)[8][4], const float* __restrict__ b, int c0) {
    ull bb[4];
#pragma unroll
    for (int j = 0; j < 4; j++) bb[j] = *(const ull*)&b[c0 + 2 * j];
#pragma unroll
    for (int i = 0; i < 8; i++)
#pragma unroll
        for (int j = 0; j < 4; j++) acc[i][j] = bb[j];
}
__device__ __forceinline__ void fill_Bs(float* Bs, const float* __restrict__ W, int kt, int t) {
    const float4* wsrc = (const float4*)(W + (size_t)kt * 128);
#pragma unroll
    for (int i = 0; i < 4; i++) {
        int fi = i * 128 + t;
        float4 w = wsrc[fi];
        int k = fi >> 5;
        int q = fi & 31;
        *(float4*)&Bs[k * 192 + (q >> 1) * 12 + (q & 1) * 4] = w;
    }
}
template <int STRIDE>
__device__ __forceinline__ void mma16(const float* A, int koff, const float* Bs,
                                      int r0, int gb, ull (&acc)[8][4]) {
#pragma unroll
    for (int k4 = 0; k4 < 4; k4++) {
        float4 a4[8];
#pragma unroll
        for (int i = 0; i < 8; i++)
            a4[i] = *(const float4*)&A[(r0 + i) * STRIDE + koff + 4 * k4];
#pragma unroll
        for (int kk = 0; kk < 4; kk++) {
            const float* bp = &Bs[(4 * k4 + kk) * 192 + gb];
            ulonglong2 bA = *(const ulonglong2*)bp;
            ulonglong2 bB = *(const ulonglong2*)(bp + 4);
#pragma unroll
            for (int i = 0; i < 8; i++) {
                float av = (kk == 0) ? a4[i].x : (kk == 1) ? a4[i].y
                         : (kk == 2) ? a4[i].z : a4[i].w;
                ull ad = dupf(av);
                ffma2(acc[i][0], ad, bA.x);
                ffma2(acc[i][1], ad, bA.y);
                ffma2(acc[i][2], ad, bB.x);
                ffma2(acc[i][3], ad, bB.y);
            }
        }
    }
}
__device__ __forceinline__ void selu_store(float* Hs, ull (&acc)[8][4], int r0, int c0) {
#pragma unroll
    for (int i = 0; i < 8; i++) {
        float2 p0 = unpk(acc[i][0]), p1 = unpk(acc[i][1]);
        float2 p2 = unpk(acc[i][2]), p3 = unpk(acc[i][3]);
        *(float4*)&Hs[(r0 + i) * 132 + c0] =
            make_float4(selu_f(p0.x), selu_f(p0.y), selu_f(p1.x), selu_f(p1.y));
        *(float4*)&Hs[(r0 + i) * 132 + c0 + 4] =
            make_float4(selu_f(p2.x), selu_f(p2.y), selu_f(p3.x), selu_f(p3.y));
    }
}
__device__ __forceinline__ void hidden_layer(const float* __restrict__ W,
                                             const float* Hs, float* BsBase,
                                             int t, int r0, int gb, ull (&acc)[8][4],
                                             bool act) {
    if (act) fill_Bs(BsBase, W, 0, t);
    __syncthreads();
#pragma unroll 1
    for (int kt = 0; kt < 8; kt++) {
        if (kt < 7 && act) fill_Bs(BsBase + ((kt + 1) & 1) * BS_BUF, W, (kt + 1) * 16, t);
        mma16<132>(Hs, kt * 16, BsBase + (kt & 1) * BS_BUF, r0, gb, acc);
        __syncthreads();
    }
}

// ---------------- fallback SIMT tiles ----------------
__device__ void edge_simt_tile(
    float* sm, float* __restrict__ e, const float* __restrict__ v,
    const int* __restrict__ src, const int* __restrict__ dst,
    const float* __restrict__ w0, const float* __restrict__ b0,
    const float* __restrict__ w1, const float* __restrict__ b1,
    const float* __restrict__ w2, const float* __restrict__ b2,
    float* __restrict__ agg, int row0, int tfull) {
    float* As = sm + AS_OFF;
    float* Bs = sm + BS_OFF;
    float* Hs = sm + HS_OFF;
    int* s_src = (int*)(sm + IX_OFF);
    int* s_dst = s_src + 64;
    const bool act = tfull < 128;
    const int t = tfull & 127;

    __syncthreads();
    if (act && t < 64) {
        int r = row0 + t;
        if (r >= Ee) r = Ee - 1;
        s_src[t] = src[r];
        s_dst[t] = dst[r];
    }
    const int c0 = (t & 15) * 8;
    const int gb = (t & 15) * 12;
    const int r0 = (t >> 4) * 8;
    __syncthreads();

    ull acc[8][4];
    acc_init(acc, b0, c0);

    auto fill_As = [&](float* dstA, int kt) {
#pragma unroll
        for (int i = 0; i < 2; i++) {
            int f = t * 2 + i;
            int ar = f >> 2;
            int kl = (f & 3) << 2;
            int k = kt + kl;
            int grow = row0 + ar;
            if (grow >= Ee) grow = Ee - 1;
            float4 val;
            if (k < 128)      val = *(const float4*)(e + (size_t)grow * 128 + k);
            else if (k < 256) val = *(const float4*)(v + (size_t)s_src[ar] * 128 + (k - 128));
            else              val = *(const float4*)(v + (size_t)s_dst[ar] * 128 + (k - 256));
            *(float4*)&dstA[ar * 20 + kl] = val;
        }
    };
    if (act) { fill_As(As, 0); fill_Bs(Bs, w0, 0, t); }
    __syncthreads();
#pragma unroll 1
    for (int kt = 0; kt < 24; kt++) {
        if (kt < 23 && act) {
            int nb = (kt + 1) & 1;
            fill_As(As + nb * AS_BUF, (kt + 1) * 16);
            fill_Bs(Bs + nb * BS_BUF, w0, (kt + 1) * 16, t);
        }
        mma16<20>(As + (kt & 1) * AS_BUF, 0, Bs + (kt & 1) * BS_BUF, r0, gb, acc);
        __syncthreads();
    }
    if (act) selu_store(Hs, acc, r0, c0);
    acc_init(acc, b1, c0);
    hidden_layer(w1, Hs, Bs, t, r0, gb, acc, act);
    if (act) selu_store(Hs, acc, r0, c0);
    acc_init(acc, b2, c0);
    hidden_layer(w2, Hs, Bs, t, r0, gb, acc, act);

    if (act) {
#pragma unroll
        for (int i = 0; i < 8; i++) {
            int row = row0 + r0 + i;
            if (row < Ee) {
                int dn = s_dst[r0 + i];
                float* erow = e + (size_t)row * 128 + c0;
                float* arow = agg + (size_t)dn * 128 + c0;
                float2 p0 = unpk(acc[i][0]), p1 = unpk(acc[i][1]);
                float2 p2 = unpk(acc[i][2]), p3 = unpk(acc[i][3]);
                float4 e0 = *(float4*)erow;
                float4 e1 = *(float4*)(erow + 4);
                float4 rA = make_float4(e0.x + p0.x, e0.y + p0.y, e0.z + p1.x, e0.w + p1.y);
                float4 rB = make_float4(e1.x + p2.x, e1.y + p2.y, e1.z + p3.x, e1.w + p3.y);
                *(float4*)erow       = rA;
                *(float4*)(erow + 4) = rB;
                red_add_v4(arow, rA);
                red_add_v4(arow + 4, rB);
            }
        }
    }
}

__device__ void node_simt_tile(
    float* sm, float* __restrict__ v, const float* __restrict__ agg,
    const float* __restrict__ deg,
    const float* __restrict__ w0, const float* __restrict__ b0,
    const float* __restrict__ w1, const float* __restrict__ b1,
    const float* __restrict__ w2, const float* __restrict__ b2,
    int row0, int tfull) {
    float* As = sm + AS_OFF;
    float* Bs = sm + BS_OFF;
    float* Hs = sm + HS_OFF;
    float* s_inv = sm + IX_OFF;
    const bool act = tfull < 128;
    const int t = tfull & 127;

    __syncthreads();
    if (act && t < 64) {
        int r = row0 + t;
        if (r >= Nn) r = Nn - 1;
        s_inv[t] = 1.f / fmaxf(deg[r], 1.f);
    }
    const int c0 = (t & 15) * 8;
    const int gb = (t & 15) * 12;
    const int r0 = (t >> 4) * 8;
    __syncthreads();

    ull acc[8][4];
    acc_init(acc, b0, c0);

    auto fill_As = [&](float* dstA, int kt) {
#pragma unroll
        for (int i = 0; i < 2; i++) {
            int f = t * 2 + i;
            int ar = f >> 2;
            int kl = (f & 3) << 2;
            int k = kt + kl;
            int grow = row0 + ar;
            if (grow >= Nn) grow = Nn - 1;
            float4 val;
            if (k < 128) {
                val = *(const float4*)(v + (size_t)grow * 128 + k);
            } else {
                val = *(const float4*)(agg + (size_t)grow * 128 + (k - 128));
                float sc = s_inv[ar];
                val.x *= sc; val.y *= sc; val.z *= sc; val.w *= sc;
            }
            *(float4*)&dstA[ar * 20 + kl] = val;
        }
    };
    if (act) { fill_As(As, 0); fill_Bs(Bs, w0, 0, t); }
    __syncthreads();
#pragma unroll 1
    for (int kt = 0; kt < 16; kt++) {
        if (kt < 15 && act) {
            int nb = (kt + 1) & 1;
            fill_As(As + nb * AS_BUF, (kt + 1) * 16);
            fill_Bs(Bs + nb * BS_BUF, w0, (kt + 1) * 16, t);
        }
        mma16<20>(As + (kt & 1) * AS_BUF, 0, Bs + (kt & 1) * BS_BUF, r0, gb, acc);
        __syncthreads();
    }
    if (act) selu_store(Hs, acc, r0, c0);
    acc_init(acc, b1, c0);
    hidden_layer(w1, Hs, Bs, t, r0, gb, acc, act);
    if (act) selu_store(Hs, acc, r0, c0);
    acc_init(acc, b2, c0);
    hidden_layer(w2, Hs, Bs, t, r0, gb, acc, act);

    if (act) {
#pragma unroll
        for (int i = 0; i < 8; i++) {
            int row = row0 + r0 + i;
            if (row < Nn) {
                float* vrow = v + (size_t)row * 128 + c0;
                float2 p0 = unpk(acc[i][0]), p1 = unpk(acc[i][1]);
                float2 p2 = unpk(acc[i][2]), p3 = unpk(acc[i][3]);
                float4 v0 = *(float4*)vrow;
                float4 v1 = *(float4*)(vrow + 4);
                *(float4*)vrow       = make_float4(v0.x + p0.x, v0.y + p0.y, v0.z + p1.x, v0.w + p1.y);
                *(float4*)(vrow + 4) = make_float4(v1.x + p2.x, v1.y + p2.y, v1.z + p3.x, v1.w + p3.y);
            }
        }
    }
}

__device__ void pool_simt_tile(
    float* sm, const float* __restrict__ v, const float* __restrict__ pos,
    const int* __restrict__ cluster, const float* __restrict__ cpos,
    const float* __restrict__ w0, const float* __restrict__ b0,
    const float* __restrict__ w1, const float* __restrict__ b1,
    const float* __restrict__ w2, const float* __restrict__ b2,
    float* __restrict__ vc, int row0, int tfull) {
    float* As = sm + AS_OFF;
    float* Bs = sm + BS_OFF;
    float* Hs = sm + HS_OFF;
    float* s_rel = sm + IX_OFF;
    int* s_cl = (int*)(sm + IX_OFF + 64);
    const bool act = tfull < 128;
    const int t = tfull & 127;

    __syncthreads();
    if (act && t < 64) {
        int r = row0 + t;
        if (r >= Nn) r = Nn - 1;
        int cl = cluster[r];
        float dx = pos[2 * r] - cpos[2 * cl];
        float dy = pos[2 * r + 1] - cpos[2 * cl + 1];
        s_rel[t] = sqrtf(dx * dx + dy * dy + 1e-12f);
        s_cl[t] = cl;
    }
    const int c0 = (t & 15) * 8;
    const int gb = (t & 15) * 12;
    const int r0 = (t >> 4) * 8;
    __syncthreads();

    ull acc[8][4];
    acc_init(acc, b0, c0);

    auto fill_As = [&](float* dstA, int kt) {
#pragma unroll
        for (int i = 0; i < 2; i++) {
            int f = t * 2 + i;
            int ar = f >> 2;
            int kl = (f & 3) << 2;
            int grow = row0 + ar;
            if (grow >= Nn) grow = Nn - 1;
            float4 val = *(const float4*)(v + (size_t)grow * 128 + kt + kl);
            *(float4*)&dstA[ar * 20 + kl] = val;
        }
    };
    if (act) { fill_As(As, 0); fill_Bs(Bs, w0, 0, t); }
    __syncthreads();
#pragma unroll 1
    for (int kt = 0; kt < 8; kt++) {
        if (kt < 7 && act) {
            int nb = (kt + 1) & 1;
            fill_As(As + nb * AS_BUF, (kt + 1) * 16);
            fill_Bs(Bs + nb * BS_BUF, w0, (kt + 1) * 16, t);
        }
        mma16<20>(As + (kt & 1) * AS_BUF, 0, Bs + (kt & 1) * BS_BUF, r0, gb, acc);
        __syncthreads();
    }
    if (act) {
        ull wx[4];
#pragma unroll
        for (int j = 0; j < 4; j++) wx[j] = *(const ull*)&w0[128 * 128 + c0 + 2 * j];
#pragma unroll
        for (int i = 0; i < 8; i++) {
            ull rl2 = dupf(s_rel[r0 + i]);
#pragma unroll
            for (int j = 0; j < 4; j++) ffma2(acc[i][j], rl2, wx[j]);
        }
        selu_store(Hs, acc, r0, c0);
    }
    acc_init(acc, b1, c0);
    hidden_layer(w1, Hs, Bs, t, r0, gb, acc, act);
    if (act) selu_store(Hs, acc, r0, c0);
    acc_init(acc, b2, c0);
    hidden_layer(w2, Hs, Bs, t, r0, gb, acc, act);

    if (act) {
#pragma unroll
        for (int i = 0; i < 8; i++) {
            int row = row0 + r0 + i;
            if (row < Nn) {
                int cl = s_cl[r0 + i];
                float* crow = vc + (size_t)cl * 128 + c0;
                float2 p0 = unpk(acc[i][0]), p1 = unpk(acc[i][1]);
                float2 p2 = unpk(acc[i][2]), p3 = unpk(acc[i][3]);
                red_add_v4(crow, make_float4(p0.x, p0.y, p1.x, p1.y));
                red_add_v4(crow + 4, make_float4(p2.x, p2.y, p3.x, p3.y));
            }
        }
    }
}

__device__ void eenc_simt_tile(
    float* sm, const int* __restrict__ cei, const float* __restrict__ cpos,
    const float* __restrict__ w0, const float* __restrict__ b0,
    const float* __restrict__ w1, const float* __restrict__ b1,
    const float* __restrict__ w2, const float* __restrict__ b2,
    float* __restrict__ ec, int row0, int tfull) {
    float* Bs = sm + BS_OFF;
    float* Hs = sm + HS_OFF;
    float* s_crel = sm + IX_OFF;
    const bool act = tfull < 128;
    const int t = tfull & 127;

    __syncthreads();
    if (act && t < 64) {
        int r = row0 + t;
        if (r >= ECc) r = ECc - 1;
        int a = cei[r];
        int b = cei[ECc + r];
        float dx = cpos[2 * a] - cpos[2 * b];
        float dy = cpos[2 * a + 1] - cpos[2 * b + 1];
        s_crel[t] = sqrtf(dx * dx + dy * dy + 1e-12f);
    }
    const int c0 = (t & 15) * 8;
    const int gb = (t & 15) * 12;
    const int r0 = (t >> 4) * 8;
    __syncthreads();

    if (act) {
#pragma unroll
        for (int i = 0; i < 8; i++) {
            float cr = s_crel[r0 + i];
#pragma unroll
            for (int j = 0; j < 8; j++)
                Hs[(r0 + i) * 132 + c0 + j] =
                    selu_f(fmaf(cr, __ldg(&w0[c0 + j]), __ldg(&b0[c0 + j])));
        }
    }
    ull acc[8][4];
    acc_init(acc, b1, c0);
    hidden_layer(w1, Hs, Bs, t, r0, gb, acc, act);
    if (act) selu_store(Hs, acc, r0, c0);
    acc_init(acc, b2, c0);
    hidden_layer(w2, Hs, Bs, t, r0, gb, acc, act);

    if (act) {
#pragma unroll
        for (int i = 0; i < 8; i++) {
            int row = row0 + r0 + i;
            if (row < ECc) {
                float* erow = ec + (size_t)row * 128 + c0;
                float2 p0 = unpk(acc[i][0]), p1 = unpk(acc[i][1]);
                float2 p2 = unpk(acc[i][2]), p3 = unpk(acc[i][3]);
                *(float4*)erow       = make_float4(p0.x, p0.y, p1.x, p1.y);
                *(float4*)(erow + 4) = make_float4(p2.x, p2.y, p3.x, p3.y);
            }
        }
    }
}

// ================= tcgen05 helpers (sm_103a only) =================
#if TC_PATH
__device__ __forceinline__ uint32 elect_one_pred() {
    uint32 pred;
    asm volatile("{\n\t.reg .pred p;\n\telect.sync _|p, 0xFFFFFFFF;\n\tselp.b32 %0, 1, 0, p;\n\t}" : "=r"(pred));
    return pred;
}
__device__ __forceinline__ uint32 smem_u32(const void* p) {
    uint32 a;
    asm("{ .reg .u64 tmp; cvta.to.shared.u64 tmp, %1; cvt.u32.u64 %0, tmp; }" : "=r"(a) : "l"(p));
    return a;
}
#define MBARRIER_INIT(addr, cnt) \
    asm volatile("mbarrier.init.shared.b64 [%0], %1;" :: "r"((uint32)(addr)), "r"((uint32)(cnt)) : "memory")
#define MBARRIER_WAIT_PARITY(addr, par) do {                                            \
    uint32 _m = (uint32)(addr); uint32 _p = (uint32)(par); uint32 _d;                   \
    asm volatile("{\n\t.reg .pred p;\n\t"                                               \
        "mbarrier.try_wait.parity.acquire.cta.shared::cta.b64 p, [%1], %2;\n\t"         \
        "selp.b32 %0, 1, 0, p;\n\t}" : "=r"(_d) : "r"(_m), "r"(_p) : "memory");         \
    if (!_d) {                                                                          \
        asm volatile("{\n\t.reg .pred P1;\n\t"                                          \
            "WL_%=:\n\t"                                                                \
            "mbarrier.try_wait.parity.acquire.cta.shared::cta.b64 P1, [%0], %1, 0x989680;\n\t" \
            "@P1 bra.uni WD_%=;\n\tbra.uni WL_%=;\n\tWD_%=:\n\t}"                        \
            :: "r"(_m), "r"(_p) : "memory");                                            \
    } } while (0)
#define TCGEN05_ALLOC(slot, n) \
    asm volatile("tcgen05.alloc.cta_group::1.sync.aligned.shared::cta.b32 [%0], %1;" :: "r"((uint32)(slot)), "r"((uint32)(n)) : "memory")
#define TCGEN05_DEALLOC(tm, n) \
    asm volatile("tcgen05.dealloc.cta_group::1.sync.aligned.b32 %0, %1;" :: "r"(tm), "r"((uint32)(n)))
#define TCGEN05_RELINQ() \
    asm volatile("tcgen05.relinquish_alloc_permit.cta_group::1.sync.aligned;")
#define TCGEN05_COMMIT(mb) \
    asm volatile("tcgen05.commit.cta_group::1.mbarrier::arrive::one.shared::cluster.b64 [%0];" :: "r"((uint32)(mb)) : "memory")
#define TCGEN05_WAIT_LD() asm volatile("tcgen05.wait::ld.sync.aligned;" ::: "memory")
#define TCGEN05_FENCE_BEFORE() asm volatile("tcgen05.fence::before_thread_sync;" ::: "memory")
#define TCGEN05_FENCE_AFTER()  asm volatile("tcgen05.fence::after_thread_sync;" ::: "memory")
#define FENCE_PROXY_ASYNC() asm volatile("fence.proxy.async.shared::cta;" ::: "memory")
#define TCGEN05_LD_X32(r, tm) \
    asm volatile("tcgen05.ld.sync.aligned.32x32b.x32.b32 " \
        "{%0, %1, %2, %3, %4, %5, %6, %7, %8, %9, %10, %11, %12, %13, %14, %15, " \
        " %16, %17, %18, %19, %20, %21, %22, %23, %24, %25, %26, %27, %28, %29, %30, %31}, [%32];" \
        : "=r"((r)[0]),  "=r"((r)[1]),  "=r"((r)[2]),  "=r"((r)[3]),  "=r"((r)[4]),  "=r"((r)[5]),  "=r"((r)[6]),  "=r"((r)[7]), \
          "=r"((r)[8]),  "=r"((r)[9]),  "=r"((r)[10]), "=r"((r)[11]), "=r"((r)[12]), "=r"((r)[13]), "=r"((r)[14]), "=r"((r)[15]), \
          "=r"((r)[16]), "=r"((r)[17]), "=r"((r)[18]), "=r"((r)[19]), "=r"((r)[20]), "=r"((r)[21]), "=r"((r)[22]), "=r"((r)[23]), \
          "=r"((r)[24]), "=r"((r)[25]), "=r"((r)[26]), "=r"((r)[27]), "=r"((r)[28]), "=r"((r)[29]), "=r"((r)[30]), "=r"((r)[31]) \
        : "r"(tm))

static constexpr unsigned long long SMEM_DESC_BASE_SW128 =
    (2ull << 61) | (1ull << 46) | (64ull << 32) | (1ull << 16);
#define MAKE_SMEM_DESC(addr) (SMEM_DESC_BASE_SW128 | (((unsigned long long)((addr) >> 4)) & 0x3FFF))

#define IDESC_BF 0x8200490u

__device__ __forceinline__ void mma_ss_bf16(uint32 d, unsigned long long a, unsigned long long b, uint32 en) {
    asm volatile(
        "{\n\t.reg .pred p;\n\tsetp.ne.u32 p, %4, 0;\n\t"
        "tcgen05.mma.cta_group::1.kind::f16 [%0], %1, %2, %3, {%5, %5, %5, %5}, p;\n\t}"
        :: "r"(d), "l"(a), "l"(b), "r"(IDESC_BF), "r"(en), "r"(0u) : "memory");
}
#endif  // TC_PATH

// split pair of fp32 into packed bf16 hi + packed bf16 residual
__device__ __forceinline__ void split2(float a, float b, unsigned& h, unsigned& l) {
    asm("cvt.rn.bf16x2.f32 %0, %1, %2;" : "=r"(h) : "f"(b), "f"(a));
    float ha = __uint_as_float(h << 16);
    float hb = __uint_as_float(h & 0xffff0000u);
    asm("cvt.rn.bf16x2.f32 %0, %1, %2;" : "=r"(l) : "f"(b - hb), "f"(a - ha));
}

// ===== weight prep: transpose + bf16 split + SW128 swizzle, per 64-K chunk =====
__global__ void prep_w_kernel(const float* __restrict__ w, int Kdim, unsigned short* __restrict__ outp) {
    int idx = blockIdx.x * blockDim.x + threadIdx.x;
    if (idx >= Kdim * 128) return;
    int k = idx >> 7, n = idx & 127;
    float x = w[(size_t)k * 128 + n];
    __nv_bfloat16 h = __float2bfloat16(x);
    __nv_bfloat16 l = __float2bfloat16(x - __bfloat162float(h));
    int c = k >> 6, kl = k & 63;
    int byte = n * 128 + kl * 2;
    int sw = byte ^ ((byte >> 3) & 0x70);
    char* base = (char*)(outp + (size_t)c * 16384);
    *(unsigned short*)(base + sw) = __bfloat16_as_ushort(h);
    *(unsigned short*)(base + 16384 + sw) = __bfloat16_as_ushort(l);
}

#define TC_SMEM 101376

// ---------------- common tc boilerplate macro ----------------
#if TC_PATH
#define TC_PROLOG(MISC_EXTRA_DECL)                                          \
    uint32 raw = smem_u32(smraw);                                           \
    uint32 sb = (raw + 1023) & ~1023u;                                      \
    char* gb = (char*)smraw + (sb - raw);                                   \
    const uint32 A_B = sb;                                                  \
    const uint32 W_B = sb + 65536;                                          \
    const uint32 MISC = sb + 98304;                                         \
    char* A_g = gb;                                                         \
    char* W_g = gb + 65536;                                                 \
    uint32 slot = MISC;                                                     \
    uint32 mb0 = MISC + 8;                                                  \
    MISC_EXTRA_DECL                                                         \
    const int t = threadIdx.x;                                              \
    const int wid = t >> 5, lid = t & 31;                                   \
    const int row0 = blockIdx.x * 128;

#define TC_DEF_WPIPE()                                                      \
    uint4 wreg[8];                                                          \
    auto ldW = [&](const unsigned short* chunk) {                           \
        const uint4* s = (const uint4*)chunk;                               \
        _Pragma("unroll")                                                   \
        for (int i = 0; i < 8; i++) wreg[i] = s[i * 256 + t];               \
    };                                                                      \
    auto stW = [&]() {                                                      \
        uint4* d = (uint4*)W_g;                                             \
        _Pragma("unroll")                                                   \
        for (int i = 0; i < 8; i++) d[i * 256 + t] = wreg[i];               \
    };                                                                      \
    auto mma_chunk = [&](uint32 aoff, bool first) {                         \
        if (wid == 0 && elect_one_pred()) {                                 \
            FENCE_PROXY_ASYNC();                                            \
            unsigned long long ah = MAKE_SMEM_DESC(aoff);                   \
            unsigned long long al = MAKE_SMEM_DESC(aoff + 16384);           \
            unsigned long long wh = MAKE_SMEM_DESC(W_B);                    \
            unsigned long long wl = MAKE_SMEM_DESC(W_B + 16384);            \
            uint32 en = first ? 0u : 1u;                                    \
            _Pragma("unroll")                                               \
            for (int s = 0; s < 4; s++) {                                   \
                mma_ss_bf16(tmb, ah + s * 2, wh + s * 2, en); en = 1u;      \
                mma_ss_bf16(tmb, ah + s * 2, wl + s * 2, 1u);               \
                mma_ss_bf16(tmb, al + s * 2, wh + s * 2, 1u);               \
            }                                                               \
            TCGEN05_COMMIT(mb0);                                            \
        }                                                                   \
    };                                                                      \
    auto wait1 = [&]() { MBARRIER_WAIT_PARITY(mb0, par); par ^= 1; };       \
    auto epi_hidden = [&](const float* __restrict__ bias) {                 \
        TCGEN05_FENCE_AFTER();                                              \
        int r = (wid & 3) * 32 + lid;                                       \
        int cb0 = (wid >> 2) * 2;                                           \
        _Pragma("unroll 1")                                                 \
        for (int k = 0; k < 2; k++) {                                       \
            int cb = cb0 + k;                                               \
            uint32 d[32];                                                   \
            TCGEN05_LD_X32(d, tmb + cb * 32);                               \
            TCGEN05_WAIT_LD();                                              \
            char* hi = A_g + (cb >> 1) * 32768;                             \
            char* lo = hi + 16384;                                          \
            _Pragma("unroll")                                               \
            for (int j = 0; j < 32; j += 2) {                               \
                float x0 = selu_f(__uint_as_float(d[j])     + __ldg(&bias[cb * 32 + j]));     \
                float x1 = selu_f(__uint_as_float(d[j + 1]) + __ldg(&bias[cb * 32 + j + 1])); \
                unsigned hb, lb;                                            \
                split2(x0, x1, hb, lb);                                     \
                int c = (cb & 1) * 32 + j;                                  \
                int byte = r * 128 + c * 2;                                 \
                int sw = byte ^ ((byte >> 3) & 0x70);                       \
                *(unsigned*)(hi + sw) = hb;                                 \
                *(unsigned*)(lo + sw) = lb;                                 \
            }                                                               \
        }                                                                   \
        TCGEN05_FENCE_BEFORE();                                             \
        __syncthreads();                                                    \
    };
#endif

// ================= edge tc kernel =================
__global__ void __launch_bounds__(256, 2) edge_tc_kernel(
    float* __restrict__ e, const float* __restrict__ v,
    const int* __restrict__ src, const int* __restrict__ dst,
    const unsigned short* __restrict__ wt,
    const float* __restrict__ w0f, const float* __restrict__ w1f, const float* __restrict__ w2f,
    const float* __restrict__ b0, const float* __restrict__ b1, const float* __restrict__ b2,
    float* __restrict__ agg) {
    extern __shared__ float smraw[];
#if TC_PATH
    TC_PROLOG(int* s_src = (int*)(gb + 98304 + 16); int* s_dst = s_src + 128;)

    if (t < 128) {
        int r = row0 + t;
        if (r >= Ee) r = Ee - 1;
        s_src[t] = src[r];
        s_dst[t] = dst[r];
    }
    if (t == 0) MBARRIER_INIT(mb0, 1);
    if (wid == 0) { TCGEN05_ALLOC(slot, 128); TCGEN05_RELINQ(); }
    __syncthreads();
    uint32 tmb;
    asm volatile("ld.shared.b32 %0, [%1];" : "=r"(tmb) : "r"(slot));
    int par = 0;

    TC_DEF_WPIPE()

    auto fill_A = [&](int kc) {
        char* hi = A_g + (kc & 1) * 32768;
        char* lo = hi + 16384;
#pragma unroll
        for (int i = 0; i < 8; i++) {
            int fi = i * 256 + t;
            int row = fi >> 4, q = fi & 15;
            int grow = row0 + row; if (grow >= Ee) grow = Ee - 1;
            const float* rp;
            if (kc < 2)      rp = e + (size_t)grow * 128;
            else if (kc < 4) rp = v + (size_t)s_src[row] * 128;
            else             rp = v + (size_t)s_dst[row] * 128;
            float4 x = *(const float4*)(rp + (kc & 1) * 64 + q * 4);
            uint2 hb, lb;
            split2(x.x, x.y, hb.x, lb.x);
            split2(x.z, x.w, hb.y, lb.y);
            int byte = row * 128 + q * 8;
            int sw = byte ^ ((byte >> 3) & 0x70);
            *(uint2*)(hi + sw) = hb;
            *(uint2*)(lo + sw) = lb;
        }
    };

    // layer 0: K = 384, 6 chunks (W prefetch to regs overlaps MMA wait)
    ldW(wt); fill_A(0); stW(); __syncthreads(); mma_chunk(A_B, true);
#pragma unroll 1
    for (int i = 1; i < 6; i++) {
        ldW(wt + i * 16384);
        fill_A(i);
        wait1();
        stW(); __syncthreads();
        mma_chunk(A_B + (i & 1) * 32768, false);
    }
    wait1();
    ldW(wt + 6 * 16384);
    epi_hidden(b0);

    // layer 1
    stW(); __syncthreads(); mma_chunk(A_B, true);
    ldW(wt + 7 * 16384);
    wait1();
    stW(); __syncthreads(); mma_chunk(A_B + 32768, false);
    wait1();
    ldW(wt + 8 * 16384);
    epi_hidden(b1);

    // layer 2
    stW(); __syncthreads(); mma_chunk(A_B, true);
    ldW(wt + 9 * 16384);
    wait1();
    stW(); __syncthreads(); mma_chunk(A_B + 32768, false);
    wait1();

    // final epilogue: residual + store e + vectorized red to agg
    TCGEN05_FENCE_AFTER();
    {
        int r = (wid & 3) * 32 + lid;
        int cb0 = (wid >> 2) * 2;
        int grow = row0 + r;
        bool valid = grow < Ee;
        int dn = valid ? s_dst[r] : 0;
#pragma unroll 1
        for (int k = 0; k < 2; k++) {
            int cb = cb0 + k;
            uint32 d[32];
            TCGEN05_LD_X32(d, tmb + cb * 32);
            TCGEN05_WAIT_LD();
            if (valid) {
                float* erow = e + (size_t)grow * 128 + cb * 32;
                float* arow = agg + (size_t)dn * 128 + cb * 32;
#pragma unroll
                for (int q = 0; q < 8; q++) {
                    float4 ev = *(float4*)(erow + q * 4);
                    float4 rr;
                    rr.x = ev.x + __uint_as_float(d[q * 4 + 0]) + __ldg(&b2[cb * 32 + q * 4 + 0]);
                    rr.y = ev.y + __uint_as_float(d[q * 4 + 1]) + __ldg(&b2[cb * 32 + q * 4 + 1]);
                    rr.z = ev.z + __uint_as_float(d[q * 4 + 2]) + __ldg(&b2[cb * 32 + q * 4 + 2]);
                    rr.w = ev.w + __uint_as_float(d[q * 4 + 3]) + __ldg(&b2[cb * 32 + q * 4 + 3]);
                    *(float4*)(erow + q * 4) = rr;
                    red_add_v4(arow + q * 4, rr);
                }
            }
        }
    }
    TCGEN05_FENCE_BEFORE();
    __syncthreads();
    if (wid == 0) TCGEN05_DEALLOC(tmb, 128);
#else
    const int t = threadIdx.x;
    const int row0 = blockIdx.x * 128;
    edge_simt_tile(smraw, e, v, src, dst, w0f, b0, w1f, b1, w2f, b2, agg, row0, t);
    edge_simt_tile(smraw, e, v, src, dst, w0f, b0, w1f, b1, w2f, b2, agg, row0 + 64, t);
#endif
}

// ================= node tc kernel =================
__global__ void __launch_bounds__(256, 2) node_tc_kernel(
    float* __restrict__ v, const float* __restrict__ agg, const float* __restrict__ deg,
    const unsigned short* __restrict__ wt,
    const float* __restrict__ w0f, const float* __restrict__ w1f, const float* __restrict__ w2f,
    const float* __restrict__ b0, const float* __restrict__ b1, const float* __restrict__ b2) {
    extern __shared__ float smraw[];
#if TC_PATH
    TC_PROLOG(float* s_inv = (float*)(gb + 98304 + 16);)

    if (t < 128) {
        int r = row0 + t;
        if (r >= Nn) r = Nn - 1;
        s_inv[t] = 1.f / fmaxf(deg[r], 1.f);
    }
    if (t == 0) MBARRIER_INIT(mb0, 1);
    if (wid == 0) { TCGEN05_ALLOC(slot, 128); TCGEN05_RELINQ(); }
    __syncthreads();
    uint32 tmb;
    asm volatile("ld.shared.b32 %0, [%1];" : "=r"(tmb) : "r"(slot));
    int par = 0;

    TC_DEF_WPIPE()

    auto fill_A = [&](int kc) {
        char* hi = A_g + (kc & 1) * 32768;
        char* lo = hi + 16384;
#pragma unroll
        for (int i = 0; i < 8; i++) {
            int fi = i * 256 + t;
            int row = fi >> 4, q = fi & 15;
            int grow = row0 + row; if (grow >= Nn) grow = Nn - 1;
            float4 x;
            if (kc < 2) {
                x = *(const float4*)(v + (size_t)grow * 128 + (kc & 1) * 64 + q * 4);
            } else {
                x = *(const float4*)(agg + (size_t)grow * 128 + (kc & 1) * 64 + q * 4);
                float sc = s_inv[row];
                x.x *= sc; x.y *= sc; x.z *= sc; x.w *= sc;
            }
            uint2 hb, lb;
            split2(x.x, x.y, hb.x, lb.x);
            split2(x.z, x.w, hb.y, lb.y);
            int byte = row * 128 + q * 8;
            int sw = byte ^ ((byte >> 3) & 0x70);
            *(uint2*)(hi + sw) = hb;
            *(uint2*)(lo + sw) = lb;
        }
    };

    // layer 0: K = 256, 4 chunks
    ldW(wt); fill_A(0); stW(); __syncthreads(); mma_chunk(A_B, true);
#pragma unroll 1
    for (int i = 1; i < 4; i++) {
        ldW(wt + i * 16384);
        fill_A(i);
        wait1();
        stW(); __syncthreads();
        mma_chunk(A_B + (i & 1) * 32768, false);
    }
    wait1();
    ldW(wt + 4 * 16384);
    epi_hidden(b0);

    stW(); __syncthreads(); mma_chunk(A_B, true);
    ldW(wt + 5 * 16384);
    wait1();
    stW(); __syncthreads(); mma_chunk(A_B + 32768, false);
    wait1();
    ldW(wt + 6 * 16384);
    epi_hidden(b1);

    stW(); __syncthreads(); mma_chunk(A_B, true);
    ldW(wt + 7 * 16384);
    wait1();
    stW(); __syncthreads(); mma_chunk(A_B + 32768, false);
    wait1();

    TCGEN05_FENCE_AFTER();
    {
        int r = (wid & 3) * 32 + lid;
        int cb0 = (wid >> 2) * 2;
        int grow = row0 + r;
        bool valid = grow < Nn;
#pragma unroll 1
        for (int k = 0; k < 2; k++) {
            int cb = cb0 + k;
            uint32 d[32];
            TCGEN05_LD_X32(d, tmb + cb * 32);
            TCGEN05_WAIT_LD();
            if (valid) {
                float* vrow = v + (size_t)grow * 128 + cb * 32;
#pragma unroll
                for (int q = 0; q < 8; q++) {
                    float4 vv = *(float4*)(vrow + q * 4);
                    vv.x += __uint_as_float(d[q * 4 + 0]) + __ldg(&b2[cb * 32 + q * 4 + 0]);
                    vv.y += __uint_as_float(d[q * 4 + 1]) + __ldg(&b2[cb * 32 + q * 4 + 1]);
                    vv.z += __uint_as_float(d[q * 4 + 2]) + __ldg(&b2[cb * 32 + q * 4 + 2]);
                    vv.w += __uint_as_float(d[q * 4 + 3]) + __ldg(&b2[cb * 32 + q * 4 + 3]);
                    *(float4*)(vrow + q * 4) = vv;
                }
            }
        }
    }
    TCGEN05_FENCE_BEFORE();
    __syncthreads();
    if (wid == 0) TCGEN05_DEALLOC(tmb, 128);
#else
    const int t = threadIdx.x;
    const int row0 = blockIdx.x * 128;
    node_simt_tile(smraw, v, agg, deg, w0f, b0, w1f, b1, w2f, b2, row0, t);
    node_simt_tile(smraw, v, agg, deg, w0f, b0, w1f, b1, w2f, b2, row0 + 64, t);
#endif
}

// ================= pool tc kernel =================
__global__ void __launch_bounds__(256, 2) pool_tc_kernel(
    const float* __restrict__ v, const float* __restrict__ pos,
    const int* __restrict__ cluster, const float* __restrict__ cpos,
    const unsigned short* __restrict__ wt,
    const float* __restrict__ w0f, const float* __restrict__ w1f, const float* __restrict__ w2f,
    const float* __restrict__ b0, const float* __restrict__ b1, const float* __restrict__ b2,
    float* __restrict__ vc) {
    extern __shared__ float smraw[];
#if TC_PATH
    TC_PROLOG(float* s_rel = (float*)(gb + 98304 + 16); int* s_cl = (int*)(gb + 98304 + 16 + 512);)

    if (t < 128) {
        int r = row0 + t;
        if (r >= Nn) r = Nn - 1;
        int cl = cluster[r];
        float dx = pos[2 * r] - cpos[2 * cl];
        float dy = pos[2 * r + 1] - cpos[2 * cl + 1];
        s_rel[t] = sqrtf(dx * dx + dy * dy + 1e-12f);
        s_cl[t] = cl;
    }
    if (t == 0) MBARRIER_INIT(mb0, 1);
    if (wid == 0) { TCGEN05_ALLOC(slot, 128); TCGEN05_RELINQ(); }
    __syncthreads();
    uint32 tmb;
    asm volatile("ld.shared.b32 %0, [%1];" : "=r"(tmb) : "r"(slot));
    int par = 0;

    TC_DEF_WPIPE()

    auto fill_A = [&](int kc) {
        char* hi = A_g + (kc & 1) * 32768;
        char* lo = hi + 16384;
#pragma unroll
        for (int i = 0; i < 8; i++) {
            int fi = i * 256 + t;
            int row = fi >> 4, q = fi & 15;
            int grow = row0 + row; if (grow >= Nn) grow = Nn - 1;
            float4 x = *(const float4*)(v + (size_t)grow * 128 + (kc & 1) * 64 + q * 4);
            uint2 hb, lb;
            split2(x.x, x.y, hb.x, lb.x);
            split2(x.z, x.w, hb.y, lb.y);
            int byte = row * 128 + q * 8;
            int sw = byte ^ ((byte >> 3) & 0x70);
            *(uint2*)(hi + sw) = hb;
            *(uint2*)(lo + sw) = lb;
        }
    };
    // layer-0 epilogue with rank-1 rel term: selu(d + rel*w0_last + b0)
    const float* w0L = w0f + 128 * 128;
    auto epi_pool0 = [&]() {
        TCGEN05_FENCE_AFTER();
        int r = (wid & 3) * 32 + lid;
        int cb0 = (wid >> 2) * 2;
        float rel = s_rel[r];
#pragma unroll 1
        for (int k = 0; k < 2; k++) {
            int cb = cb0 + k;
            uint32 d[32];
            TCGEN05_LD_X32(d, tmb + cb * 32);
            TCGEN05_WAIT_LD();
            char* hi = A_g + (cb >> 1) * 32768;
            char* lo = hi + 16384;
#pragma unroll
            for (int j = 0; j < 32; j += 2) {
                int c = cb * 32 + j;
                float x0 = selu_f(__uint_as_float(d[j])     + rel * __ldg(&w0L[c])     + __ldg(&b0[c]));
                float x1 = selu_f(__uint_as_float(d[j + 1]) + rel * __ldg(&w0L[c + 1]) + __ldg(&b0[c + 1]));
                unsigned hb, lb;
                split2(x0, x1, hb, lb);
                int cc = (cb & 1) * 32 + j;
                int byte = r * 128 + cc * 2;
                int sw = byte ^ ((byte >> 3) & 0x70);
                *(unsigned*)(hi + sw) = hb;
                *(unsigned*)(lo + sw) = lb;
            }
        }
        TCGEN05_FENCE_BEFORE();
        __syncthreads();
    };

    // layer 0: K = 128 (v), 2 chunks
    ldW(wt); fill_A(0); stW(); __syncthreads(); mma_chunk(A_B, true);
    ldW(wt + 1 * 16384);
    fill_A(1);
    wait1();
    stW(); __syncthreads(); mma_chunk(A_B + 32768, false);
    wait1();
    ldW(wt + 2 * 16384);
    epi_pool0();

    stW(); __syncthreads(); mma_chunk(A_B, true);
    ldW(wt + 3 * 16384);
    wait1();
    stW(); __syncthreads(); mma_chunk(A_B + 32768, false);
    wait1();
    ldW(wt + 4 * 16384);
    epi_hidden(b1);

    stW(); __syncthreads(); mma_chunk(A_B, true);
    ldW(wt + 5 * 16384);
    wait1();
    stW(); __syncthreads(); mma_chunk(A_B + 32768, false);
    wait1();

    TCGEN05_FENCE_AFTER();
    {
        int r = (wid & 3) * 32 + lid;
        int cb0 = (wid >> 2) * 2;
        int grow = row0 + r;
        bool valid = grow < Nn;
        int cl = s_cl[r];
#pragma unroll 1
        for (int k = 0; k < 2; k++) {
            int cb = cb0 + k;
            uint32 d[32];
            TCGEN05_LD_X32(d, tmb + cb * 32);
            TCGEN05_WAIT_LD();
            if (valid) {
                float* crow = vc + (size_t)cl * 128 + cb * 32;
#pragma unroll
                for (int q = 0; q < 8; q++) {
                    float4 rr;
                    rr.x = __uint_as_float(d[q * 4 + 0]) + __ldg(&b2[cb * 32 + q * 4 + 0]);
                    rr.y = __uint_as_float(d[q * 4 + 1]) + __ldg(&b2[cb * 32 + q * 4 + 1]);
                    rr.z = __uint_as_float(d[q * 4 + 2]) + __ldg(&b2[cb * 32 + q * 4 + 2]);
                    rr.w = __uint_as_float(d[q * 4 + 3]) + __ldg(&b2[cb * 32 + q * 4 + 3]);
                    red_add_v4(crow + q * 4, rr);
                }
            }
        }
    }
    TCGEN05_FENCE_BEFORE();
    __syncthreads();
    if (wid == 0) TCGEN05_DEALLOC(tmb, 128);
#else
    const int t = threadIdx.x;
    const int row0 = blockIdx.x * 128;
    pool_simt_tile(smraw, v, pos, cluster, cpos, w0f, b0, w1f, b1, w2f, b2, vc, row0, t);
    pool_simt_tile(smraw, v, pos, cluster, cpos, w0f, b0, w1f, b1, w2f, b2, vc, row0 + 64, t);
#endif
}

// ================= eenc tc kernel =================
__global__ void __launch_bounds__(256, 2) eenc_tc_kernel(
    const int* __restrict__ cei, const float* __restrict__ cpos,
    const unsigned short* __restrict__ wt,
    const float* __restrict__ w0f, const float* __restrict__ w1f, const float* __restrict__ w2f,
    const float* __restrict__ b0, const float* __restrict__ b1, const float* __restrict__ b2,
    float* __restrict__ ec) {
    extern __shared__ float smraw[];
#if TC_PATH
    TC_PROLOG(float* s_crel = (float*)(gb + 98304 + 16);)

    if (t < 128) {
        int r = row0 + t;
        if (r >= ECc) r = ECc - 1;
        int a = cei[r];
        int b = cei[ECc + r];
        float dx = cpos[2 * a] - cpos[2 * b];
        float dy = cpos[2 * a + 1] - cpos[2 * b + 1];
        s_crel[t] = sqrtf(dx * dx + dy * dy + 1e-12f);
    }
    if (t == 0) MBARRIER_INIT(mb0, 1);
    if (wid == 0) { TCGEN05_ALLOC(slot, 128); TCGEN05_RELINQ(); }
    __syncthreads();
    uint32 tmb;
    asm volatile("ld.shared.b32 %0, [%1];" : "=r"(tmb) : "r"(slot));
    int par = 0;

    TC_DEF_WPIPE()

    // layer 0 (K=1) computed directly into A region
    auto fill_A0 = [&](int ch) {
        char* hi = A_g + ch * 32768;
        char* lo = hi + 16384;
#pragma unroll
        for (int i = 0; i < 8; i++) {
            int fi = i * 256 + t;
            int row = fi >> 4, q = fi & 15;
            float cr = s_crel[row];
            float x0 = selu_f(fmaf(cr, __ldg(&w0f[ch * 64 + q * 4 + 0]), __ldg(&b0[ch * 64 + q * 4 + 0])));
            float x1 = selu_f(fmaf(cr, __ldg(&w0f[ch * 64 + q * 4 + 1]), __ldg(&b0[ch * 64 + q * 4 + 1])));
            float x2 = selu_f(fmaf(cr, __ldg(&w0f[ch * 64 + q * 4 + 2]), __ldg(&b0[ch * 64 + q * 4 + 2])));
            float x3 = selu_f(fmaf(cr, __ldg(&w0f[ch * 64 + q * 4 + 3]), __ldg(&b0[ch * 64 + q * 4 + 3])));
            uint2 hb, lb;
            split2(x0, x1, hb.x, lb.x);
            split2(x2, x3, hb.y, lb.y);
            int byte = row * 128 + q * 8;
            int sw = byte ^ ((byte >> 3) & 0x70);
            *(uint2*)(hi + sw) = hb;
            *(uint2*)(lo + sw) = lb;
        }
    };
    fill_A0(0);
    fill_A0(1);

    // layer 1
    ldW(wt); stW(); __syncthreads(); mma_chunk(A_B, true);
    ldW(wt + 1 * 16384);
    wait1();
    stW(); __syncthreads(); mma_chunk(A_B + 32768, false);
    wait1();
    ldW(wt + 2 * 16384);
    epi_hidden(b1);

    // layer 2
    stW(); __syncthreads(); mma_chunk(A_B, true);
    ldW(wt + 3 * 16384);
    wait1();
    stW(); __syncthreads(); mma_chunk(A_B + 32768, false);
    wait1();

    TCGEN05_FENCE_AFTER();
    {
        int r = (wid & 3) * 32 + lid;
        int cb0 = (wid >> 2) * 2;
        int grow = row0 + r;
        bool valid = grow < ECc;
#pragma unroll 1
        for (int k = 0; k < 2; k++) {
            int cb = cb0 + k;
            uint32 d[32];
            TCGEN05_LD_X32(d, tmb + cb * 32);
            TCGEN05_WAIT_LD();
            if (valid) {
                float* erow = ec + (size_t)grow * 128 + cb * 32;
#pragma unroll
                for (int q = 0; q < 8; q++) {
                    float4 rr;
                    rr.x = __uint_as_float(d[q * 4 + 0]) + __ldg(&b2[cb * 32 + q * 4 + 0]);
                    rr.y = __uint_as_float(d[q * 4 + 1]) + __ldg(&b2[cb * 32 + q * 4 + 1]);
                    rr.z = __uint_as_float(d[q * 4 + 2]) + __ldg(&b2[cb * 32 + q * 4 + 2]);
                    rr.w = __uint_as_float(d[q * 4 + 3]) + __ldg(&b2[cb * 32 + q * 4 + 3]);
                    *(float4*)(erow + q * 4) = rr;
                }
            }
        }
    }
    TCGEN05_FENCE_BEFORE();
    __syncthreads();
    if (wid == 0) TCGEN05_DEALLOC(tmb, 128);
#else
    const int t = threadIdx.x;
    const int row0 = blockIdx.x * 128;
    eenc_simt_tile(smraw, cei, cpos, w0f, b0, w1f, b1, w2f, b2, ec, row0, t);
    eenc_simt_tile(smraw, cei, cpos, w0f, b0, w1f, b1, w2f, b2, ec, row0 + 64, t);
#endif
}

// ---------------- small helpers ----------------
__global__ void deg_scatter(const int* __restrict__ dst, float* __restrict__ deg) {
    int i = blockIdx.x * blockDim.x + threadIdx.x;
    if (i < Ee) atomicAdd(&deg[dst[i]], 1.f);
}
__global__ void cpos_scatter(const float* __restrict__ pos, const int* __restrict__ cluster,
                             float* __restrict__ cposs, float* __restrict__ ccnt) {
    int i = blockIdx.x * blockDim.x + threadIdx.x;
    if (i < Nn) {
        int c = cluster[i];
        atomicAdd(&cposs[2 * c], pos[2 * i]);
        atomicAdd(&cposs[2 * c + 1], pos[2 * i + 1]);
        atomicAdd(&ccnt[c], 1.f);
    }
}
__global__ void cpos_fin(const float* __restrict__ cposs, const float* __restrict__ ccnt,
                         float* __restrict__ cpos, float* __restrict__ cinv) {
    int c = blockIdx.x * blockDim.x + threadIdx.x;
    if (c < NCc) {
        float inv = 1.f / fmaxf(ccnt[c], 1.f);
        cpos[2 * c] = cposs[2 * c] * inv;
        cpos[2 * c + 1] = cposs[2 * c + 1] * inv;
        cinv[c] = inv;
    }
}
__global__ void vc_scale(float* __restrict__ vc, const float* __restrict__ cinv) {
    int i = blockIdx.x * blockDim.x + threadIdx.x;
    if (i < NCc * 128) vc[i] *= cinv[i >> 7];
}

// ---------------- launch ----------------
extern "C" void kernel_launch(void* const* d_in, const int* in_sizes, int n_in,
                              void* d_out, int out_size) {
    const float* v0      = (const float*)d_in[0];
    const float* e0      = (const float*)d_in[1];
    const float* pos     = (const float*)d_in[2];
    const int*   ei      = (const int*)d_in[3];
    const int*   cluster = (const int*)d_in[4];
    const int*   cei     = (const int*)d_in[5];
    const float* ew0 = (const float*)d_in[6],  *eb0 = (const float*)d_in[7];
    const float* ew1 = (const float*)d_in[8],  *eb1 = (const float*)d_in[9];
    const float* ew2 = (const float*)d_in[10], *eb2 = (const float*)d_in[11];
    const float* nw0 = (const float*)d_in[12], *nb0 = (const float*)d_in[13];
    const float* nw1 = (const float*)d_in[14], *nb1 = (const float*)d_in[15];
    const float* nw2 = (const float*)d_in[16], *nb2 = (const float*)d_in[17];
    const float* pw0 = (const float*)d_in[18], *pb0 = (const float*)d_in[19];
    const float* pw1 = (const float*)d_in[20], *pb1 = (const float*)d_in[21];
    const float* pw2 = (const float*)d_in[22], *pb2 = (const float*)d_in[23];
    const float* qw0 = (const float*)d_in[24], *qb0 = (const float*)d_in[25];
    const float* qw1 = (const float*)d_in[26], *qb1 = (const float*)d_in[27];
    const float* qw2 = (const float*)d_in[28], *qb2 = (const float*)d_in[29];

    float* out    = (float*)d_out;
    float* out_vc = out;
    float* out_ec = out + OFF_EC;
    float* vbuf   = out + OFF_V;
    float* ebuf   = out + OFF_E;

    float *agg, *deg, *cposs, *ccnt, *cpos, *cinv;
    unsigned short *wt, *wtn, *wtp, *wtq;
    cudaGetSymbolAddress((void**)&agg,   g_agg);
    cudaGetSymbolAddress((void**)&deg,   g_deg);
    cudaGetSymbolAddress((void**)&cposs, g_cposs);
    cudaGetSymbolAddress((void**)&ccnt,  g_ccnt);
    cudaGetSymbolAddress((void**)&cpos,  g_cpos);
    cudaGetSymbolAddress((void**)&cinv,  g_cinv);
    cudaGetSymbolAddress((void**)&wt,    g_wt);
    cudaGetSymbolAddress((void**)&wtn,   g_wtn);
    cudaGetSymbolAddress((void**)&wtp,   g_wtp);
    cudaGetSymbolAddress((void**)&wtq,   g_wtq);

    cudaFuncSetAttribute(edge_tc_kernel, cudaFuncAttributeMaxDynamicSharedMemorySize, TC_SMEM);
    cudaFuncSetAttribute(node_tc_kernel, cudaFuncAttributeMaxDynamicSharedMemorySize, TC_SMEM);
    cudaFuncSetAttribute(pool_tc_kernel, cudaFuncAttributeMaxDynamicSharedMemorySize, TC_SMEM);
    cudaFuncSetAttribute(eenc_tc_kernel, cudaFuncAttributeMaxDynamicSharedMemorySize, TC_SMEM);

    cudaMemcpyAsync(vbuf, v0, sizeof(float) * (size_t)Nn * 128, cudaMemcpyDeviceToDevice, 0);
    cudaMemcpyAsync(ebuf, e0, sizeof(float) * (size_t)Ee * 128, cudaMemcpyDeviceToDevice, 0);

    const int* src  = ei;
    const int* dstp = ei + Ee;

    cudaMemsetAsync(deg, 0, sizeof(float) * Nn, 0);
    deg_scatter<<<(Ee + 255) / 256, 256>>>(dstp, deg);

    // prep all weights (transpose + bf16 split + swizzle)
    for (int d = 0; d < 4; d++) {
        unsigned short* wtb = wt + (size_t)d * 163840;
        prep_w_kernel<<<(384 * 128 + 255) / 256, 256>>>(ew0 + (size_t)d * 384 * 128, 384, wtb);
        prep_w_kernel<<<(128 * 128 + 255) / 256, 256>>>(ew1 + (size_t)d * 128 * 128, 128, wtb + 6 * 16384);
        prep_w_kernel<<<(128 * 128 + 255) / 256, 256>>>(ew2 + (size_t)d * 128 * 128, 128, wtb + 8 * 16384);
        unsigned short* wnb = wtn + (size_t)d * 131072;
        prep_w_kernel<<<(256 * 128 + 255) / 256, 256>>>(nw0 + (size_t)d * 256 * 128, 256, wnb);
        prep_w_kernel<<<(128 * 128 + 255) / 256, 256>>>(nw1 + (size_t)d * 128 * 128, 128, wnb + 4 * 16384);
        prep_w_kernel<<<(128 * 128 + 255) / 256, 256>>>(nw2 + (size_t)d * 128 * 128, 128, wnb + 6 * 16384);
    }
    prep_w_kernel<<<(128 * 128 + 255) / 256, 256>>>(pw0, 128, wtp);
    prep_w_kernel<<<(128 * 128 + 255) / 256, 256>>>(pw1, 128, wtp + 2 * 16384);
    prep_w_kernel<<<(128 * 128 + 255) / 256, 256>>>(pw2, 128, wtp + 4 * 16384);
    prep_w_kernel<<<(128 * 128 + 255) / 256, 256>>>(qw1, 128, wtq);
    prep_w_kernel<<<(128 * 128 + 255) / 256, 256>>>(qw2, 128, wtq + 2 * 16384);

    for (int d = 0; d < 4; d++) {
        cudaMemsetAsync(agg, 0, sizeof(float) * (size_t)Nn * 128, 0);
        edge_tc_kernel<<<(Ee + 127) / 128, 256, TC_SMEM>>>(
            ebuf, vbuf, src, dstp, wt + (size_t)d * 163840,
            ew0 + (size_t)d * 384 * 128, ew1 + (size_t)d * 128 * 128, ew2 + (size_t)d * 128 * 128,
            eb0 + d * 128, eb1 + d * 128, eb2 + d * 128, agg);
        node_tc_kernel<<<(Nn + 127) / 128, 256, TC_SMEM>>>(
            vbuf, agg, deg, wtn + (size_t)d * 131072,
            nw0 + (size_t)d * 256 * 128, nw1 + (size_t)d * 128 * 128, nw2 + (size_t)d * 128 * 128,
            nb0 + d * 128, nb1 + d * 128, nb2 + d * 128);
    }

    cudaMemsetAsync(cposs, 0, sizeof(float) * NCc * 2, 0);
    cudaMemsetAsync(ccnt, 0, sizeof(float) * NCc, 0);
    cpos_scatter<<<(Nn + 255) / 256, 256>>>(pos, cluster, cposs, ccnt);
    cpos_fin<<<(NCc + 255) / 256, 256>>>(cposs, ccnt, cpos, cinv);

    cudaMemsetAsync(out_vc, 0, sizeof(float) * NCc * 128, 0);
    pool_tc_kernel<<<(Nn + 127) / 128, 256, TC_SMEM>>>(
        vbuf, pos, cluster, cpos, wtp, pw0, pw1, pw2, pb0, pb1, pb2, out_vc);
    vc_scale<<<(NCc * 128 + 255) / 256, 256>>>(out_vc, cinv);

    eenc_tc_kernel<<<(ECc + 127) / 128, 256, TC_SMEM>>>(
        cei, cpos, wtq, qw0, qw1, qw2, qb0, qb1, qb2, out_ec);
}